// round 1
// baseline (speedup 1.0000x reference)
#include <cuda_runtime.h>

// Problem constants
#define Bb   8
#define Nn   1024
#define Dd   512
#define Hh   8
#define DHd  64
#define MTOT (Bb*Nn)   // 8192

// Scratch for Q/K/V projections (16 MB each)
__device__ float g_q[MTOT*Dd];
__device__ float g_k[MTOT*Dd];
__device__ float g_v[MTOT*Dd];

// ---------------------------------------------------------------------------
// GEMM: out[M,512] = X[M,512] @ W[512,512] + bias   (W is [in,out], so row-major
// W works directly: C[m,n] = sum_k X[m,k]*W[k,n] + b[n])
// 128x128 block tile, BK=16, 256 threads, 8x8 per-thread micro-tile.
// ---------------------------------------------------------------------------
__global__ __launch_bounds__(256) void gemm_bias_kernel(
    const float* __restrict__ X, const float* __restrict__ W,
    const float* __restrict__ bias, int which)
{
    float* Cout = (which == 0) ? g_q : (which == 1) ? g_k : g_v;

    // As padded to 132 floats/row: keeps transposed scalar stores ~2-way max
    // and preserves 16B alignment for float4 reads (132*4 = 528 = 33*16).
    __shared__ float As[16][132];
    __shared__ float Bs[16][128];

    const int tid = threadIdx.x;
    const int bm  = blockIdx.x * 128;
    const int bn  = blockIdx.y * 128;
    const int ty  = tid / 16;       // 0..15
    const int tx  = tid % 16;       // 0..15

    float acc[8][8];
    #pragma unroll
    for (int i = 0; i < 8; i++)
        #pragma unroll
        for (int j = 0; j < 8; j++) acc[i][j] = 0.0f;

    for (int k0 = 0; k0 < Dd; k0 += 16) {
        // Load X tile [128 x 16] -> As[k][m] (transposed). 512 float4, 2/thread.
        #pragma unroll
        for (int r = 0; r < 2; r++) {
            int f  = tid + r * 256;          // 0..511
            int m  = f >> 2;                 // 0..127
            int kk = (f & 3) * 4;            // 0,4,8,12
            float4 v = *(const float4*)(X + (size_t)(bm + m) * Dd + k0 + kk);
            As[kk + 0][m] = v.x;
            As[kk + 1][m] = v.y;
            As[kk + 2][m] = v.z;
            As[kk + 3][m] = v.w;
        }
        // Load W tile [16 x 128] -> Bs[k][n]. 512 float4, 2/thread, coalesced.
        #pragma unroll
        for (int r = 0; r < 2; r++) {
            int f  = tid + r * 256;
            int kk = f >> 5;                 // 0..15
            int nn = (f & 31) * 4;           // 0..124
            float4 v = *(const float4*)(W + (size_t)(k0 + kk) * Dd + bn + nn);
            *(float4*)&Bs[kk][nn] = v;
        }
        __syncthreads();

        #pragma unroll
        for (int k = 0; k < 16; k++) {
            float a[8], b[8];
            float4 a0 = *(const float4*)&As[k][ty * 8];
            float4 a1 = *(const float4*)&As[k][ty * 8 + 4];
            float4 b0 = *(const float4*)&Bs[k][tx * 8];
            float4 b1 = *(const float4*)&Bs[k][tx * 8 + 4];
            a[0]=a0.x; a[1]=a0.y; a[2]=a0.z; a[3]=a0.w;
            a[4]=a1.x; a[5]=a1.y; a[6]=a1.z; a[7]=a1.w;
            b[0]=b0.x; b[1]=b0.y; b[2]=b0.z; b[3]=b0.w;
            b[4]=b1.x; b[5]=b1.y; b[6]=b1.z; b[7]=b1.w;
            #pragma unroll
            for (int i = 0; i < 8; i++)
                #pragma unroll
                for (int j = 0; j < 8; j++)
                    acc[i][j] += a[i] * b[j];
        }
        __syncthreads();
    }

    // Epilogue: add bias, store
    #pragma unroll
    for (int i = 0; i < 8; i++) {
        int m = bm + ty * 8 + i;
        #pragma unroll
        for (int j = 0; j < 8; j += 4) {
            int n = bn + tx * 8 + j;
            float4 o;
            o.x = acc[i][j + 0] + bias[n + 0];
            o.y = acc[i][j + 1] + bias[n + 1];
            o.z = acc[i][j + 2] + bias[n + 2];
            o.w = acc[i][j + 3] + bias[n + 3];
            *(float4*)(Cout + (size_t)m * Dd + n) = o;
        }
    }
}

// ---------------------------------------------------------------------------
// Flash attention: one query row per thread, 128 threads/block.
// grid = (N/128, B*H). K/V tiles of 64 rows in shared (32 KB).
// Online softmax merged per 8-key chunk (register score buffer).
// NOTE: reference applies NO 1/sqrt(dh) scaling.
// ---------------------------------------------------------------------------
__global__ __launch_bounds__(128) void attn_kernel(float* __restrict__ y)
{
    __shared__ float Kt[64][DHd];   // 16 KB
    __shared__ float Vt[64][DHd];   // 16 KB

    const int bh = blockIdx.y;
    const int b  = bh / Hh;
    const int h  = bh % Hh;
    const int qrow = blockIdx.x * 128 + threadIdx.x;   // 0..N-1

    // Load this thread's query row into registers
    const float* qptr = g_q + ((size_t)(b * Nn + qrow)) * Dd + h * DHd;
    float q[DHd];
    #pragma unroll
    for (int d = 0; d < DHd; d += 4) {
        float4 v4 = *(const float4*)(qptr + d);
        q[d] = v4.x; q[d+1] = v4.y; q[d+2] = v4.z; q[d+3] = v4.w;
    }

    float acc[DHd];
    #pragma unroll
    for (int d = 0; d < DHd; d++) acc[d] = 0.0f;
    float mval = -1e30f;
    float lsum = 0.0f;

    const float* kbase = g_k + ((size_t)(b * Nn)) * Dd + h * DHd;
    const float* vbase = g_v + ((size_t)(b * Nn)) * Dd + h * DHd;

    for (int t0 = 0; t0 < Nn; t0 += 64) {
        // Cooperative tile load: 64 rows x 64 floats = 1024 float4 per buffer
        #pragma unroll
        for (int r = 0; r < 8; r++) {
            int f  = threadIdx.x + r * 128;   // 0..1023
            int j  = f >> 4;
            int dd = (f & 15) * 4;
            *(float4*)&Kt[j][dd] = *(const float4*)(kbase + (size_t)(t0 + j) * Dd + dd);
            *(float4*)&Vt[j][dd] = *(const float4*)(vbase + (size_t)(t0 + j) * Dd + dd);
        }
        __syncthreads();

        // Process the 64 keys in chunks of 8 (scores live in registers)
        #pragma unroll 1
        for (int c = 0; c < 8; c++) {
            float sc[8];
            #pragma unroll
            for (int jj = 0; jj < 8; jj++) {
                const float* kr = &Kt[c * 8 + jj][0];
                float p0 = 0.f, p1 = 0.f, p2 = 0.f, p3 = 0.f;
                #pragma unroll
                for (int d = 0; d < DHd; d += 4) {
                    p0 += q[d + 0] * kr[d + 0];
                    p1 += q[d + 1] * kr[d + 1];
                    p2 += q[d + 2] * kr[d + 2];
                    p3 += q[d + 3] * kr[d + 3];
                }
                sc[jj] = (p0 + p1) + (p2 + p3);
            }
            // Chunk max + online rescale
            float mt = mval;
            #pragma unroll
            for (int jj = 0; jj < 8; jj++) mt = fmaxf(mt, sc[jj]);
            float corr = __expf(mval - mt);   // ==1 if max unchanged, 0 if first
            lsum *= corr;
            #pragma unroll
            for (int d = 0; d < DHd; d++) acc[d] *= corr;
            mval = mt;
            // Accumulate P·V
            #pragma unroll
            for (int jj = 0; jj < 8; jj++) {
                float p = __expf(sc[jj] - mval);
                lsum += p;
                const float* vr = &Vt[c * 8 + jj][0];
                #pragma unroll
                for (int d = 0; d < DHd; d++) acc[d] += p * vr[d];
            }
        }
        __syncthreads();
    }

    float inv = 1.0f / lsum;
    float* yptr = y + ((size_t)(b * Nn + qrow)) * Dd + h * DHd;
    #pragma unroll
    for (int d = 0; d < DHd; d += 4) {
        float4 o;
        o.x = acc[d] * inv; o.y = acc[d+1] * inv;
        o.z = acc[d+2] * inv; o.w = acc[d+3] * inv;
        *(float4*)(yptr + d) = o;
    }
}

// ---------------------------------------------------------------------------
// Inputs (metadata order): x, Wq, bq, Wk, bk, Wv, bv. Output: float32 [B,N,D].
// ---------------------------------------------------------------------------
extern "C" void kernel_launch(void* const* d_in, const int* in_sizes, int n_in,
                              void* d_out, int out_size)
{
    const float* x  = (const float*)d_in[0];
    const float* Wq = (const float*)d_in[1];
    const float* bq = (const float*)d_in[2];
    const float* Wk = (const float*)d_in[3];
    const float* bk = (const float*)d_in[4];
    const float* Wv = (const float*)d_in[5];
    const float* bv = (const float*)d_in[6];
    float* y = (float*)d_out;

    dim3 ggrid(MTOT / 128, Dd / 128);   // (64, 4)
    gemm_bias_kernel<<<ggrid, 256>>>(x, Wq, bq, 0);
    gemm_bias_kernel<<<ggrid, 256>>>(x, Wk, bk, 1);
    gemm_bias_kernel<<<ggrid, 256>>>(x, Wv, bv, 2);

    dim3 agrid(Nn / 128, Bb * Hh);      // (8, 64)
    attn_kernel<<<agrid, 128>>>(y);
}

// round 3
// speedup vs baseline: 1.9311x; 1.9311x over previous
#include <cuda_runtime.h>
#include <cuda_bf16.h>

// Problem constants
#define Bb   8
#define Nn   1024
#define Dd   512
#define Hh   8
#define DHd  64
#define MTOT (Bb*Nn)   // 8192
#define BH   (Bb*Hh)   // 64

// bf16 split-precision Q/K (head-major [BH, N, 64]) and transposed V ([BH, 64, N])
__device__ __nv_bfloat16 g_qh[BH*Nn*DHd];
__device__ __nv_bfloat16 g_ql[BH*Nn*DHd];
__device__ __nv_bfloat16 g_kh[BH*Nn*DHd];
__device__ __nv_bfloat16 g_kl[BH*Nn*DHd];
__device__ __nv_bfloat16 g_vth[BH*DHd*Nn];
__device__ __nv_bfloat16 g_vtl[BH*DHd*Nn];

#define SMEM_SWZ(b) ((b) ^ (((b) >> 3) & 0x70))

static __device__ __forceinline__ unsigned smem_u32(const void* p) {
    unsigned a;
    asm("{ .reg .u64 t; cvta.to.shared.u64 t, %1; cvt.u32.u64 %0, t; }" : "=r"(a) : "l"(p));
    return a;
}

// mma.sync m16n8k16 bf16 -> fp32 (sm_80+, no arch-feature gating)
static __device__ __forceinline__ void mma16816(float* c, const unsigned* a, const unsigned* b) {
    asm volatile(
        "mma.sync.aligned.m16n8k16.row.col.f32.bf16.bf16.f32 "
        "{%0,%1,%2,%3}, {%4,%5,%6,%7}, {%8,%9}, {%0,%1,%2,%3};"
        : "+f"(c[0]), "+f"(c[1]), "+f"(c[2]), "+f"(c[3])
        : "r"(a[0]), "r"(a[1]), "r"(a[2]), "r"(a[3]), "r"(b[0]), "r"(b[1]));
}

static __device__ __forceinline__ void ldsm4(unsigned* r, unsigned addr) {
    asm volatile("ldmatrix.sync.aligned.m8n8.x4.shared.b16 {%0,%1,%2,%3}, [%4];"
                 : "=r"(r[0]), "=r"(r[1]), "=r"(r[2]), "=r"(r[3]) : "r"(addr));
}

// ---------------------------------------------------------------------------
// Projection GEMM: out = X[M,512] @ W[512,512] + bias, fp32 SIMT, epilogue
// splits into bf16 hi/lo. which: 0->Q, 1->K (head-major), 2->V (transposed).
// ---------------------------------------------------------------------------
__global__ __launch_bounds__(256) void gemm_bias_kernel(
    const float* __restrict__ X, const float* __restrict__ W,
    const float* __restrict__ bias, int which)
{
    __nv_bfloat16* Hi = (which == 0) ? g_qh : (which == 1) ? g_kh : g_vth;
    __nv_bfloat16* Lo = (which == 0) ? g_ql : (which == 1) ? g_kl : g_vtl;

    __shared__ float As[16][132];
    __shared__ float Bs[16][128];

    const int tid = threadIdx.x;
    const int bm  = blockIdx.x * 128;
    const int bn  = blockIdx.y * 128;
    const int ty  = tid / 16;
    const int tx  = tid % 16;

    float acc[8][8];
    #pragma unroll
    for (int i = 0; i < 8; i++)
        #pragma unroll
        for (int j = 0; j < 8; j++) acc[i][j] = 0.0f;

    for (int k0 = 0; k0 < Dd; k0 += 16) {
        #pragma unroll
        for (int r = 0; r < 2; r++) {
            int f  = tid + r * 256;
            int m  = f >> 2;
            int kk = (f & 3) * 4;
            float4 v = *(const float4*)(X + (size_t)(bm + m) * Dd + k0 + kk);
            As[kk + 0][m] = v.x; As[kk + 1][m] = v.y;
            As[kk + 2][m] = v.z; As[kk + 3][m] = v.w;
        }
        #pragma unroll
        for (int r = 0; r < 2; r++) {
            int f  = tid + r * 256;
            int kk = f >> 5;
            int nn = (f & 31) * 4;
            float4 v = *(const float4*)(W + (size_t)(k0 + kk) * Dd + bn + nn);
            *(float4*)&Bs[kk][nn] = v;
        }
        __syncthreads();

        #pragma unroll
        for (int k = 0; k < 16; k++) {
            float a[8], b[8];
            float4 a0 = *(const float4*)&As[k][ty * 8];
            float4 a1 = *(const float4*)&As[k][ty * 8 + 4];
            float4 b0 = *(const float4*)&Bs[k][tx * 8];
            float4 b1 = *(const float4*)&Bs[k][tx * 8 + 4];
            a[0]=a0.x; a[1]=a0.y; a[2]=a0.z; a[3]=a0.w;
            a[4]=a1.x; a[5]=a1.y; a[6]=a1.z; a[7]=a1.w;
            b[0]=b0.x; b[1]=b0.y; b[2]=b0.z; b[3]=b0.w;
            b[4]=b1.x; b[5]=b1.y; b[6]=b1.z; b[7]=b1.w;
            #pragma unroll
            for (int i = 0; i < 8; i++)
                #pragma unroll
                for (int j = 0; j < 8; j++)
                    acc[i][j] += a[i] * b[j];
        }
        __syncthreads();
    }

    #pragma unroll
    for (int i = 0; i < 8; i++) {
        int m  = bm + ty * 8 + i;
        int b  = m >> 10;
        int ns = m & 1023;
        #pragma unroll
        for (int j = 0; j < 8; j++) {
            int c = bn + tx * 8 + j;
            float val = acc[i][j] + bias[c];
            __nv_bfloat16 hi = __float2bfloat16(val);
            __nv_bfloat16 lo = __float2bfloat16(val - __bfloat162float(hi));
            int h = c >> 6, d = c & 63;
            size_t dst;
            if (which == 2)
                dst = ((size_t)(b * Hh + h) * DHd + d) * Nn + ns;       // V^T
            else
                dst = ((size_t)(b * Hh + h) * Nn + ns) * DHd + d;       // Q/K
            Hi[dst] = hi;
            Lo[dst] = lo;
        }
    }
}

// ---------------------------------------------------------------------------
// HMMA flash attention. grid = (8 q-tiles, 64 bh), 256 threads (8 warps).
// Warp w owns q rows [w*16, w*16+16). Key tiles of 64. All softmax state and
// P fragments live in registers (quad shfl reductions, C->A frag identity).
// ---------------------------------------------------------------------------
#define OFF_QH 0
#define OFF_QL 32768
#define OFF_KH 65536
#define OFF_KL 73728
#define OFF_VH 81920
#define OFF_VL 90112
#define SMEM_FA 98304

__global__ __launch_bounds__(256) void fa_kernel(float* __restrict__ y)
{
    extern __shared__ char s[];
    const unsigned base_u = smem_u32(s);

    const int tid  = threadIdx.x;
    const int w    = tid >> 5;
    const int lane = tid & 31;
    const int g    = lane >> 2;       // row in frag quad
    const int t2   = (lane & 3) * 2;  // col pair offset
    const int bh   = blockIdx.y;
    const int b    = bh >> 3, h = bh & 7;
    const int qt   = blockIdx.x;
    const int q0   = qt * 128;
    const int wq0  = w * 16;          // warp's row base within tile

    // ldmatrix lane-address components
    const int mrow = lane & 7;
    const int sel  = lane >> 3;       // 0..3

    // ---- load Q tiles (128 x 64 bf16, swizzled 128B rows) ----
    const char* qh_src = (const char*)(g_qh + ((size_t)bh * Nn + q0) * DHd);
    const char* ql_src = (const char*)(g_ql + ((size_t)bh * Nn + q0) * DHd);
    #pragma unroll
    for (int rr = 0; rr < 4; rr++) {
        int idx = tid + rr * 256;         // 0..1023
        int row = idx >> 3, c16 = idx & 7;
        unsigned byte = row * 128 + c16 * 16;
        unsigned sw = SMEM_SWZ(byte);
        *(float4*)(s + OFF_QH + sw) = *(const float4*)(qh_src + byte);
        *(float4*)(s + OFF_QL + sw) = *(const float4*)(ql_src + byte);
    }
    __syncthreads();

    // hoist Q A-fragments: 4 k-steps x 4 regs x 2 splits
    unsigned qh[4][4], ql[4][4];
    {
        int arow = wq0 + ((sel & 1) << 3) + mrow;
        #pragma unroll
        for (int ks = 0; ks < 4; ks++) {
            unsigned byte = arow * 128 + ks * 32 + ((sel >> 1) << 4);
            unsigned sw = SMEM_SWZ(byte);
            ldsm4(qh[ks], base_u + OFF_QH + sw);
            ldsm4(ql[ks], base_u + OFF_QL + sw);
        }
    }

    const char* kh_base = (const char*)(g_kh  + (size_t)bh * Nn * DHd);
    const char* kl_base = (const char*)(g_kl  + (size_t)bh * Nn * DHd);
    const char* vh_base = (const char*)(g_vth + (size_t)bh * DHd * Nn);
    const char* vl_base = (const char*)(g_vtl + (size_t)bh * DHd * Nn);

    float m0 = -1e30f, m1 = -1e30f, l0 = 0.0f, l1 = 0.0f;
    float o[8][4];
    #pragma unroll
    for (int i = 0; i < 8; i++)
        #pragma unroll
        for (int v = 0; v < 4; v++) o[i][v] = 0.0f;

    // B/V-frag lane address bases (row/k byte within tile)
    const int brow_off = ((sel >> 1) << 3) + mrow;   // + np*16
    const int bkb      = (sel & 1) << 4;             // + ks*32

    for (int t = 0; t < 16; t++) {
        const int t0 = t << 6;

        // ---- load K tile (64 keys x 64 d) and V^T tile (64 d x 64 keys) ----
        #pragma unroll
        for (int rr = 0; rr < 2; rr++) {
            int idx = tid + rr * 256;       // 0..511
            int row = idx >> 3, c16 = idx & 7;
            unsigned byte = row * 128 + c16 * 16;
            unsigned sw = SMEM_SWZ(byte);
            unsigned kof = (unsigned)(t0 + row) * 128 + c16 * 16;
            *(float4*)(s + OFF_KH + sw) = *(const float4*)(kh_base + kof);
            *(float4*)(s + OFF_KL + sw) = *(const float4*)(kl_base + kof);
            unsigned vof = (unsigned)row * 2048 + (unsigned)t0 * 2 + c16 * 16;
            *(float4*)(s + OFF_VH + sw) = *(const float4*)(vh_base + vof);
            *(float4*)(s + OFF_VL + sw) = *(const float4*)(vl_base + vof);
        }
        __syncthreads();

        // ---- S = Q K^T (3-way split), c[j][*] for 8 n-tiles ----
        float c[8][4];
        #pragma unroll
        for (int j = 0; j < 8; j++)
            #pragma unroll
            for (int v = 0; v < 4; v++) c[j][v] = 0.0f;

        #pragma unroll
        for (int ks = 0; ks < 4; ks++) {
            #pragma unroll
            for (int np = 0; np < 4; np++) {
                unsigned byte = (np * 16 + brow_off) * 128 + ks * 32 + bkb;
                unsigned sw = SMEM_SWZ(byte);
                unsigned kh4[4], kl4[4];
                ldsm4(kh4, base_u + OFF_KH + sw);
                ldsm4(kl4, base_u + OFF_KL + sw);
                mma16816(c[2*np],   qh[ks], kh4);
                mma16816(c[2*np],   qh[ks], kl4);
                mma16816(c[2*np],   ql[ks], kh4);
                mma16816(c[2*np+1], qh[ks], kh4 + 2);
                mma16816(c[2*np+1], qh[ks], kl4 + 2);
                mma16816(c[2*np+1], ql[ks], kh4 + 2);
            }
        }

        // ---- online softmax (rows g and g+8), all in registers ----
        float rm0 = -1e30f, rm1 = -1e30f;
        #pragma unroll
        for (int j = 0; j < 8; j++) {
            rm0 = fmaxf(rm0, fmaxf(c[j][0], c[j][1]));
            rm1 = fmaxf(rm1, fmaxf(c[j][2], c[j][3]));
        }
        rm0 = fmaxf(rm0, __shfl_xor_sync(0xFFFFFFFFu, rm0, 1));
        rm0 = fmaxf(rm0, __shfl_xor_sync(0xFFFFFFFFu, rm0, 2));
        rm1 = fmaxf(rm1, __shfl_xor_sync(0xFFFFFFFFu, rm1, 1));
        rm1 = fmaxf(rm1, __shfl_xor_sync(0xFFFFFFFFu, rm1, 2));

        float mn0 = fmaxf(m0, rm0), mn1 = fmaxf(m1, rm1);
        float cr0 = __expf(m0 - mn0), cr1 = __expf(m1 - mn1);
        m0 = mn0; m1 = mn1;

        float rs0 = 0.0f, rs1 = 0.0f;
        #pragma unroll
        for (int j = 0; j < 8; j++) {
            c[j][0] = __expf(c[j][0] - m0);
            c[j][1] = __expf(c[j][1] - m0);
            c[j][2] = __expf(c[j][2] - m1);
            c[j][3] = __expf(c[j][3] - m1);
            rs0 += c[j][0] + c[j][1];
            rs1 += c[j][2] + c[j][3];
        }
        rs0 += __shfl_xor_sync(0xFFFFFFFFu, rs0, 1);
        rs0 += __shfl_xor_sync(0xFFFFFFFFu, rs0, 2);
        rs1 += __shfl_xor_sync(0xFFFFFFFFu, rs1, 1);
        rs1 += __shfl_xor_sync(0xFFFFFFFFu, rs1, 2);
        l0 = l0 * cr0 + rs0;
        l1 = l1 * cr1 + rs1;

        #pragma unroll
        for (int jd = 0; jd < 8; jd++) {
            o[jd][0] *= cr0; o[jd][1] *= cr0;
            o[jd][2] *= cr1; o[jd][3] *= cr1;
        }

        // ---- build P A-fragments (hi + residual lo) in registers ----
        unsigned ph[4][4], pl[4][4];
        #pragma unroll
        for (int ks = 0; ks < 4; ks++) {
            #pragma unroll
            for (int u = 0; u < 4; u++) {
                int j = 2 * ks + (u >> 1);
                int v = (u & 1) * 2;
                float e0 = c[j][v], e1 = c[j][v + 1];
                __nv_bfloat162 hv = __float22bfloat162_rn(make_float2(e0, e1));
                float r0f = e0 - __bfloat162float(hv.x);
                float r1f = e1 - __bfloat162float(hv.y);
                __nv_bfloat162 lv = __float22bfloat162_rn(make_float2(r0f, r1f));
                ph[ks][u] = *(unsigned*)&hv;
                pl[ks][u] = *(unsigned*)&lv;
            }
        }

        // ---- O += P V (3-way split) ----
        #pragma unroll
        for (int ks = 0; ks < 4; ks++) {
            #pragma unroll
            for (int dp = 0; dp < 4; dp++) {
                unsigned byte = (dp * 16 + brow_off) * 128 + ks * 32 + bkb;
                unsigned sw = SMEM_SWZ(byte);
                unsigned vh4[4], vl4[4];
                ldsm4(vh4, base_u + OFF_VH + sw);
                ldsm4(vl4, base_u + OFF_VL + sw);
                mma16816(o[2*dp],   ph[ks], vh4);
                mma16816(o[2*dp],   ph[ks], vl4);
                mma16816(o[2*dp],   pl[ks], vh4);
                mma16816(o[2*dp+1], ph[ks], vh4 + 2);
                mma16816(o[2*dp+1], ph[ks], vl4 + 2);
                mma16816(o[2*dp+1], pl[ks], vh4 + 2);
            }
        }
        __syncthreads();
    }

    // ---- normalize and write out ----
    float inv0 = 1.0f / l0, inv1 = 1.0f / l1;
    int row0 = q0 + wq0 + g;
    int row1 = row0 + 8;
    float* y0 = y + ((size_t)(b * Nn + row0)) * Dd + h * DHd;
    float* y1 = y + ((size_t)(b * Nn + row1)) * Dd + h * DHd;
    #pragma unroll
    for (int jd = 0; jd < 8; jd++) {
        float2 p0 = make_float2(o[jd][0] * inv0, o[jd][1] * inv0);
        float2 p1 = make_float2(o[jd][2] * inv1, o[jd][3] * inv1);
        *(float2*)(y0 + jd * 8 + t2) = p0;
        *(float2*)(y1 + jd * 8 + t2) = p1;
    }
}

// ---------------------------------------------------------------------------
// Inputs (metadata order): x, Wq, bq, Wk, bk, Wv, bv. Output: float32 [B,N,D].
// ---------------------------------------------------------------------------
extern "C" void kernel_launch(void* const* d_in, const int* in_sizes, int n_in,
                              void* d_out, int out_size)
{
    const float* x  = (const float*)d_in[0];
    const float* Wq = (const float*)d_in[1];
    const float* bq = (const float*)d_in[2];
    const float* Wk = (const float*)d_in[3];
    const float* bk = (const float*)d_in[4];
    const float* Wv = (const float*)d_in[5];
    const float* bv = (const float*)d_in[6];
    float* y = (float*)d_out;

    cudaFuncSetAttribute(fa_kernel, cudaFuncAttributeMaxDynamicSharedMemorySize, SMEM_FA);

    dim3 ggrid(MTOT / 128, Dd / 128);   // (64, 4)
    gemm_bias_kernel<<<ggrid, 256>>>(x, Wq, bq, 0);
    gemm_bias_kernel<<<ggrid, 256>>>(x, Wk, bk, 1);
    gemm_bias_kernel<<<ggrid, 256>>>(x, Wv, bv, 2);

    dim3 agrid(Nn / 128, BH);           // (8, 64)
    fa_kernel<<<agrid, 256, SMEM_FA>>>(y);
}

// round 5
// speedup vs baseline: 2.9132x; 1.5086x over previous
#include <cuda_runtime.h>
#include <cuda_bf16.h>

// Problem constants
#define Bb   8
#define Nn   1024
#define Dd   512
#define Hh   8
#define DHd  64
#define MTOT (Bb*Nn)   // 8192
#define BH   (Bb*Hh)   // 64

// Split-bf16 operands for the projection GEMMs
__device__ __nv_bfloat16 g_xh[MTOT*Dd];
__device__ __nv_bfloat16 g_xl[MTOT*Dd];
__device__ __nv_bfloat16 g_wth[3*Dd*Dd];   // W^T per proj: [n][k]
__device__ __nv_bfloat16 g_wtl[3*Dd*Dd];

// bf16 split-precision Q/K (head-major [BH, N, 64]) and transposed V ([BH, 64, N])
__device__ __nv_bfloat16 g_qh[BH*Nn*DHd];
__device__ __nv_bfloat16 g_ql[BH*Nn*DHd];
__device__ __nv_bfloat16 g_kh[BH*Nn*DHd];
__device__ __nv_bfloat16 g_kl[BH*Nn*DHd];
__device__ __nv_bfloat16 g_vth[BH*DHd*Nn];
__device__ __nv_bfloat16 g_vtl[BH*DHd*Nn];

#define SMEM_SWZ(b) ((b) ^ (((b) >> 3) & 0x70))

static __device__ __forceinline__ unsigned smem_u32(const void* p) {
    unsigned a;
    asm("{ .reg .u64 t; cvta.to.shared.u64 t, %1; cvt.u32.u64 %0, t; }" : "=r"(a) : "l"(p));
    return a;
}

// mma.sync m16n8k16 bf16 -> fp32 (sm_80+, no arch-feature gating)
static __device__ __forceinline__ void mma16816(float* c, const unsigned* a, const unsigned* b) {
    asm volatile(
        "mma.sync.aligned.m16n8k16.row.col.f32.bf16.bf16.f32 "
        "{%0,%1,%2,%3}, {%4,%5,%6,%7}, {%8,%9}, {%0,%1,%2,%3};"
        : "+f"(c[0]), "+f"(c[1]), "+f"(c[2]), "+f"(c[3])
        : "r"(a[0]), "r"(a[1]), "r"(a[2]), "r"(a[3]), "r"(b[0]), "r"(b[1]));
}

static __device__ __forceinline__ void ldsm4(unsigned* r, unsigned addr) {
    asm volatile("ldmatrix.sync.aligned.m8n8.x4.shared.b16 {%0,%1,%2,%3}, [%4];"
                 : "=r"(r[0]), "=r"(r[1]), "=r"(r[2]), "=r"(r[3]) : "r"(addr));
}

static __device__ __forceinline__ void split2(float v, __nv_bfloat16& hi, __nv_bfloat16& lo) {
    hi = __float2bfloat16(v);
    lo = __float2bfloat16(v - __bfloat162float(hi));
}

// ---------------------------------------------------------------------------
// split_x: x fp32 [8192,512] -> g_xh/g_xl bf16. One float4 per thread.
// ---------------------------------------------------------------------------
__global__ __launch_bounds__(256) void split_x_kernel(const float* __restrict__ x)
{
    int i = blockIdx.x * 256 + threadIdx.x;          // float4 index, < 1048576
    float4 v = ((const float4*)x)[i];
    __nv_bfloat16 h[4], l[4];
    split2(v.x, h[0], l[0]); split2(v.y, h[1], l[1]);
    split2(v.z, h[2], l[2]); split2(v.w, h[3], l[3]);
    ((uint2*)g_xh)[i] = *(uint2*)h;
    ((uint2*)g_xl)[i] = *(uint2*)l;
}

// ---------------------------------------------------------------------------
// split_wt: W [512,512] ([k][n]) -> W^T hi/lo [n][k]. 64x64 tiles.
// grid (8, 8, 3), 256 threads.
// ---------------------------------------------------------------------------
__global__ __launch_bounds__(256) void split_wt_kernel(
    const float* __restrict__ W0, const float* __restrict__ W1,
    const float* __restrict__ W2)
{
    const float* W = (blockIdx.z == 0) ? W0 : (blockIdx.z == 1) ? W1 : W2;
    __nv_bfloat16* Oh = g_wth + (size_t)blockIdx.z * Dd * Dd;
    __nv_bfloat16* Ol = g_wtl + (size_t)blockIdx.z * Dd * Dd;

    __shared__ __nv_bfloat16 sh[64][68];
    __shared__ __nv_bfloat16 sl[64][68];

    const int k0 = blockIdx.y * 64;
    const int n0 = blockIdx.x * 64;
    const int tid = threadIdx.x;

    // read W[k0+r][n0+c], store transposed into smem [n][k]
    int r = tid >> 2;                  // 0..63 (k-local)
    int cs = (tid & 3) * 16;           // n-local segment
    #pragma unroll
    for (int j = 0; j < 4; j++) {
        float4 v = *(const float4*)(W + (size_t)(k0 + r) * Dd + n0 + cs + j * 4);
        __nv_bfloat16 h, l;
        split2(v.x, h, l); sh[cs + j*4 + 0][r] = h; sl[cs + j*4 + 0][r] = l;
        split2(v.y, h, l); sh[cs + j*4 + 1][r] = h; sl[cs + j*4 + 1][r] = l;
        split2(v.z, h, l); sh[cs + j*4 + 2][r] = h; sl[cs + j*4 + 2][r] = l;
        split2(v.w, h, l); sh[cs + j*4 + 3][r] = h; sl[cs + j*4 + 3][r] = l;
    }
    __syncthreads();

    // write rows of W^T: [n0+n][k0 + kseg..+16]
    int n = tid >> 2;
    int ks = (tid & 3) * 16;
    #pragma unroll
    for (int j = 0; j < 8; j++) {
        __nv_bfloat16 p0 = sh[n][ks + j*2], p1 = sh[n][ks + j*2 + 1];
        unsigned uh = (unsigned)__bfloat16_as_ushort(p0) | ((unsigned)__bfloat16_as_ushort(p1) << 16);
        p0 = sl[n][ks + j*2]; p1 = sl[n][ks + j*2 + 1];
        unsigned ul = (unsigned)__bfloat16_as_ushort(p0) | ((unsigned)__bfloat16_as_ushort(p1) << 16);
        *(unsigned*)(Oh + (size_t)(n0 + n) * Dd + k0 + ks + j*2) = uh;
        *(unsigned*)(Ol + (size_t)(n0 + n) * Dd + k0 + ks + j*2) = ul;
    }
}

// ---------------------------------------------------------------------------
// HMMA projection GEMM: C[8192,512] = X @ W + bias via 3-way split bf16 MMA.
// 128x128 tile, 256 threads (8 warps, 2x4 warp grid, 64x32 per warp), KT=64.
// Epilogue: bias add + hi/lo split, Q/K head-major or V transposed.
// ---------------------------------------------------------------------------
#define OFF_AH 0
#define OFF_AL 16384
#define OFF_BH 32768
#define OFF_BL 49152
#define SMEM_GEMM 65536

__global__ __launch_bounds__(256, 1) void gemm_hmma_kernel(
    const float* __restrict__ bias, int which)
{
    extern __shared__ char s[];
    const unsigned base_u = smem_u32(s);

    __nv_bfloat16* Hi = (which == 0) ? g_qh : (which == 1) ? g_kh : g_vth;
    __nv_bfloat16* Lo = (which == 0) ? g_ql : (which == 1) ? g_kl : g_vtl;
    const char* wh_base = (const char*)(g_wth + (size_t)which * Dd * Dd);
    const char* wl_base = (const char*)(g_wtl + (size_t)which * Dd * Dd);
    const char* xh_base = (const char*)g_xh;
    const char* xl_base = (const char*)g_xl;

    const int tid  = threadIdx.x;
    const int w    = tid >> 5;
    const int lane = tid & 31;
    const int g    = lane >> 2;
    const int mrow = lane & 7;
    const int sel  = lane >> 3;
    const int wm0  = (w >> 2) * 64;    // warp m offset in tile
    const int wn0  = (w & 3) * 32;     // warp n offset in tile
    const int bm   = blockIdx.x * 128;
    const int bn   = blockIdx.y * 128;

    const int a_row_off = ((sel & 1) << 3) + mrow;
    const int a_k_off   = (sel >> 1) << 4;
    const int brow_off  = ((sel >> 1) << 3) + mrow;
    const int bkb       = (sel & 1) << 4;

    float c[4][4][4];
    #pragma unroll
    for (int mi = 0; mi < 4; mi++)
        #pragma unroll
        for (int nj = 0; nj < 4; nj++)
            #pragma unroll
            for (int v = 0; v < 4; v++) c[mi][nj][v] = 0.0f;

    for (int kt = 0; kt < 8; kt++) {
        // load A (X rows bm..bm+128, k slice) and B (W^T rows bn..+128, k slice)
        #pragma unroll
        for (int rr = 0; rr < 4; rr++) {
            int idx = tid + rr * 256;            // 0..1023
            int row = idx >> 3, c16 = idx & 7;
            unsigned byte = row * 128 + c16 * 16;
            unsigned sw = SMEM_SWZ(byte);
            unsigned gA = (unsigned)(bm + row) * 1024 + kt * 128 + c16 * 16;
            unsigned gB = (unsigned)(bn + row) * 1024 + kt * 128 + c16 * 16;
            *(float4*)(s + OFF_AH + sw) = *(const float4*)(xh_base + gA);
            *(float4*)(s + OFF_AL + sw) = *(const float4*)(xl_base + gA);
            *(float4*)(s + OFF_BH + sw) = *(const float4*)(wh_base + gB);
            *(float4*)(s + OFF_BL + sw) = *(const float4*)(wl_base + gB);
        }
        __syncthreads();

        #pragma unroll
        for (int ks = 0; ks < 4; ks++) {
            unsigned ah[4][4], al[4][4];
            #pragma unroll
            for (int mi = 0; mi < 4; mi++) {
                unsigned byte = (wm0 + mi * 16 + a_row_off) * 128 + ks * 32 + a_k_off;
                unsigned sw = SMEM_SWZ(byte);
                ldsm4(ah[mi], base_u + OFF_AH + sw);
                ldsm4(al[mi], base_u + OFF_AL + sw);
            }
            unsigned bh4[2][4], bl4[2][4];
            #pragma unroll
            for (int np = 0; np < 2; np++) {
                unsigned byte = (wn0 + np * 16 + brow_off) * 128 + ks * 32 + bkb;
                unsigned sw = SMEM_SWZ(byte);
                ldsm4(bh4[np], base_u + OFF_BH + sw);
                ldsm4(bl4[np], base_u + OFF_BL + sw);
            }
            #pragma unroll
            for (int mi = 0; mi < 4; mi++)
                #pragma unroll
                for (int nj = 0; nj < 4; nj++) {
                    const unsigned* bp_h = bh4[nj >> 1] + (nj & 1) * 2;
                    const unsigned* bp_l = bl4[nj >> 1] + (nj & 1) * 2;
                    mma16816(c[mi][nj], ah[mi], bp_h);
                    mma16816(c[mi][nj], ah[mi], bp_l);
                    mma16816(c[mi][nj], al[mi], bp_h);
                }
        }
        __syncthreads();
    }

    // Epilogue: bias + split + scatter
    #pragma unroll
    for (int nj = 0; nj < 4; nj++) {
        int cb = bn + wn0 + nj * 8 + (lane & 3) * 2;
        float b0 = __ldg(bias + cb), b1 = __ldg(bias + cb + 1);
        int h0 = cb >> 6, d0 = cb & 63;
        int h1 = (cb + 1) >> 6, d1 = (cb + 1) & 63;
        #pragma unroll
        for (int mi = 0; mi < 4; mi++) {
            #pragma unroll
            for (int half = 0; half < 2; half++) {
                int m = bm + wm0 + mi * 16 + g + half * 8;
                int bb = m >> 10, ns = m & 1023;
                float v0 = c[mi][nj][half * 2 + 0] + b0;
                float v1 = c[mi][nj][half * 2 + 1] + b1;
                __nv_bfloat16 hi, lo;
                size_t dst0, dst1;
                if (which == 2) {
                    dst0 = ((size_t)(bb * Hh + h0) * DHd + d0) * Nn + ns;
                    dst1 = ((size_t)(bb * Hh + h1) * DHd + d1) * Nn + ns;
                } else {
                    dst0 = ((size_t)(bb * Hh + h0) * Nn + ns) * DHd + d0;
                    dst1 = dst0 + (d1 - d0) + (size_t)(h1 - h0) * Nn * DHd;
                }
                split2(v0, hi, lo); Hi[dst0] = hi; Lo[dst0] = lo;
                split2(v1, hi, lo); Hi[dst1] = hi; Lo[dst1] = lo;
            }
        }
    }
}

// ---------------------------------------------------------------------------
// HMMA flash attention (unchanged from round 3). grid = (8, 64), 256 threads.
// ---------------------------------------------------------------------------
#define OFF_QH 0
#define OFF_QL 32768
#define OFF_KH 65536
#define OFF_KL 73728
#define OFF_VH 81920
#define OFF_VL 90112
#define SMEM_FA 98304

__global__ __launch_bounds__(256) void fa_kernel(float* __restrict__ y)
{
    extern __shared__ char s[];
    const unsigned base_u = smem_u32(s);

    const int tid  = threadIdx.x;
    const int w    = tid >> 5;
    const int lane = tid & 31;
    const int g    = lane >> 2;
    const int t2   = (lane & 3) * 2;
    const int bh   = blockIdx.y;
    const int b    = bh >> 3, h = bh & 7;
    const int qt   = blockIdx.x;
    const int q0   = qt * 128;
    const int wq0  = w * 16;

    const int mrow = lane & 7;
    const int sel  = lane >> 3;

    const char* qh_src = (const char*)(g_qh + ((size_t)bh * Nn + q0) * DHd);
    const char* ql_src = (const char*)(g_ql + ((size_t)bh * Nn + q0) * DHd);
    #pragma unroll
    for (int rr = 0; rr < 4; rr++) {
        int idx = tid + rr * 256;
        int row = idx >> 3, c16 = idx & 7;
        unsigned byte = row * 128 + c16 * 16;
        unsigned sw = SMEM_SWZ(byte);
        *(float4*)(s + OFF_QH + sw) = *(const float4*)(qh_src + byte);
        *(float4*)(s + OFF_QL + sw) = *(const float4*)(ql_src + byte);
    }
    __syncthreads();

    unsigned qh[4][4], ql[4][4];
    {
        int arow = wq0 + ((sel & 1) << 3) + mrow;
        #pragma unroll
        for (int ks = 0; ks < 4; ks++) {
            unsigned byte = arow * 128 + ks * 32 + ((sel >> 1) << 4);
            unsigned sw = SMEM_SWZ(byte);
            ldsm4(qh[ks], base_u + OFF_QH + sw);
            ldsm4(ql[ks], base_u + OFF_QL + sw);
        }
    }

    const char* kh_base = (const char*)(g_kh  + (size_t)bh * Nn * DHd);
    const char* kl_base = (const char*)(g_kl  + (size_t)bh * Nn * DHd);
    const char* vh_base = (const char*)(g_vth + (size_t)bh * DHd * Nn);
    const char* vl_base = (const char*)(g_vtl + (size_t)bh * DHd * Nn);

    float m0 = -1e30f, m1 = -1e30f, l0 = 0.0f, l1 = 0.0f;
    float o[8][4];
    #pragma unroll
    for (int i = 0; i < 8; i++)
        #pragma unroll
        for (int v = 0; v < 4; v++) o[i][v] = 0.0f;

    const int brow_off = ((sel >> 1) << 3) + mrow;
    const int bkb      = (sel & 1) << 4;

    for (int t = 0; t < 16; t++) {
        const int t0 = t << 6;

        #pragma unroll
        for (int rr = 0; rr < 2; rr++) {
            int idx = tid + rr * 256;
            int row = idx >> 3, c16 = idx & 7;
            unsigned byte = row * 128 + c16 * 16;
            unsigned sw = SMEM_SWZ(byte);
            unsigned kof = (unsigned)(t0 + row) * 128 + c16 * 16;
            *(float4*)(s + OFF_KH + sw) = *(const float4*)(kh_base + kof);
            *(float4*)(s + OFF_KL + sw) = *(const float4*)(kl_base + kof);
            unsigned vof = (unsigned)row * 2048 + (unsigned)t0 * 2 + c16 * 16;
            *(float4*)(s + OFF_VH + sw) = *(const float4*)(vh_base + vof);
            *(float4*)(s + OFF_VL + sw) = *(const float4*)(vl_base + vof);
        }
        __syncthreads();

        float c[8][4];
        #pragma unroll
        for (int j = 0; j < 8; j++)
            #pragma unroll
            for (int v = 0; v < 4; v++) c[j][v] = 0.0f;

        #pragma unroll
        for (int ks = 0; ks < 4; ks++) {
            #pragma unroll
            for (int np = 0; np < 4; np++) {
                unsigned byte = (np * 16 + brow_off) * 128 + ks * 32 + bkb;
                unsigned sw = SMEM_SWZ(byte);
                unsigned kh4[4], kl4[4];
                ldsm4(kh4, base_u + OFF_KH + sw);
                ldsm4(kl4, base_u + OFF_KL + sw);
                mma16816(c[2*np],   qh[ks], kh4);
                mma16816(c[2*np],   qh[ks], kl4);
                mma16816(c[2*np],   ql[ks], kh4);
                mma16816(c[2*np+1], qh[ks], kh4 + 2);
                mma16816(c[2*np+1], qh[ks], kl4 + 2);
                mma16816(c[2*np+1], ql[ks], kh4 + 2);
            }
        }

        float rm0 = -1e30f, rm1 = -1e30f;
        #pragma unroll
        for (int j = 0; j < 8; j++) {
            rm0 = fmaxf(rm0, fmaxf(c[j][0], c[j][1]));
            rm1 = fmaxf(rm1, fmaxf(c[j][2], c[j][3]));
        }
        rm0 = fmaxf(rm0, __shfl_xor_sync(0xFFFFFFFFu, rm0, 1));
        rm0 = fmaxf(rm0, __shfl_xor_sync(0xFFFFFFFFu, rm0, 2));
        rm1 = fmaxf(rm1, __shfl_xor_sync(0xFFFFFFFFu, rm1, 1));
        rm1 = fmaxf(rm1, __shfl_xor_sync(0xFFFFFFFFu, rm1, 2));

        float mn0 = fmaxf(m0, rm0), mn1 = fmaxf(m1, rm1);
        float cr0 = __expf(m0 - mn0), cr1 = __expf(m1 - mn1);
        m0 = mn0; m1 = mn1;

        float rs0 = 0.0f, rs1 = 0.0f;
        #pragma unroll
        for (int j = 0; j < 8; j++) {
            c[j][0] = __expf(c[j][0] - m0);
            c[j][1] = __expf(c[j][1] - m0);
            c[j][2] = __expf(c[j][2] - m1);
            c[j][3] = __expf(c[j][3] - m1);
            rs0 += c[j][0] + c[j][1];
            rs1 += c[j][2] + c[j][3];
        }
        rs0 += __shfl_xor_sync(0xFFFFFFFFu, rs0, 1);
        rs0 += __shfl_xor_sync(0xFFFFFFFFu, rs0, 2);
        rs1 += __shfl_xor_sync(0xFFFFFFFFu, rs1, 1);
        rs1 += __shfl_xor_sync(0xFFFFFFFFu, rs1, 2);
        l0 = l0 * cr0 + rs0;
        l1 = l1 * cr1 + rs1;

        #pragma unroll
        for (int jd = 0; jd < 8; jd++) {
            o[jd][0] *= cr0; o[jd][1] *= cr0;
            o[jd][2] *= cr1; o[jd][3] *= cr1;
        }

        unsigned ph[4][4], pl[4][4];
        #pragma unroll
        for (int ks = 0; ks < 4; ks++) {
            #pragma unroll
            for (int u = 0; u < 4; u++) {
                int j = 2 * ks + (u >> 1);
                int v = (u & 1) * 2;
                float e0 = c[j][v], e1 = c[j][v + 1];
                __nv_bfloat162 hv = __float22bfloat162_rn(make_float2(e0, e1));
                float r0f = e0 - __bfloat162float(hv.x);
                float r1f = e1 - __bfloat162float(hv.y);
                __nv_bfloat162 lv = __float22bfloat162_rn(make_float2(r0f, r1f));
                ph[ks][u] = *(unsigned*)&hv;
                pl[ks][u] = *(unsigned*)&lv;
            }
        }

        #pragma unroll
        for (int ks = 0; ks < 4; ks++) {
            #pragma unroll
            for (int dp = 0; dp < 4; dp++) {
                unsigned byte = (dp * 16 + brow_off) * 128 + ks * 32 + bkb;
                unsigned sw = SMEM_SWZ(byte);
                unsigned vh4[4], vl4[4];
                ldsm4(vh4, base_u + OFF_VH + sw);
                ldsm4(vl4, base_u + OFF_VL + sw);
                mma16816(o[2*dp],   ph[ks], vh4);
                mma16816(o[2*dp],   ph[ks], vl4);
                mma16816(o[2*dp],   pl[ks], vh4);
                mma16816(o[2*dp+1], ph[ks], vh4 + 2);
                mma16816(o[2*dp+1], ph[ks], vl4 + 2);
                mma16816(o[2*dp+1], pl[ks], vh4 + 2);
            }
        }
        __syncthreads();
    }

    float inv0 = 1.0f / l0, inv1 = 1.0f / l1;
    int row0 = q0 + wq0 + g;
    int row1 = row0 + 8;
    float* y0 = y + ((size_t)(b * Nn + row0)) * Dd + h * DHd;
    float* y1 = y + ((size_t)(b * Nn + row1)) * Dd + h * DHd;
    #pragma unroll
    for (int jd = 0; jd < 8; jd++) {
        float2 p0 = make_float2(o[jd][0] * inv0, o[jd][1] * inv0);
        float2 p1 = make_float2(o[jd][2] * inv1, o[jd][3] * inv1);
        *(float2*)(y0 + jd * 8 + t2) = p0;
        *(float2*)(y1 + jd * 8 + t2) = p1;
    }
}

// ---------------------------------------------------------------------------
// Inputs (metadata order): x, Wq, bq, Wk, bk, Wv, bv. Output: float32 [B,N,D].
// ---------------------------------------------------------------------------
extern "C" void kernel_launch(void* const* d_in, const int* in_sizes, int n_in,
                              void* d_out, int out_size)
{
    const float* x  = (const float*)d_in[0];
    const float* Wq = (const float*)d_in[1];
    const float* bq = (const float*)d_in[2];
    const float* Wk = (const float*)d_in[3];
    const float* bk = (const float*)d_in[4];
    const float* Wv = (const float*)d_in[5];
    const float* bv = (const float*)d_in[6];
    float* y = (float*)d_out;

    cudaFuncSetAttribute(gemm_hmma_kernel, cudaFuncAttributeMaxDynamicSharedMemorySize, SMEM_GEMM);
    cudaFuncSetAttribute(fa_kernel, cudaFuncAttributeMaxDynamicSharedMemorySize, SMEM_FA);

    split_x_kernel<<<4096, 256>>>(x);
    split_wt_kernel<<<dim3(8, 8, 3), 256>>>(Wq, Wk, Wv);

    dim3 ggrid(MTOT / 128, Dd / 128);   // (64, 4)
    gemm_hmma_kernel<<<ggrid, 256, SMEM_GEMM>>>(bq, 0);
    gemm_hmma_kernel<<<ggrid, 256, SMEM_GEMM>>>(bk, 1);
    gemm_hmma_kernel<<<ggrid, 256, SMEM_GEMM>>>(bv, 2);

    dim3 agrid(Nn / 128, BH);           // (8, 64)
    fa_kernel<<<agrid, 256, SMEM_FA>>>(y);
}

// round 8
// speedup vs baseline: 3.6904x; 1.2668x over previous
#include <cuda_runtime.h>
#include <cuda_bf16.h>

// Problem constants
#define Bb   8
#define Nn   1024
#define Dd   512
#define Hh   8
#define DHd  64
#define MTOT (Bb*Nn)   // 8192
#define BH   (Bb*Hh)   // 64

// Split-bf16 operands for the projection GEMMs
__device__ __nv_bfloat16 g_xh[MTOT*Dd];
__device__ __nv_bfloat16 g_xl[MTOT*Dd];
__device__ __nv_bfloat16 g_wth[3*Dd*Dd];   // W^T per proj: [n][k]
__device__ __nv_bfloat16 g_wtl[3*Dd*Dd];

// bf16 split-precision Q/K (head-major [BH, N, 64]) and transposed V ([BH, 64, N])
__device__ __nv_bfloat16 g_qh[BH*Nn*DHd];
__device__ __nv_bfloat16 g_ql[BH*Nn*DHd];
__device__ __nv_bfloat16 g_kh[BH*Nn*DHd];
__device__ __nv_bfloat16 g_kl[BH*Nn*DHd];
__device__ __nv_bfloat16 g_vth[BH*DHd*Nn];
__device__ __nv_bfloat16 g_vtl[BH*DHd*Nn];

#define SMEM_SWZ(b) ((b) ^ (((b) >> 3) & 0x70))

static __device__ __forceinline__ unsigned smem_u32(const void* p) {
    unsigned a;
    asm("{ .reg .u64 t; cvta.to.shared.u64 t, %1; cvt.u32.u64 %0, t; }" : "=r"(a) : "l"(p));
    return a;
}

// cp.async helpers (sm_80+)
#define CP_ASYNC16(dst_u32, src_ptr) \
    asm volatile("cp.async.cg.shared.global [%0], [%1], 16;" :: "r"(dst_u32), "l"(src_ptr))
#define CP_COMMIT() asm volatile("cp.async.commit_group;")
#define CP_WAIT1()  asm volatile("cp.async.wait_group 1;")
#define CP_WAIT0()  asm volatile("cp.async.wait_group 0;")

// mma.sync m16n8k16 bf16 -> fp32 (sm_80+, no arch-feature gating)
static __device__ __forceinline__ void mma16816(float* c, const unsigned* a, const unsigned* b) {
    asm volatile(
        "mma.sync.aligned.m16n8k16.row.col.f32.bf16.bf16.f32 "
        "{%0,%1,%2,%3}, {%4,%5,%6,%7}, {%8,%9}, {%0,%1,%2,%3};"
        : "+f"(c[0]), "+f"(c[1]), "+f"(c[2]), "+f"(c[3])
        : "r"(a[0]), "r"(a[1]), "r"(a[2]), "r"(a[3]), "r"(b[0]), "r"(b[1]));
}

static __device__ __forceinline__ void ldsm4(unsigned* r, unsigned addr) {
    asm volatile("ldmatrix.sync.aligned.m8n8.x4.shared.b16 {%0,%1,%2,%3}, [%4];"
                 : "=r"(r[0]), "=r"(r[1]), "=r"(r[2]), "=r"(r[3]) : "r"(addr));
}

static __device__ __forceinline__ void split2(float v, __nv_bfloat16& hi, __nv_bfloat16& lo) {
    hi = __float2bfloat16(v);
    lo = __float2bfloat16(v - __bfloat162float(hi));
}

// ---------------------------------------------------------------------------
// split_x: x fp32 [8192,512] -> g_xh/g_xl bf16. One float4 per thread.
// ---------------------------------------------------------------------------
__global__ __launch_bounds__(256) void split_x_kernel(const float* __restrict__ x)
{
    int i = blockIdx.x * 256 + threadIdx.x;          // float4 index, < 1048576
    float4 v = ((const float4*)x)[i];
    __nv_bfloat16 h[4], l[4];
    split2(v.x, h[0], l[0]); split2(v.y, h[1], l[1]);
    split2(v.z, h[2], l[2]); split2(v.w, h[3], l[3]);
    ((uint2*)g_xh)[i] = *(uint2*)h;
    ((uint2*)g_xl)[i] = *(uint2*)l;
}

// ---------------------------------------------------------------------------
// split_wt: W [512,512] ([k][n]) -> W^T hi/lo [n][k]. 64x64 tiles.
// grid (8, 8, 3), 256 threads.
// ---------------------------------------------------------------------------
__global__ __launch_bounds__(256) void split_wt_kernel(
    const float* __restrict__ W0, const float* __restrict__ W1,
    const float* __restrict__ W2)
{
    const float* W = (blockIdx.z == 0) ? W0 : (blockIdx.z == 1) ? W1 : W2;
    __nv_bfloat16* Oh = g_wth + (size_t)blockIdx.z * Dd * Dd;
    __nv_bfloat16* Ol = g_wtl + (size_t)blockIdx.z * Dd * Dd;

    __shared__ __nv_bfloat16 sh[64][68];
    __shared__ __nv_bfloat16 sl[64][68];

    const int k0 = blockIdx.y * 64;
    const int n0 = blockIdx.x * 64;
    const int tid = threadIdx.x;

    int r = tid >> 2;
    int cs = (tid & 3) * 16;
    #pragma unroll
    for (int j = 0; j < 4; j++) {
        float4 v = *(const float4*)(W + (size_t)(k0 + r) * Dd + n0 + cs + j * 4);
        __nv_bfloat16 h, l;
        split2(v.x, h, l); sh[cs + j*4 + 0][r] = h; sl[cs + j*4 + 0][r] = l;
        split2(v.y, h, l); sh[cs + j*4 + 1][r] = h; sl[cs + j*4 + 1][r] = l;
        split2(v.z, h, l); sh[cs + j*4 + 2][r] = h; sl[cs + j*4 + 2][r] = l;
        split2(v.w, h, l); sh[cs + j*4 + 3][r] = h; sl[cs + j*4 + 3][r] = l;
    }
    __syncthreads();

    int n = tid >> 2;
    int ks = (tid & 3) * 16;
    #pragma unroll
    for (int j = 0; j < 8; j++) {
        __nv_bfloat16 p0 = sh[n][ks + j*2], p1 = sh[n][ks + j*2 + 1];
        unsigned uh = (unsigned)__bfloat16_as_ushort(p0) | ((unsigned)__bfloat16_as_ushort(p1) << 16);
        p0 = sl[n][ks + j*2]; p1 = sl[n][ks + j*2 + 1];
        unsigned ul = (unsigned)__bfloat16_as_ushort(p0) | ((unsigned)__bfloat16_as_ushort(p1) << 16);
        *(unsigned*)(Oh + (size_t)(n0 + n) * Dd + k0 + ks + j*2) = uh;
        *(unsigned*)(Ol + (size_t)(n0 + n) * Dd + k0 + ks + j*2) = ul;
    }
}

// ---------------------------------------------------------------------------
// HMMA projection GEMM, fused (gridDim.z picks proj), 2-stage cp.async pipe.
// 128x128 tile, 256 threads (2x4 warp grid, 64x32 per warp), KT=64 per stage.
// ---------------------------------------------------------------------------
#define GOFF_AH 0
#define GOFF_AL 16384
#define GOFF_BH 32768
#define GOFF_BL 49152
#define GSTAGE  65536
#define SMEM_GEMM (2*GSTAGE)

__global__ __launch_bounds__(256, 1) void gemm_hmma_kernel(
    const float* __restrict__ bq, const float* __restrict__ bk,
    const float* __restrict__ bv)
{
    extern __shared__ char s[];
    const unsigned base_u = smem_u32(s);

    const int which = blockIdx.z;
    const float* bias = (which == 0) ? bq : (which == 1) ? bk : bv;
    __nv_bfloat16* Hi = (which == 0) ? g_qh : (which == 1) ? g_kh : g_vth;
    __nv_bfloat16* Lo = (which == 0) ? g_ql : (which == 1) ? g_kl : g_vtl;
    const char* wh_base = (const char*)(g_wth + (size_t)which * Dd * Dd);
    const char* wl_base = (const char*)(g_wtl + (size_t)which * Dd * Dd);
    const char* xh_base = (const char*)g_xh;
    const char* xl_base = (const char*)g_xl;

    const int tid  = threadIdx.x;
    const int w    = tid >> 5;
    const int lane = tid & 31;
    const int g    = lane >> 2;
    const int mrow = lane & 7;
    const int sel  = lane >> 3;
    const int wm0  = (w >> 2) * 64;
    const int wn0  = (w & 3) * 32;
    const int bm   = blockIdx.x * 128;
    const int bn   = blockIdx.y * 128;

    const int a_row_off = ((sel & 1) << 3) + mrow;
    const int a_k_off   = (sel >> 1) << 4;
    const int brow_off  = ((sel >> 1) << 3) + mrow;
    const int bkb       = (sel & 1) << 4;

    // per-thread load addresses (4 rows of 16B per buffer)
    unsigned ld_sw[4];
    unsigned ld_gA[4], ld_gB[4];
    #pragma unroll
    for (int rr = 0; rr < 4; rr++) {
        int idx = tid + rr * 256;
        int row = idx >> 3, c16 = idx & 7;
        ld_sw[rr] = SMEM_SWZ((unsigned)(row * 128 + c16 * 16));
        ld_gA[rr] = (unsigned)(bm + row) * 1024 + c16 * 16;
        ld_gB[rr] = (unsigned)(bn + row) * 1024 + c16 * 16;
    }

    float c[4][4][4];
    #pragma unroll
    for (int mi = 0; mi < 4; mi++)
        #pragma unroll
        for (int nj = 0; nj < 4; nj++)
            #pragma unroll
            for (int v = 0; v < 4; v++) c[mi][nj][v] = 0.0f;

    // issue stage for k-tile kt
    auto issue = [&](int kt) {
        unsigned so = base_u + (kt & 1) * GSTAGE;
        unsigned ko = (unsigned)kt * 128;
        #pragma unroll
        for (int rr = 0; rr < 4; rr++) {
            CP_ASYNC16(so + GOFF_AH + ld_sw[rr], xh_base + ld_gA[rr] + ko);
            CP_ASYNC16(so + GOFF_AL + ld_sw[rr], xl_base + ld_gA[rr] + ko);
            CP_ASYNC16(so + GOFF_BH + ld_sw[rr], wh_base + ld_gB[rr] + ko);
            CP_ASYNC16(so + GOFF_BL + ld_sw[rr], wl_base + ld_gB[rr] + ko);
        }
        CP_COMMIT();
    };

    issue(0);
    for (int kt = 0; kt < 8; kt++) {
        if (kt < 7) { issue(kt + 1); CP_WAIT1(); } else { CP_WAIT0(); }
        __syncthreads();

        unsigned sb = base_u + (kt & 1) * GSTAGE;
        #pragma unroll
        for (int ks = 0; ks < 4; ks++) {
            unsigned ah[4][4], al[4][4];
            #pragma unroll
            for (int mi = 0; mi < 4; mi++) {
                unsigned sw = SMEM_SWZ((unsigned)((wm0 + mi * 16 + a_row_off) * 128 + ks * 32 + a_k_off));
                ldsm4(ah[mi], sb + GOFF_AH + sw);
                ldsm4(al[mi], sb + GOFF_AL + sw);
            }
            unsigned bh4[2][4], bl4[2][4];
            #pragma unroll
            for (int np = 0; np < 2; np++) {
                unsigned sw = SMEM_SWZ((unsigned)((wn0 + np * 16 + brow_off) * 128 + ks * 32 + bkb));
                ldsm4(bh4[np], sb + GOFF_BH + sw);
                ldsm4(bl4[np], sb + GOFF_BL + sw);
            }
            #pragma unroll
            for (int mi = 0; mi < 4; mi++)
                #pragma unroll
                for (int nj = 0; nj < 4; nj++) {
                    const unsigned* bp_h = bh4[nj >> 1] + (nj & 1) * 2;
                    const unsigned* bp_l = bl4[nj >> 1] + (nj & 1) * 2;
                    mma16816(c[mi][nj], ah[mi], bp_h);
                    mma16816(c[mi][nj], ah[mi], bp_l);
                    mma16816(c[mi][nj], al[mi], bp_h);
                }
        }
        __syncthreads();   // stage (kt&1) free for reuse at kt+2
    }

    // Epilogue: bias + split + scatter
    #pragma unroll
    for (int nj = 0; nj < 4; nj++) {
        int cb = bn + wn0 + nj * 8 + (lane & 3) * 2;
        float b0 = __ldg(bias + cb), b1 = __ldg(bias + cb + 1);
        int h0 = cb >> 6, d0 = cb & 63;
        int h1 = (cb + 1) >> 6, d1 = (cb + 1) & 63;
        #pragma unroll
        for (int mi = 0; mi < 4; mi++) {
            #pragma unroll
            for (int half = 0; half < 2; half++) {
                int m = bm + wm0 + mi * 16 + g + half * 8;
                int bb = m >> 10, ns = m & 1023;
                float v0 = c[mi][nj][half * 2 + 0] + b0;
                float v1 = c[mi][nj][half * 2 + 1] + b1;
                __nv_bfloat16 hi, lo;
                size_t dst0, dst1;
                if (which == 2) {
                    dst0 = ((size_t)(bb * Hh + h0) * DHd + d0) * Nn + ns;
                    dst1 = ((size_t)(bb * Hh + h1) * DHd + d1) * Nn + ns;
                } else {
                    dst0 = ((size_t)(bb * Hh + h0) * Nn + ns) * DHd + d0;
                    dst1 = dst0 + (d1 - d0) + (size_t)(h1 - h0) * Nn * DHd;
                }
                split2(v0, hi, lo); Hi[dst0] = hi; Lo[dst0] = lo;
                split2(v1, hi, lo); Hi[dst1] = hi; Lo[dst1] = lo;
            }
        }
    }
}

// ---------------------------------------------------------------------------
// HMMA flash attention with 2-stage cp.async K/V pipeline.
// grid = (8 q-tiles, 64 bh), 256 threads (8 warps, 16 q-rows per warp).
// smem: QH 0..16K, QL 16K..32K, stages at 32K + s*32K {KH,KL,VH,VL} x 8KB.
// ---------------------------------------------------------------------------
#define FOFF_Q   0
#define FOFF_QL  16384
#define FSTAGE0  32768
#define FKH 0
#define FKL 8192
#define FVH 16384
#define FVL 24576
#define FSTAGE   32768
#define SMEM_FA  98304

__global__ __launch_bounds__(256, 1) void fa_kernel(float* __restrict__ y)
{
    extern __shared__ char s[];
    const unsigned base_u = smem_u32(s);

    const int tid  = threadIdx.x;
    const int w    = tid >> 5;
    const int lane = tid & 31;
    const int g    = lane >> 2;
    const int t2   = (lane & 3) * 2;
    const int bh   = blockIdx.y;
    const int b    = bh >> 3, h = bh & 7;
    const int qt   = blockIdx.x;
    const int q0   = qt * 128;
    const int wq0  = w * 16;

    const int mrow = lane & 7;
    const int sel  = lane >> 3;

    const char* kh_base = (const char*)(g_kh  + (size_t)bh * Nn * DHd);
    const char* kl_base = (const char*)(g_kl  + (size_t)bh * Nn * DHd);
    const char* vh_base = (const char*)(g_vth + (size_t)bh * DHd * Nn);
    const char* vl_base = (const char*)(g_vtl + (size_t)bh * DHd * Nn);

    // per-thread K/V load addressing (2 x 16B rows per buffer)
    unsigned f_sw[2]; int f_row[2], f_c16[2];
    #pragma unroll
    for (int rr = 0; rr < 2; rr++) {
        int idx = tid + rr * 256;
        f_row[rr] = idx >> 3; f_c16[rr] = idx & 7;
        f_sw[rr] = SMEM_SWZ((unsigned)(f_row[rr] * 128 + f_c16[rr] * 16));
    }

    auto issue = [&](int t) {
        unsigned so = base_u + FSTAGE0 + (t & 1) * FSTAGE;
        int t0 = t << 6;
        #pragma unroll
        for (int rr = 0; rr < 2; rr++) {
            unsigned kof = (unsigned)(t0 + f_row[rr]) * 128 + f_c16[rr] * 16;
            unsigned vof = (unsigned)f_row[rr] * 2048 + (unsigned)t0 * 2 + f_c16[rr] * 16;
            CP_ASYNC16(so + FKH + f_sw[rr], kh_base + kof);
            CP_ASYNC16(so + FKL + f_sw[rr], kl_base + kof);
            CP_ASYNC16(so + FVH + f_sw[rr], vh_base + vof);
            CP_ASYNC16(so + FVL + f_sw[rr], vl_base + vof);
        }
        CP_COMMIT();
    };

    issue(0);   // overlap with Q load + fragment hoist below

    // Q tiles (128 x 64 bf16, swizzled 128B rows)
    const char* qh_src = (const char*)(g_qh + ((size_t)bh * Nn + q0) * DHd);
    const char* ql_src = (const char*)(g_ql + ((size_t)bh * Nn + q0) * DHd);
    #pragma unroll
    for (int rr = 0; rr < 4; rr++) {
        int idx = tid + rr * 256;
        int row = idx >> 3, c16 = idx & 7;
        unsigned byte = row * 128 + c16 * 16;
        unsigned sw = SMEM_SWZ(byte);
        *(float4*)(s + FOFF_Q + sw) = *(const float4*)(qh_src + byte);
        *(float4*)(s + FOFF_QL + sw) = *(const float4*)(ql_src + byte);
    }
    __syncthreads();

    unsigned qh[4][4], ql[4][4];
    {
        int arow = wq0 + ((sel & 1) << 3) + mrow;
        #pragma unroll
        for (int ks = 0; ks < 4; ks++) {
            unsigned byte = arow * 128 + ks * 32 + ((sel >> 1) << 4);
            unsigned sw = SMEM_SWZ(byte);
            ldsm4(qh[ks], base_u + FOFF_Q + sw);
            ldsm4(ql[ks], base_u + FOFF_QL + sw);
        }
    }

    float m0 = -1e30f, m1 = -1e30f, l0 = 0.0f, l1 = 0.0f;
    float o[8][4];
    #pragma unroll
    for (int i = 0; i < 8; i++)
        #pragma unroll
        for (int v = 0; v < 4; v++) o[i][v] = 0.0f;

    const int brow_off = ((sel >> 1) << 3) + mrow;
    const int bkb      = (sel & 1) << 4;

    for (int t = 0; t < 16; t++) {
        if (t < 15) { issue(t + 1); CP_WAIT1(); } else { CP_WAIT0(); }
        __syncthreads();

        unsigned sb = base_u + FSTAGE0 + (t & 1) * FSTAGE;

        float c[8][4];
        #pragma unroll
        for (int j = 0; j < 8; j++)
            #pragma unroll
            for (int v = 0; v < 4; v++) c[j][v] = 0.0f;

        #pragma unroll
        for (int ks = 0; ks < 4; ks++) {
            #pragma unroll
            for (int np = 0; np < 4; np++) {
                unsigned sw = SMEM_SWZ((unsigned)((np * 16 + brow_off) * 128 + ks * 32 + bkb));
                unsigned kh4[4], kl4[4];
                ldsm4(kh4, sb + FKH + sw);
                ldsm4(kl4, sb + FKL + sw);
                mma16816(c[2*np],   qh[ks], kh4);
                mma16816(c[2*np],   qh[ks], kl4);
                mma16816(c[2*np],   ql[ks], kh4);
                mma16816(c[2*np+1], qh[ks], kh4 + 2);
                mma16816(c[2*np+1], qh[ks], kl4 + 2);
                mma16816(c[2*np+1], ql[ks], kh4 + 2);
            }
        }

        float rm0 = -1e30f, rm1 = -1e30f;
        #pragma unroll
        for (int j = 0; j < 8; j++) {
            rm0 = fmaxf(rm0, fmaxf(c[j][0], c[j][1]));
            rm1 = fmaxf(rm1, fmaxf(c[j][2], c[j][3]));
        }
        rm0 = fmaxf(rm0, __shfl_xor_sync(0xFFFFFFFFu, rm0, 1));
        rm0 = fmaxf(rm0, __shfl_xor_sync(0xFFFFFFFFu, rm0, 2));
        rm1 = fmaxf(rm1, __shfl_xor_sync(0xFFFFFFFFu, rm1, 1));
        rm1 = fmaxf(rm1, __shfl_xor_sync(0xFFFFFFFFu, rm1, 2));

        float mn0 = fmaxf(m0, rm0), mn1 = fmaxf(m1, rm1);
        float cr0 = __expf(m0 - mn0), cr1 = __expf(m1 - mn1);
        m0 = mn0; m1 = mn1;

        float rs0 = 0.0f, rs1 = 0.0f;
        #pragma unroll
        for (int j = 0; j < 8; j++) {
            c[j][0] = __expf(c[j][0] - m0);
            c[j][1] = __expf(c[j][1] - m0);
            c[j][2] = __expf(c[j][2] - m1);
            c[j][3] = __expf(c[j][3] - m1);
            rs0 += c[j][0] + c[j][1];
            rs1 += c[j][2] + c[j][3];
        }
        rs0 += __shfl_xor_sync(0xFFFFFFFFu, rs0, 1);
        rs0 += __shfl_xor_sync(0xFFFFFFFFu, rs0, 2);
        rs1 += __shfl_xor_sync(0xFFFFFFFFu, rs1, 1);
        rs1 += __shfl_xor_sync(0xFFFFFFFFu, rs1, 2);
        l0 = l0 * cr0 + rs0;
        l1 = l1 * cr1 + rs1;

        #pragma unroll
        for (int jd = 0; jd < 8; jd++) {
            o[jd][0] *= cr0; o[jd][1] *= cr0;
            o[jd][2] *= cr1; o[jd][3] *= cr1;
        }

        unsigned ph[4][4], pl[4][4];
        #pragma unroll
        for (int ks = 0; ks < 4; ks++) {
            #pragma unroll
            for (int u = 0; u < 4; u++) {
                int j = 2 * ks + (u >> 1);
                int v = (u & 1) * 2;
                float e0 = c[j][v], e1 = c[j][v + 1];
                __nv_bfloat162 hv = __float22bfloat162_rn(make_float2(e0, e1));
                float r0f = e0 - __bfloat162float(hv.x);
                float r1f = e1 - __bfloat162float(hv.y);
                __nv_bfloat162 lv = __float22bfloat162_rn(make_float2(r0f, r1f));
                ph[ks][u] = *(unsigned*)&hv;
                pl[ks][u] = *(unsigned*)&lv;
            }
        }

        #pragma unroll
        for (int ks = 0; ks < 4; ks++) {
            #pragma unroll
            for (int dp = 0; dp < 4; dp++) {
                unsigned sw = SMEM_SWZ((unsigned)((dp * 16 + brow_off) * 128 + ks * 32 + bkb));
                unsigned vh4[4], vl4[4];
                ldsm4(vh4, sb + FVH + sw);
                ldsm4(vl4, sb + FVL + sw);
                mma16816(o[2*dp],   ph[ks], vh4);
                mma16816(o[2*dp],   ph[ks], vl4);
                mma16816(o[2*dp],   pl[ks], vh4);
                mma16816(o[2*dp+1], ph[ks], vh4 + 2);
                mma16816(o[2*dp+1], ph[ks], vl4 + 2);
                mma16816(o[2*dp+1], pl[ks], vh4 + 2);
            }
        }
        __syncthreads();   // stage (t&1) reusable at t+2
    }

    float inv0 = 1.0f / l0, inv1 = 1.0f / l1;
    int row0 = q0 + wq0 + g;
    int row1 = row0 + 8;
    float* y0 = y + ((size_t)(b * Nn + row0)) * Dd + h * DHd;
    float* y1 = y + ((size_t)(b * Nn + row1)) * Dd + h * DHd;
    #pragma unroll
    for (int jd = 0; jd < 8; jd++) {
        float2 p0 = make_float2(o[jd][0] * inv0, o[jd][1] * inv0);
        float2 p1 = make_float2(o[jd][2] * inv1, o[jd][3] * inv1);
        *(float2*)(y0 + jd * 8 + t2) = p0;
        *(float2*)(y1 + jd * 8 + t2) = p1;
    }
}

// ---------------------------------------------------------------------------
// Inputs (metadata order): x, Wq, bq, Wk, bk, Wv, bv. Output: float32 [B,N,D].
// ---------------------------------------------------------------------------
extern "C" void kernel_launch(void* const* d_in, const int* in_sizes, int n_in,
                              void* d_out, int out_size)
{
    const float* x  = (const float*)d_in[0];
    const float* Wq = (const float*)d_in[1];
    const float* bq = (const float*)d_in[2];
    const float* Wk = (const float*)d_in[3];
    const float* bk = (const float*)d_in[4];
    const float* Wv = (const float*)d_in[5];
    const float* bv = (const float*)d_in[6];
    float* y = (float*)d_out;

    cudaFuncSetAttribute(gemm_hmma_kernel, cudaFuncAttributeMaxDynamicSharedMemorySize, SMEM_GEMM);
    cudaFuncSetAttribute(fa_kernel, cudaFuncAttributeMaxDynamicSharedMemorySize, SMEM_FA);

    split_x_kernel<<<4096, 256>>>(x);
    split_wt_kernel<<<dim3(8, 8, 3), 256>>>(Wq, Wk, Wv);

    dim3 ggrid(MTOT / 128, Dd / 128, 3);   // (64, 4, 3) fused
    gemm_hmma_kernel<<<ggrid, 256, SMEM_GEMM>>>(bq, bk, bv);

    dim3 agrid(Nn / 128, BH);              // (8, 64)
    fa_kernel<<<agrid, 256, SMEM_FA>>>(y);
}

// round 9
// speedup vs baseline: 4.2892x; 1.1623x over previous
#include <cuda_runtime.h>
#include <cuda_bf16.h>

// Problem constants
#define Bb   8
#define Nn   1024
#define Dd   512
#define Hh   8
#define DHd  64
#define MTOT (Bb*Nn)   // 8192
#define BH   (Bb*Hh)   // 64

// Split-bf16 operands for the projection GEMMs
__device__ __nv_bfloat16 g_xh[MTOT*Dd];
__device__ __nv_bfloat16 g_xl[MTOT*Dd];
__device__ __nv_bfloat16 g_wth[3*Dd*Dd];   // W^T per proj: [n][k]
__device__ __nv_bfloat16 g_wtl[3*Dd*Dd];

// bf16 split-precision Q/K (head-major [BH, N, 64]) and transposed V ([BH, 64, N])
__device__ __nv_bfloat16 g_qh[BH*Nn*DHd];
__device__ __nv_bfloat16 g_ql[BH*Nn*DHd];
__device__ __nv_bfloat16 g_kh[BH*Nn*DHd];
__device__ __nv_bfloat16 g_kl[BH*Nn*DHd];
__device__ __nv_bfloat16 g_vth[BH*DHd*Nn];
__device__ __nv_bfloat16 g_vtl[BH*DHd*Nn];

#define SMEM_SWZ(b) ((b) ^ (((b) >> 3) & 0x70))

static __device__ __forceinline__ unsigned smem_u32(const void* p) {
    unsigned a;
    asm("{ .reg .u64 t; cvta.to.shared.u64 t, %1; cvt.u32.u64 %0, t; }" : "=r"(a) : "l"(p));
    return a;
}

// cp.async helpers (sm_80+)
#define CP_ASYNC16(dst_u32, src_ptr) \
    asm volatile("cp.async.cg.shared.global [%0], [%1], 16;" :: "r"(dst_u32), "l"(src_ptr))
#define CP_COMMIT() asm volatile("cp.async.commit_group;")
#define CP_WAIT1()  asm volatile("cp.async.wait_group 1;")
#define CP_WAIT0()  asm volatile("cp.async.wait_group 0;")

// mma.sync m16n8k16 bf16 -> fp32 (sm_80+, no arch-feature gating)
static __device__ __forceinline__ void mma16816(float* c, const unsigned* a, const unsigned* b) {
    asm volatile(
        "mma.sync.aligned.m16n8k16.row.col.f32.bf16.bf16.f32 "
        "{%0,%1,%2,%3}, {%4,%5,%6,%7}, {%8,%9}, {%0,%1,%2,%3};"
        : "+f"(c[0]), "+f"(c[1]), "+f"(c[2]), "+f"(c[3])
        : "r"(a[0]), "r"(a[1]), "r"(a[2]), "r"(a[3]), "r"(b[0]), "r"(b[1]));
}

static __device__ __forceinline__ void ldsm4(unsigned* r, unsigned addr) {
    asm volatile("ldmatrix.sync.aligned.m8n8.x4.shared.b16 {%0,%1,%2,%3}, [%4];"
                 : "=r"(r[0]), "=r"(r[1]), "=r"(r[2]), "=r"(r[3]) : "r"(addr));
}

static __device__ __forceinline__ void split2(float v, __nv_bfloat16& hi, __nv_bfloat16& lo) {
    hi = __float2bfloat16(v);
    lo = __float2bfloat16(v - __bfloat162float(hi));
}

// ---------------------------------------------------------------------------
// split_x: x fp32 [8192,512] -> g_xh/g_xl bf16. One float4 per thread.
// ---------------------------------------------------------------------------
__global__ __launch_bounds__(256) void split_x_kernel(const float* __restrict__ x)
{
    int i = blockIdx.x * 256 + threadIdx.x;          // float4 index, < 1048576
    float4 v = ((const float4*)x)[i];
    __nv_bfloat16 h[4], l[4];
    split2(v.x, h[0], l[0]); split2(v.y, h[1], l[1]);
    split2(v.z, h[2], l[2]); split2(v.w, h[3], l[3]);
    ((uint2*)g_xh)[i] = *(uint2*)h;
    ((uint2*)g_xl)[i] = *(uint2*)l;
}

// ---------------------------------------------------------------------------
// split_wt: W [512,512] ([k][n]) -> W^T hi/lo [n][k]. 64x64 tiles.
// grid (8, 8, 3), 256 threads.
// ---------------------------------------------------------------------------
__global__ __launch_bounds__(256) void split_wt_kernel(
    const float* __restrict__ W0, const float* __restrict__ W1,
    const float* __restrict__ W2)
{
    const float* W = (blockIdx.z == 0) ? W0 : (blockIdx.z == 1) ? W1 : W2;
    __nv_bfloat16* Oh = g_wth + (size_t)blockIdx.z * Dd * Dd;
    __nv_bfloat16* Ol = g_wtl + (size_t)blockIdx.z * Dd * Dd;

    __shared__ __nv_bfloat16 sh[64][68];
    __shared__ __nv_bfloat16 sl[64][68];

    const int k0 = blockIdx.y * 64;
    const int n0 = blockIdx.x * 64;
    const int tid = threadIdx.x;

    int r = tid >> 2;
    int cs = (tid & 3) * 16;
    #pragma unroll
    for (int j = 0; j < 4; j++) {
        float4 v = *(const float4*)(W + (size_t)(k0 + r) * Dd + n0 + cs + j * 4);
        __nv_bfloat16 h, l;
        split2(v.x, h, l); sh[cs + j*4 + 0][r] = h; sl[cs + j*4 + 0][r] = l;
        split2(v.y, h, l); sh[cs + j*4 + 1][r] = h; sl[cs + j*4 + 1][r] = l;
        split2(v.z, h, l); sh[cs + j*4 + 2][r] = h; sl[cs + j*4 + 2][r] = l;
        split2(v.w, h, l); sh[cs + j*4 + 3][r] = h; sl[cs + j*4 + 3][r] = l;
    }
    __syncthreads();

    int n = tid >> 2;
    int ks = (tid & 3) * 16;
    #pragma unroll
    for (int j = 0; j < 8; j++) {
        __nv_bfloat16 p0 = sh[n][ks + j*2], p1 = sh[n][ks + j*2 + 1];
        unsigned uh = (unsigned)__bfloat16_as_ushort(p0) | ((unsigned)__bfloat16_as_ushort(p1) << 16);
        p0 = sl[n][ks + j*2]; p1 = sl[n][ks + j*2 + 1];
        unsigned ul = (unsigned)__bfloat16_as_ushort(p0) | ((unsigned)__bfloat16_as_ushort(p1) << 16);
        *(unsigned*)(Oh + (size_t)(n0 + n) * Dd + k0 + ks + j*2) = uh;
        *(unsigned*)(Ol + (size_t)(n0 + n) * Dd + k0 + ks + j*2) = ul;
    }
}

// ---------------------------------------------------------------------------
// HMMA projection GEMM, fused (gridDim.z picks proj), 2-stage cp.async pipe.
// 64x128 tile, 128 threads (4 warps, each 64x32), KT=64 per stage.
// 48KB/stage x2 = 96KB smem -> 2 CTAs/SM for cross-CTA phase overlap.
// ---------------------------------------------------------------------------
#define GOFF_AH 0
#define GOFF_AL 8192
#define GOFF_BH 16384
#define GOFF_BL 32768
#define GSTAGE  49152
#define SMEM_GEMM (2*GSTAGE)

__global__ __launch_bounds__(128, 2) void gemm_hmma_kernel(
    const float* __restrict__ bq, const float* __restrict__ bk,
    const float* __restrict__ bv)
{
    extern __shared__ char s[];
    const unsigned base_u = smem_u32(s);

    const int which = blockIdx.z;
    const float* bias = (which == 0) ? bq : (which == 1) ? bk : bv;
    __nv_bfloat16* Hi = (which == 0) ? g_qh : (which == 1) ? g_kh : g_vth;
    __nv_bfloat16* Lo = (which == 0) ? g_ql : (which == 1) ? g_kl : g_vtl;
    const char* wh_base = (const char*)(g_wth + (size_t)which * Dd * Dd);
    const char* wl_base = (const char*)(g_wtl + (size_t)which * Dd * Dd);
    const char* xh_base = (const char*)g_xh;
    const char* xl_base = (const char*)g_xl;

    const int tid  = threadIdx.x;
    const int w    = tid >> 5;        // 0..3
    const int lane = tid & 31;
    const int g    = lane >> 2;
    const int mrow = lane & 7;
    const int sel  = lane >> 3;
    const int wn0  = w * 32;          // warp n offset in tile (m offset = 0)
    const int bm   = blockIdx.x * 64;
    const int bn   = blockIdx.y * 128;

    const int a_row_off = ((sel & 1) << 3) + mrow;
    const int a_k_off   = (sel >> 1) << 4;
    const int brow_off  = ((sel >> 1) << 3) + mrow;
    const int bkb       = (sel & 1) << 4;

    float c[4][4][4];
    #pragma unroll
    for (int mi = 0; mi < 4; mi++)
        #pragma unroll
        for (int nj = 0; nj < 4; nj++)
            #pragma unroll
            for (int v = 0; v < 4; v++) c[mi][nj][v] = 0.0f;

    // issue stage for k-tile kt: A 64 rows (hi+lo), B 128 rows (hi+lo)
    auto issue = [&](int kt) {
        unsigned so = base_u + (kt & 1) * GSTAGE;
        unsigned ko = (unsigned)kt * 128;
        #pragma unroll
        for (int rr = 0; rr < 4; rr++) {          // A: 512 chunks / 128 thr
            int idx = tid + rr * 128;
            int row = idx >> 3, c16 = idx & 7;
            unsigned sw = SMEM_SWZ((unsigned)(row * 128 + c16 * 16));
            unsigned gA = (unsigned)(bm + row) * 1024 + c16 * 16 + ko;
            CP_ASYNC16(so + GOFF_AH + sw, xh_base + gA);
            CP_ASYNC16(so + GOFF_AL + sw, xl_base + gA);
        }
        #pragma unroll
        for (int rr = 0; rr < 8; rr++) {          // B: 1024 chunks / 128 thr
            int idx = tid + rr * 128;
            int row = idx >> 3, c16 = idx & 7;
            unsigned sw = SMEM_SWZ((unsigned)(row * 128 + c16 * 16));
            unsigned gB = (unsigned)(bn + row) * 1024 + c16 * 16 + ko;
            CP_ASYNC16(so + GOFF_BH + sw, wh_base + gB);
            CP_ASYNC16(so + GOFF_BL + sw, wl_base + gB);
        }
        CP_COMMIT();
    };

    issue(0);
    for (int kt = 0; kt < 8; kt++) {
        if (kt < 7) { issue(kt + 1); CP_WAIT1(); } else { CP_WAIT0(); }
        __syncthreads();

        unsigned sb = base_u + (kt & 1) * GSTAGE;
        #pragma unroll
        for (int ks = 0; ks < 4; ks++) {
            unsigned ah[4][4], al[4][4];
            #pragma unroll
            for (int mi = 0; mi < 4; mi++) {
                unsigned sw = SMEM_SWZ((unsigned)((mi * 16 + a_row_off) * 128 + ks * 32 + a_k_off));
                ldsm4(ah[mi], sb + GOFF_AH + sw);
                ldsm4(al[mi], sb + GOFF_AL + sw);
            }
            unsigned bh4[2][4], bl4[2][4];
            #pragma unroll
            for (int np = 0; np < 2; np++) {
                unsigned sw = SMEM_SWZ((unsigned)((wn0 + np * 16 + brow_off) * 128 + ks * 32 + bkb));
                ldsm4(bh4[np], sb + GOFF_BH + sw);
                ldsm4(bl4[np], sb + GOFF_BL + sw);
            }
            #pragma unroll
            for (int mi = 0; mi < 4; mi++)
                #pragma unroll
                for (int nj = 0; nj < 4; nj++) {
                    const unsigned* bp_h = bh4[nj >> 1] + (nj & 1) * 2;
                    const unsigned* bp_l = bl4[nj >> 1] + (nj & 1) * 2;
                    mma16816(c[mi][nj], ah[mi], bp_h);
                    mma16816(c[mi][nj], ah[mi], bp_l);
                    mma16816(c[mi][nj], al[mi], bp_h);
                }
        }
        __syncthreads();   // stage (kt&1) free for reuse at kt+2
    }

    // Epilogue: bias + split + scatter
    #pragma unroll
    for (int nj = 0; nj < 4; nj++) {
        int cb = bn + wn0 + nj * 8 + (lane & 3) * 2;
        float b0 = __ldg(bias + cb), b1 = __ldg(bias + cb + 1);
        int h0 = cb >> 6, d0 = cb & 63;
        int h1 = (cb + 1) >> 6, d1 = (cb + 1) & 63;
        #pragma unroll
        for (int mi = 0; mi < 4; mi++) {
            #pragma unroll
            for (int half = 0; half < 2; half++) {
                int m = bm + mi * 16 + g + half * 8;
                int bb = m >> 10, ns = m & 1023;
                float v0 = c[mi][nj][half * 2 + 0] + b0;
                float v1 = c[mi][nj][half * 2 + 1] + b1;
                __nv_bfloat16 hi, lo;
                size_t dst0, dst1;
                if (which == 2) {
                    dst0 = ((size_t)(bb * Hh + h0) * DHd + d0) * Nn + ns;
                    dst1 = ((size_t)(bb * Hh + h1) * DHd + d1) * Nn + ns;
                } else {
                    dst0 = ((size_t)(bb * Hh + h0) * Nn + ns) * DHd + d0;
                    dst1 = dst0 + (d1 - d0) + (size_t)(h1 - h0) * Nn * DHd;
                }
                split2(v0, hi, lo); Hi[dst0] = hi; Lo[dst0] = lo;
                split2(v1, hi, lo); Hi[dst1] = hi; Lo[dst1] = lo;
            }
        }
    }
}

// ---------------------------------------------------------------------------
// HMMA flash attention, 128 threads (4 warps) per CTA over a 64-row q tile,
// 2-stage cp.async K/V pipeline. smem 80KB -> 2 CTAs/SM (cross-CTA overlap).
// grid = (16 q-tiles, 64 bh). Each warp owns 16 q rows.
// ---------------------------------------------------------------------------
#define FOFF_Q   0
#define FOFF_QL  8192
#define FSTAGE0  16384
#define FKH 0
#define FKL 8192
#define FVH 16384
#define FVL 24576
#define FSTAGE   32768
#define SMEM_FA  81920

__global__ __launch_bounds__(128, 2) void fa_kernel(float* __restrict__ y)
{
    extern __shared__ char s[];
    const unsigned base_u = smem_u32(s);

    const int tid  = threadIdx.x;
    const int w    = tid >> 5;        // 0..3
    const int lane = tid & 31;
    const int g    = lane >> 2;
    const int t2   = (lane & 3) * 2;
    const int bh   = blockIdx.y;
    const int b    = bh >> 3, h = bh & 7;
    const int qt   = blockIdx.x;
    const int q0   = qt * 64;
    const int wq0  = w * 16;

    const int mrow = lane & 7;
    const int sel  = lane >> 3;

    const char* kh_base = (const char*)(g_kh  + (size_t)bh * Nn * DHd);
    const char* kl_base = (const char*)(g_kl  + (size_t)bh * Nn * DHd);
    const char* vh_base = (const char*)(g_vth + (size_t)bh * DHd * Nn);
    const char* vl_base = (const char*)(g_vtl + (size_t)bh * DHd * Nn);

    // per-thread K/V load addressing (4 x 16B chunks per 8KB buffer)
    unsigned f_sw[4]; int f_row[4], f_c16[4];
    #pragma unroll
    for (int rr = 0; rr < 4; rr++) {
        int idx = tid + rr * 128;
        f_row[rr] = idx >> 3; f_c16[rr] = idx & 7;
        f_sw[rr] = SMEM_SWZ((unsigned)(f_row[rr] * 128 + f_c16[rr] * 16));
    }

    auto issue = [&](int t) {
        unsigned so = base_u + FSTAGE0 + (t & 1) * FSTAGE;
        int t0 = t << 6;
        #pragma unroll
        for (int rr = 0; rr < 4; rr++) {
            unsigned kof = (unsigned)(t0 + f_row[rr]) * 128 + f_c16[rr] * 16;
            unsigned vof = (unsigned)f_row[rr] * 2048 + (unsigned)t0 * 2 + f_c16[rr] * 16;
            CP_ASYNC16(so + FKH + f_sw[rr], kh_base + kof);
            CP_ASYNC16(so + FKL + f_sw[rr], kl_base + kof);
            CP_ASYNC16(so + FVH + f_sw[rr], vh_base + vof);
            CP_ASYNC16(so + FVL + f_sw[rr], vl_base + vof);
        }
        CP_COMMIT();
    };

    issue(0);   // overlap with Q load + fragment hoist below

    // Q tiles (64 q-rows x 64 d bf16, swizzled 128B rows)
    const char* qh_src = (const char*)(g_qh + ((size_t)bh * Nn + q0) * DHd);
    const char* ql_src = (const char*)(g_ql + ((size_t)bh * Nn + q0) * DHd);
    #pragma unroll
    for (int rr = 0; rr < 4; rr++) {
        int idx = tid + rr * 128;
        int row = idx >> 3, c16 = idx & 7;
        unsigned byte = row * 128 + c16 * 16;
        unsigned sw = SMEM_SWZ(byte);
        *(float4*)(s + FOFF_Q + sw) = *(const float4*)(qh_src + byte);
        *(float4*)(s + FOFF_QL + sw) = *(const float4*)(ql_src + byte);
    }
    __syncthreads();

    unsigned qh[4][4], ql[4][4];
    {
        int arow = wq0 + ((sel & 1) << 3) + mrow;
        #pragma unroll
        for (int ks = 0; ks < 4; ks++) {
            unsigned byte = arow * 128 + ks * 32 + ((sel >> 1) << 4);
            unsigned sw = SMEM_SWZ(byte);
            ldsm4(qh[ks], base_u + FOFF_Q + sw);
            ldsm4(ql[ks], base_u + FOFF_QL + sw);
        }
    }

    float m0 = -1e30f, m1 = -1e30f, l0 = 0.0f, l1 = 0.0f;
    float o[8][4];
    #pragma unroll
    for (int i = 0; i < 8; i++)
        #pragma unroll
        for (int v = 0; v < 4; v++) o[i][v] = 0.0f;

    const int brow_off = ((sel >> 1) << 3) + mrow;
    const int bkb      = (sel & 1) << 4;

    for (int t = 0; t < 16; t++) {
        if (t < 15) { issue(t + 1); CP_WAIT1(); } else { CP_WAIT0(); }
        __syncthreads();

        unsigned sb = base_u + FSTAGE0 + (t & 1) * FSTAGE;

        float c[8][4];
        #pragma unroll
        for (int j = 0; j < 8; j++)
            #pragma unroll
            for (int v = 0; v < 4; v++) c[j][v] = 0.0f;

        #pragma unroll
        for (int ks = 0; ks < 4; ks++) {
            #pragma unroll
            for (int np = 0; np < 4; np++) {
                unsigned sw = SMEM_SWZ((unsigned)((np * 16 + brow_off) * 128 + ks * 32 + bkb));
                unsigned kh4[4], kl4[4];
                ldsm4(kh4, sb + FKH + sw);
                ldsm4(kl4, sb + FKL + sw);
                mma16816(c[2*np],   qh[ks], kh4);
                mma16816(c[2*np],   qh[ks], kl4);
                mma16816(c[2*np],   ql[ks], kh4);
                mma16816(c[2*np+1], qh[ks], kh4 + 2);
                mma16816(c[2*np+1], qh[ks], kl4 + 2);
                mma16816(c[2*np+1], ql[ks], kh4 + 2);
            }
        }

        float rm0 = -1e30f, rm1 = -1e30f;
        #pragma unroll
        for (int j = 0; j < 8; j++) {
            rm0 = fmaxf(rm0, fmaxf(c[j][0], c[j][1]));
            rm1 = fmaxf(rm1, fmaxf(c[j][2], c[j][3]));
        }
        rm0 = fmaxf(rm0, __shfl_xor_sync(0xFFFFFFFFu, rm0, 1));
        rm0 = fmaxf(rm0, __shfl_xor_sync(0xFFFFFFFFu, rm0, 2));
        rm1 = fmaxf(rm1, __shfl_xor_sync(0xFFFFFFFFu, rm1, 1));
        rm1 = fmaxf(rm1, __shfl_xor_sync(0xFFFFFFFFu, rm1, 2));

        float mn0 = fmaxf(m0, rm0), mn1 = fmaxf(m1, rm1);
        float cr0 = __expf(m0 - mn0), cr1 = __expf(m1 - mn1);
        m0 = mn0; m1 = mn1;

        float rs0 = 0.0f, rs1 = 0.0f;
        #pragma unroll
        for (int j = 0; j < 8; j++) {
            c[j][0] = __expf(c[j][0] - m0);
            c[j][1] = __expf(c[j][1] - m0);
            c[j][2] = __expf(c[j][2] - m1);
            c[j][3] = __expf(c[j][3] - m1);
            rs0 += c[j][0] + c[j][1];
            rs1 += c[j][2] + c[j][3];
        }
        rs0 += __shfl_xor_sync(0xFFFFFFFFu, rs0, 1);
        rs0 += __shfl_xor_sync(0xFFFFFFFFu, rs0, 2);
        rs1 += __shfl_xor_sync(0xFFFFFFFFu, rs1, 1);
        rs1 += __shfl_xor_sync(0xFFFFFFFFu, rs1, 2);
        l0 = l0 * cr0 + rs0;
        l1 = l1 * cr1 + rs1;

        #pragma unroll
        for (int jd = 0; jd < 8; jd++) {
            o[jd][0] *= cr0; o[jd][1] *= cr0;
            o[jd][2] *= cr1; o[jd][3] *= cr1;
        }

        unsigned ph[4][4], pl[4][4];
        #pragma unroll
        for (int ks = 0; ks < 4; ks++) {
            #pragma unroll
            for (int u = 0; u < 4; u++) {
                int j = 2 * ks + (u >> 1);
                int v = (u & 1) * 2;
                float e0 = c[j][v], e1 = c[j][v + 1];
                __nv_bfloat162 hv = __float22bfloat162_rn(make_float2(e0, e1));
                float r0f = e0 - __bfloat162float(hv.x);
                float r1f = e1 - __bfloat162float(hv.y);
                __nv_bfloat162 lv = __float22bfloat162_rn(make_float2(r0f, r1f));
                ph[ks][u] = *(unsigned*)&hv;
                pl[ks][u] = *(unsigned*)&lv;
            }
        }

        #pragma unroll
        for (int ks = 0; ks < 4; ks++) {
            #pragma unroll
            for (int dp = 0; dp < 4; dp++) {
                unsigned sw = SMEM_SWZ((unsigned)((dp * 16 + brow_off) * 128 + ks * 32 + bkb));
                unsigned vh4[4], vl4[4];
                ldsm4(vh4, sb + FVH + sw);
                ldsm4(vl4, sb + FVL + sw);
                mma16816(o[2*dp],   ph[ks], vh4);
                mma16816(o[2*dp],   ph[ks], vl4);
                mma16816(o[2*dp],   pl[ks], vh4);
                mma16816(o[2*dp+1], ph[ks], vh4 + 2);
                mma16816(o[2*dp+1], ph[ks], vl4 + 2);
                mma16816(o[2*dp+1], pl[ks], vh4 + 2);
            }
        }
        __syncthreads();   // stage (t&1) reusable at t+2
    }

    float inv0 = 1.0f / l0, inv1 = 1.0f / l1;
    int row0 = q0 + wq0 + g;
    int row1 = row0 + 8;
    float* y0 = y + ((size_t)(b * Nn + row0)) * Dd + h * DHd;
    float* y1 = y + ((size_t)(b * Nn + row1)) * Dd + h * DHd;
    #pragma unroll
    for (int jd = 0; jd < 8; jd++) {
        float2 p0 = make_float2(o[jd][0] * inv0, o[jd][1] * inv0);
        float2 p1 = make_float2(o[jd][2] * inv1, o[jd][3] * inv1);
        *(float2*)(y0 + jd * 8 + t2) = p0;
        *(float2*)(y1 + jd * 8 + t2) = p1;
    }
}

// ---------------------------------------------------------------------------
// Inputs (metadata order): x, Wq, bq, Wk, bk, Wv, bv. Output: float32 [B,N,D].
// ---------------------------------------------------------------------------
extern "C" void kernel_launch(void* const* d_in, const int* in_sizes, int n_in,
                              void* d_out, int out_size)
{
    const float* x  = (const float*)d_in[0];
    const float* Wq = (const float*)d_in[1];
    const float* bq = (const float*)d_in[2];
    const float* Wk = (const float*)d_in[3];
    const float* bk = (const float*)d_in[4];
    const float* Wv = (const float*)d_in[5];
    const float* bv = (const float*)d_in[6];
    float* y = (float*)d_out;

    cudaFuncSetAttribute(gemm_hmma_kernel, cudaFuncAttributeMaxDynamicSharedMemorySize, SMEM_GEMM);
    cudaFuncSetAttribute(fa_kernel, cudaFuncAttributeMaxDynamicSharedMemorySize, SMEM_FA);

    split_x_kernel<<<4096, 256>>>(x);
    split_wt_kernel<<<dim3(8, 8, 3), 256>>>(Wq, Wk, Wv);

    dim3 ggrid(MTOT / 64, Dd / 128, 3);    // (128, 4, 3) fused
    gemm_hmma_kernel<<<ggrid, 128, SMEM_GEMM>>>(bq, bk, bv);

    dim3 agrid(Nn / 64, BH);               // (16, 64)
    fa_kernel<<<agrid, 128, SMEM_FA>>>(y);
}

// round 10
// speedup vs baseline: 4.9217x; 1.1475x over previous
#include <cuda_runtime.h>
#include <cuda_bf16.h>
#include <cuda_fp16.h>

// Problem constants
#define Bb   8
#define Nn   1024
#define Dd   512
#define Hh   8
#define DHd  64
#define MTOT (Bb*Nn)   // 8192
#define BH   (Bb*Hh)   // 64
#define LOG2E 1.4426950408889634f

// Split-bf16 operands for the projection GEMMs
__device__ __nv_bfloat16 g_xh[MTOT*Dd];
__device__ __nv_bfloat16 g_xl[MTOT*Dd];
__device__ __nv_bfloat16 g_wth[3*Dd*Dd];   // W^T per proj: [n][k]
__device__ __nv_bfloat16 g_wtl[3*Dd*Dd];

// Q/K split-bf16 head-major [BH, N, 64] (Q pre-scaled by log2e); V^T fp16 [BH, 64, N]
__device__ __nv_bfloat16 g_qh[BH*Nn*DHd];
__device__ __nv_bfloat16 g_ql[BH*Nn*DHd];
__device__ __nv_bfloat16 g_kh[BH*Nn*DHd];
__device__ __nv_bfloat16 g_kl[BH*Nn*DHd];
__device__ __half        g_vh[BH*DHd*Nn];

#define SMEM_SWZ(b) ((b) ^ (((b) >> 3) & 0x70))

static __device__ __forceinline__ unsigned smem_u32(const void* p) {
    unsigned a;
    asm("{ .reg .u64 t; cvta.to.shared.u64 t, %1; cvt.u32.u64 %0, t; }" : "=r"(a) : "l"(p));
    return a;
}

static __device__ __forceinline__ float ex2f(float x) {
    float r;
    asm("ex2.approx.f32 %0, %1;" : "=f"(r) : "f"(x));
    return r;
}

// cp.async helpers (sm_80+)
#define CP_ASYNC16(dst_u32, src_ptr) \
    asm volatile("cp.async.cg.shared.global [%0], [%1], 16;" :: "r"(dst_u32), "l"(src_ptr))
#define CP_COMMIT() asm volatile("cp.async.commit_group;")
#define CP_WAIT1()  asm volatile("cp.async.wait_group 1;")
#define CP_WAIT0()  asm volatile("cp.async.wait_group 0;")

// mma.sync m16n8k16 bf16 -> fp32
static __device__ __forceinline__ void mma16816(float* c, const unsigned* a, const unsigned* b) {
    asm volatile(
        "mma.sync.aligned.m16n8k16.row.col.f32.bf16.bf16.f32 "
        "{%0,%1,%2,%3}, {%4,%5,%6,%7}, {%8,%9}, {%0,%1,%2,%3};"
        : "+f"(c[0]), "+f"(c[1]), "+f"(c[2]), "+f"(c[3])
        : "r"(a[0]), "r"(a[1]), "r"(a[2]), "r"(a[3]), "r"(b[0]), "r"(b[1]));
}

// mma.sync m16n8k16 fp16 -> fp32
static __device__ __forceinline__ void mma16816h(float* c, const unsigned* a, const unsigned* b) {
    asm volatile(
        "mma.sync.aligned.m16n8k16.row.col.f32.f16.f16.f32 "
        "{%0,%1,%2,%3}, {%4,%5,%6,%7}, {%8,%9}, {%0,%1,%2,%3};"
        : "+f"(c[0]), "+f"(c[1]), "+f"(c[2]), "+f"(c[3])
        : "r"(a[0]), "r"(a[1]), "r"(a[2]), "r"(a[3]), "r"(b[0]), "r"(b[1]));
}

static __device__ __forceinline__ void ldsm4(unsigned* r, unsigned addr) {
    asm volatile("ldmatrix.sync.aligned.m8n8.x4.shared.b16 {%0,%1,%2,%3}, [%4];"
                 : "=r"(r[0]), "=r"(r[1]), "=r"(r[2]), "=r"(r[3]) : "r"(addr));
}

static __device__ __forceinline__ void split2(float v, __nv_bfloat16& hi, __nv_bfloat16& lo) {
    hi = __float2bfloat16(v);
    lo = __float2bfloat16(v - __bfloat162float(hi));
}

// ---------------------------------------------------------------------------
// split_x: x fp32 [8192,512] -> g_xh/g_xl bf16. One float4 per thread.
// ---------------------------------------------------------------------------
__global__ __launch_bounds__(256) void split_x_kernel(const float* __restrict__ x)
{
    int i = blockIdx.x * 256 + threadIdx.x;          // float4 index, < 1048576
    float4 v = ((const float4*)x)[i];
    __nv_bfloat16 h[4], l[4];
    split2(v.x, h[0], l[0]); split2(v.y, h[1], l[1]);
    split2(v.z, h[2], l[2]); split2(v.w, h[3], l[3]);
    ((uint2*)g_xh)[i] = *(uint2*)h;
    ((uint2*)g_xl)[i] = *(uint2*)l;
}

// ---------------------------------------------------------------------------
// split_wt: W [512,512] ([k][n]) -> W^T hi/lo [n][k]. 64x64 tiles.
// ---------------------------------------------------------------------------
__global__ __launch_bounds__(256) void split_wt_kernel(
    const float* __restrict__ W0, const float* __restrict__ W1,
    const float* __restrict__ W2)
{
    const float* W = (blockIdx.z == 0) ? W0 : (blockIdx.z == 1) ? W1 : W2;
    __nv_bfloat16* Oh = g_wth + (size_t)blockIdx.z * Dd * Dd;
    __nv_bfloat16* Ol = g_wtl + (size_t)blockIdx.z * Dd * Dd;

    __shared__ __nv_bfloat16 sh[64][68];
    __shared__ __nv_bfloat16 sl[64][68];

    const int k0 = blockIdx.y * 64;
    const int n0 = blockIdx.x * 64;
    const int tid = threadIdx.x;

    int r = tid >> 2;
    int cs = (tid & 3) * 16;
    #pragma unroll
    for (int j = 0; j < 4; j++) {
        float4 v = *(const float4*)(W + (size_t)(k0 + r) * Dd + n0 + cs + j * 4);
        __nv_bfloat16 h, l;
        split2(v.x, h, l); sh[cs + j*4 + 0][r] = h; sl[cs + j*4 + 0][r] = l;
        split2(v.y, h, l); sh[cs + j*4 + 1][r] = h; sl[cs + j*4 + 1][r] = l;
        split2(v.z, h, l); sh[cs + j*4 + 2][r] = h; sl[cs + j*4 + 2][r] = l;
        split2(v.w, h, l); sh[cs + j*4 + 3][r] = h; sl[cs + j*4 + 3][r] = l;
    }
    __syncthreads();

    int n = tid >> 2;
    int ks = (tid & 3) * 16;
    #pragma unroll
    for (int j = 0; j < 8; j++) {
        __nv_bfloat16 p0 = sh[n][ks + j*2], p1 = sh[n][ks + j*2 + 1];
        unsigned uh = (unsigned)__bfloat16_as_ushort(p0) | ((unsigned)__bfloat16_as_ushort(p1) << 16);
        p0 = sl[n][ks + j*2]; p1 = sl[n][ks + j*2 + 1];
        unsigned ul = (unsigned)__bfloat16_as_ushort(p0) | ((unsigned)__bfloat16_as_ushort(p1) << 16);
        *(unsigned*)(Oh + (size_t)(n0 + n) * Dd + k0 + ks + j*2) = uh;
        *(unsigned*)(Ol + (size_t)(n0 + n) * Dd + k0 + ks + j*2) = ul;
    }
}

// ---------------------------------------------------------------------------
// HMMA projection GEMM, fused (gridDim.z picks proj), 2-stage cp.async pipe.
// 64x128 tile, 128 threads (4 warps, each 64x32), KT=64 per stage, 2 CTAs/SM.
// Epilogue: Q scaled by log2e + split; K split; V single fp16 transposed.
// ---------------------------------------------------------------------------
#define GOFF_AH 0
#define GOFF_AL 8192
#define GOFF_BH 16384
#define GOFF_BL 32768
#define GSTAGE  49152
#define SMEM_GEMM (2*GSTAGE)

__global__ __launch_bounds__(128, 2) void gemm_hmma_kernel(
    const float* __restrict__ bq, const float* __restrict__ bk,
    const float* __restrict__ bv)
{
    extern __shared__ char s[];
    const unsigned base_u = smem_u32(s);

    const int which = blockIdx.z;
    const float* bias = (which == 0) ? bq : (which == 1) ? bk : bv;
    __nv_bfloat16* Hi = (which == 0) ? g_qh : g_kh;
    __nv_bfloat16* Lo = (which == 0) ? g_ql : g_kl;
    const char* wh_base = (const char*)(g_wth + (size_t)which * Dd * Dd);
    const char* wl_base = (const char*)(g_wtl + (size_t)which * Dd * Dd);
    const char* xh_base = (const char*)g_xh;
    const char* xl_base = (const char*)g_xl;

    const int tid  = threadIdx.x;
    const int w    = tid >> 5;
    const int lane = tid & 31;
    const int g    = lane >> 2;
    const int mrow = lane & 7;
    const int sel  = lane >> 3;
    const int wn0  = w * 32;
    const int bm   = blockIdx.x * 64;
    const int bn   = blockIdx.y * 128;

    const int a_row_off = ((sel & 1) << 3) + mrow;
    const int a_k_off   = (sel >> 1) << 4;
    const int brow_off  = ((sel >> 1) << 3) + mrow;
    const int bkb       = (sel & 1) << 4;

    float c[4][4][4];
    #pragma unroll
    for (int mi = 0; mi < 4; mi++)
        #pragma unroll
        for (int nj = 0; nj < 4; nj++)
            #pragma unroll
            for (int v = 0; v < 4; v++) c[mi][nj][v] = 0.0f;

    auto issue = [&](int kt) {
        unsigned so = base_u + (kt & 1) * GSTAGE;
        unsigned ko = (unsigned)kt * 128;
        #pragma unroll
        for (int rr = 0; rr < 4; rr++) {
            int idx = tid + rr * 128;
            int row = idx >> 3, c16 = idx & 7;
            unsigned sw = SMEM_SWZ((unsigned)(row * 128 + c16 * 16));
            unsigned gA = (unsigned)(bm + row) * 1024 + c16 * 16 + ko;
            CP_ASYNC16(so + GOFF_AH + sw, xh_base + gA);
            CP_ASYNC16(so + GOFF_AL + sw, xl_base + gA);
        }
        #pragma unroll
        for (int rr = 0; rr < 8; rr++) {
            int idx = tid + rr * 128;
            int row = idx >> 3, c16 = idx & 7;
            unsigned sw = SMEM_SWZ((unsigned)(row * 128 + c16 * 16));
            unsigned gB = (unsigned)(bn + row) * 1024 + c16 * 16 + ko;
            CP_ASYNC16(so + GOFF_BH + sw, wh_base + gB);
            CP_ASYNC16(so + GOFF_BL + sw, wl_base + gB);
        }
        CP_COMMIT();
    };

    issue(0);
    for (int kt = 0; kt < 8; kt++) {
        if (kt < 7) { issue(kt + 1); CP_WAIT1(); } else { CP_WAIT0(); }
        __syncthreads();

        unsigned sb = base_u + (kt & 1) * GSTAGE;
        #pragma unroll
        for (int ks = 0; ks < 4; ks++) {
            unsigned ah[4][4], al[4][4];
            #pragma unroll
            for (int mi = 0; mi < 4; mi++) {
                unsigned sw = SMEM_SWZ((unsigned)((mi * 16 + a_row_off) * 128 + ks * 32 + a_k_off));
                ldsm4(ah[mi], sb + GOFF_AH + sw);
                ldsm4(al[mi], sb + GOFF_AL + sw);
            }
            unsigned bh4[2][4], bl4[2][4];
            #pragma unroll
            for (int np = 0; np < 2; np++) {
                unsigned sw = SMEM_SWZ((unsigned)((wn0 + np * 16 + brow_off) * 128 + ks * 32 + bkb));
                ldsm4(bh4[np], sb + GOFF_BH + sw);
                ldsm4(bl4[np], sb + GOFF_BL + sw);
            }
            #pragma unroll
            for (int mi = 0; mi < 4; mi++)
                #pragma unroll
                for (int nj = 0; nj < 4; nj++) {
                    const unsigned* bp_h = bh4[nj >> 1] + (nj & 1) * 2;
                    const unsigned* bp_l = bl4[nj >> 1] + (nj & 1) * 2;
                    mma16816(c[mi][nj], ah[mi], bp_h);
                    mma16816(c[mi][nj], ah[mi], bp_l);
                    mma16816(c[mi][nj], al[mi], bp_h);
                }
        }
        __syncthreads();
    }

    // Epilogue: bias + per-proj transform + scatter
    #pragma unroll
    for (int nj = 0; nj < 4; nj++) {
        int cb = bn + wn0 + nj * 8 + (lane & 3) * 2;
        float b0 = __ldg(bias + cb), b1 = __ldg(bias + cb + 1);
        int h0 = cb >> 6, d0 = cb & 63;
        int h1 = (cb + 1) >> 6, d1 = (cb + 1) & 63;
        #pragma unroll
        for (int mi = 0; mi < 4; mi++) {
            #pragma unroll
            for (int half = 0; half < 2; half++) {
                int m = bm + mi * 16 + g + half * 8;
                int bb = m >> 10, ns = m & 1023;
                float v0 = c[mi][nj][half * 2 + 0] + b0;
                float v1 = c[mi][nj][half * 2 + 1] + b1;
                if (which == 2) {
                    // V: single fp16, transposed per head
                    size_t dst0 = ((size_t)(bb * Hh + h0) * DHd + d0) * Nn + ns;
                    size_t dst1 = ((size_t)(bb * Hh + h1) * DHd + d1) * Nn + ns;
                    g_vh[dst0] = __float2half(v0);
                    g_vh[dst1] = __float2half(v1);
                } else {
                    if (which == 0) { v0 *= LOG2E; v1 *= LOG2E; }   // exp2-domain softmax
                    size_t dst0 = ((size_t)(bb * Hh + h0) * Nn + ns) * DHd + d0;
                    size_t dst1 = dst0 + (d1 - d0) + (size_t)(h1 - h0) * Nn * DHd;
                    __nv_bfloat16 hi, lo;
                    split2(v0, hi, lo); Hi[dst0] = hi; Lo[dst0] = lo;
                    split2(v1, hi, lo); Hi[dst1] = hi; Lo[dst1] = lo;
                }
            }
        }
    }
}

// ---------------------------------------------------------------------------
// HMMA flash attention, 128 threads (4 warps) over a 64-row q tile,
// 2-stage cp.async K/V pipeline. S: bf16 3-pass; O: fp16 single-pass.
// smem 64KB -> 2 CTAs/SM. grid = (16 q-tiles, 64 bh).
// ---------------------------------------------------------------------------
#define FOFF_Q   0
#define FOFF_QL  8192
#define FSTAGE0  16384
#define FKH 0
#define FKL 8192
#define FV  16384
#define FSTAGE   24576
#define SMEM_FA  (FSTAGE0 + 2*FSTAGE)   // 65536

__global__ __launch_bounds__(128, 2) void fa_kernel(float* __restrict__ y)
{
    extern __shared__ char s[];
    const unsigned base_u = smem_u32(s);

    const int tid  = threadIdx.x;
    const int w    = tid >> 5;
    const int lane = tid & 31;
    const int g    = lane >> 2;
    const int t2   = (lane & 3) * 2;
    const int bh   = blockIdx.y;
    const int b    = bh >> 3, h = bh & 7;
    const int qt   = blockIdx.x;
    const int q0   = qt * 64;
    const int wq0  = w * 16;

    const int mrow = lane & 7;
    const int sel  = lane >> 3;

    const char* kh_base = (const char*)(g_kh + (size_t)bh * Nn * DHd);
    const char* kl_base = (const char*)(g_kl + (size_t)bh * Nn * DHd);
    const char* vh_base = (const char*)(g_vh + (size_t)bh * DHd * Nn);

    // per-thread K/V load addressing (4 x 16B chunks per 8KB buffer)
    unsigned f_sw[4]; int f_row[4], f_c16[4];
    #pragma unroll
    for (int rr = 0; rr < 4; rr++) {
        int idx = tid + rr * 128;
        f_row[rr] = idx >> 3; f_c16[rr] = idx & 7;
        f_sw[rr] = SMEM_SWZ((unsigned)(f_row[rr] * 128 + f_c16[rr] * 16));
    }

    auto issue = [&](int t) {
        unsigned so = base_u + FSTAGE0 + (t & 1) * FSTAGE;
        int t0 = t << 6;
        #pragma unroll
        for (int rr = 0; rr < 4; rr++) {
            unsigned kof = (unsigned)(t0 + f_row[rr]) * 128 + f_c16[rr] * 16;
            unsigned vof = (unsigned)f_row[rr] * 2048 + (unsigned)t0 * 2 + f_c16[rr] * 16;
            CP_ASYNC16(so + FKH + f_sw[rr], kh_base + kof);
            CP_ASYNC16(so + FKL + f_sw[rr], kl_base + kof);
            CP_ASYNC16(so + FV  + f_sw[rr], vh_base + vof);
        }
        CP_COMMIT();
    };

    issue(0);   // overlap with Q load + fragment hoist below

    // Q tiles (64 q-rows x 64 d bf16, swizzled 128B rows)
    const char* qh_src = (const char*)(g_qh + ((size_t)bh * Nn + q0) * DHd);
    const char* ql_src = (const char*)(g_ql + ((size_t)bh * Nn + q0) * DHd);
    #pragma unroll
    for (int rr = 0; rr < 4; rr++) {
        int idx = tid + rr * 128;
        int row = idx >> 3, c16 = idx & 7;
        unsigned byte = row * 128 + c16 * 16;
        unsigned sw = SMEM_SWZ(byte);
        *(float4*)(s + FOFF_Q + sw) = *(const float4*)(qh_src + byte);
        *(float4*)(s + FOFF_QL + sw) = *(const float4*)(ql_src + byte);
    }
    __syncthreads();

    unsigned qh[4][4], ql[4][4];
    {
        int arow = wq0 + ((sel & 1) << 3) + mrow;
        #pragma unroll
        for (int ks = 0; ks < 4; ks++) {
            unsigned byte = arow * 128 + ks * 32 + ((sel >> 1) << 4);
            unsigned sw = SMEM_SWZ(byte);
            ldsm4(qh[ks], base_u + FOFF_Q + sw);
            ldsm4(ql[ks], base_u + FOFF_QL + sw);
        }
    }

    float m0 = -1e30f, m1 = -1e30f, l0 = 0.0f, l1 = 0.0f;
    float o[8][4];
    #pragma unroll
    for (int i = 0; i < 8; i++)
        #pragma unroll
        for (int v = 0; v < 4; v++) o[i][v] = 0.0f;

    const int brow_off = ((sel >> 1) << 3) + mrow;
    const int bkb      = (sel & 1) << 4;

    for (int t = 0; t < 16; t++) {
        if (t < 15) { issue(t + 1); CP_WAIT1(); } else { CP_WAIT0(); }
        __syncthreads();

        unsigned sb = base_u + FSTAGE0 + (t & 1) * FSTAGE;

        // S = Q K^T (scores already in log2 domain via Q prescale)
        float c[8][4];
        #pragma unroll
        for (int j = 0; j < 8; j++)
            #pragma unroll
            for (int v = 0; v < 4; v++) c[j][v] = 0.0f;

        #pragma unroll
        for (int ks = 0; ks < 4; ks++) {
            #pragma unroll
            for (int np = 0; np < 4; np++) {
                unsigned sw = SMEM_SWZ((unsigned)((np * 16 + brow_off) * 128 + ks * 32 + bkb));
                unsigned kh4[4], kl4[4];
                ldsm4(kh4, sb + FKH + sw);
                ldsm4(kl4, sb + FKL + sw);
                mma16816(c[2*np],   qh[ks], kh4);
                mma16816(c[2*np],   qh[ks], kl4);
                mma16816(c[2*np],   ql[ks], kh4);
                mma16816(c[2*np+1], qh[ks], kh4 + 2);
                mma16816(c[2*np+1], qh[ks], kl4 + 2);
                mma16816(c[2*np+1], ql[ks], kh4 + 2);
            }
        }

        // online softmax (exp2 domain)
        float rm0 = -1e30f, rm1 = -1e30f;
        #pragma unroll
        for (int j = 0; j < 8; j++) {
            rm0 = fmaxf(rm0, fmaxf(c[j][0], c[j][1]));
            rm1 = fmaxf(rm1, fmaxf(c[j][2], c[j][3]));
        }
        rm0 = fmaxf(rm0, __shfl_xor_sync(0xFFFFFFFFu, rm0, 1));
        rm0 = fmaxf(rm0, __shfl_xor_sync(0xFFFFFFFFu, rm0, 2));
        rm1 = fmaxf(rm1, __shfl_xor_sync(0xFFFFFFFFu, rm1, 1));
        rm1 = fmaxf(rm1, __shfl_xor_sync(0xFFFFFFFFu, rm1, 2));

        float mn0 = fmaxf(m0, rm0), mn1 = fmaxf(m1, rm1);
        float cr0 = ex2f(m0 - mn0), cr1 = ex2f(m1 - mn1);
        m0 = mn0; m1 = mn1;

        float rs0 = 0.0f, rs1 = 0.0f;
        #pragma unroll
        for (int j = 0; j < 8; j++) {
            c[j][0] = ex2f(c[j][0] - m0);
            c[j][1] = ex2f(c[j][1] - m0);
            c[j][2] = ex2f(c[j][2] - m1);
            c[j][3] = ex2f(c[j][3] - m1);
            rs0 += c[j][0] + c[j][1];
            rs1 += c[j][2] + c[j][3];
        }
        rs0 += __shfl_xor_sync(0xFFFFFFFFu, rs0, 1);
        rs0 += __shfl_xor_sync(0xFFFFFFFFu, rs0, 2);
        rs1 += __shfl_xor_sync(0xFFFFFFFFu, rs1, 1);
        rs1 += __shfl_xor_sync(0xFFFFFFFFu, rs1, 2);
        l0 = l0 * cr0 + rs0;
        l1 = l1 * cr1 + rs1;

        // rescale O only if any row's max moved (rare after warmup)
        if (__any_sync(0xFFFFFFFFu, (cr0 != 1.0f) | (cr1 != 1.0f))) {
            #pragma unroll
            for (int jd = 0; jd < 8; jd++) {
                o[jd][0] *= cr0; o[jd][1] *= cr0;
                o[jd][2] *= cr1; o[jd][3] *= cr1;
            }
        }

        // P as single fp16 fragments
        unsigned ph[4][4];
        #pragma unroll
        for (int ks = 0; ks < 4; ks++) {
            #pragma unroll
            for (int u = 0; u < 4; u++) {
                int j = 2 * ks + (u >> 1);
                int v = (u & 1) * 2;
                __half2 hv = __floats2half2_rn(c[j][v], c[j][v + 1]);
                ph[ks][u] = *(unsigned*)&hv;
            }
        }

        // O += P V, single fp16 pass
        #pragma unroll
        for (int ks = 0; ks < 4; ks++) {
            #pragma unroll
            for (int dp = 0; dp < 4; dp++) {
                unsigned sw = SMEM_SWZ((unsigned)((dp * 16 + brow_off) * 128 + ks * 32 + bkb));
                unsigned vh4[4];
                ldsm4(vh4, sb + FV + sw);
                mma16816h(o[2*dp],   ph[ks], vh4);
                mma16816h(o[2*dp+1], ph[ks], vh4 + 2);
            }
        }
        __syncthreads();   // stage (t&1) reusable at t+2
    }

    float inv0 = 1.0f / l0, inv1 = 1.0f / l1;
    int row0 = q0 + wq0 + g;
    int row1 = row0 + 8;
    float* y0 = y + ((size_t)(b * Nn + row0)) * Dd + h * DHd;
    float* y1 = y + ((size_t)(b * Nn + row1)) * Dd + h * DHd;
    #pragma unroll
    for (int jd = 0; jd < 8; jd++) {
        float2 p0 = make_float2(o[jd][0] * inv0, o[jd][1] * inv0);
        float2 p1 = make_float2(o[jd][2] * inv1, o[jd][3] * inv1);
        *(float2*)(y0 + jd * 8 + t2) = p0;
        *(float2*)(y1 + jd * 8 + t2) = p1;
    }
}

// ---------------------------------------------------------------------------
// Inputs (metadata order): x, Wq, bq, Wk, bk, Wv, bv. Output: float32 [B,N,D].
// ---------------------------------------------------------------------------
extern "C" void kernel_launch(void* const* d_in, const int* in_sizes, int n_in,
                              void* d_out, int out_size)
{
    const float* x  = (const float*)d_in[0];
    const float* Wq = (const float*)d_in[1];
    const float* bq = (const float*)d_in[2];
    const float* Wk = (const float*)d_in[3];
    const float* bk = (const float*)d_in[4];
    const float* Wv = (const float*)d_in[5];
    const float* bv = (const float*)d_in[6];
    float* y = (float*)d_out;

    cudaFuncSetAttribute(gemm_hmma_kernel, cudaFuncAttributeMaxDynamicSharedMemorySize, SMEM_GEMM);
    cudaFuncSetAttribute(fa_kernel, cudaFuncAttributeMaxDynamicSharedMemorySize, SMEM_FA);

    split_x_kernel<<<4096, 256>>>(x);
    split_wt_kernel<<<dim3(8, 8, 3), 256>>>(Wq, Wk, Wv);

    dim3 ggrid(MTOT / 64, Dd / 128, 3);    // (128, 4, 3) fused
    gemm_hmma_kernel<<<ggrid, 128, SMEM_GEMM>>>(bq, bk, bv);

    dim3 agrid(Nn / 64, BH);               // (16, 64)
    fa_kernel<<<agrid, 128, SMEM_FA>>>(y);
}

// round 11
// speedup vs baseline: 5.0669x; 1.0295x over previous
#include <cuda_runtime.h>
#include <cuda_bf16.h>
#include <cuda_fp16.h>

// Problem constants
#define Bb   8
#define Nn   1024
#define Dd   512
#define Hh   8
#define DHd  64
#define MTOT (Bb*Nn)   // 8192
#define BH   (Bb*Hh)   // 64
#define LOG2E 1.4426950408889634f

// Split-bf16 operands for the projection GEMMs
__device__ __nv_bfloat16 g_xh[MTOT*Dd];
__device__ __nv_bfloat16 g_xl[MTOT*Dd];
__device__ __nv_bfloat16 g_wth[3*Dd*Dd];   // W^T per proj: [n][k]
__device__ __nv_bfloat16 g_wtl[3*Dd*Dd];

// Q/K split-bf16 head-major [BH, N, 64] (Q pre-scaled by log2e); V^T fp16 [BH, 64, N]
__device__ __nv_bfloat16 g_qh[BH*Nn*DHd];
__device__ __nv_bfloat16 g_ql[BH*Nn*DHd];
__device__ __nv_bfloat16 g_kh[BH*Nn*DHd];
__device__ __nv_bfloat16 g_kl[BH*Nn*DHd];
__device__ __half        g_vh[BH*DHd*Nn];

#define SMEM_SWZ(b) ((b) ^ (((b) >> 3) & 0x70))

static __device__ __forceinline__ unsigned smem_u32(const void* p) {
    unsigned a;
    asm("{ .reg .u64 t; cvta.to.shared.u64 t, %1; cvt.u32.u64 %0, t; }" : "=r"(a) : "l"(p));
    return a;
}

static __device__ __forceinline__ float ex2f(float x) {
    float r;
    asm("ex2.approx.f32 %0, %1;" : "=f"(r) : "f"(x));
    return r;
}

// cp.async helpers (sm_80+)
#define CP_ASYNC16(dst_u32, src_ptr) \
    asm volatile("cp.async.cg.shared.global [%0], [%1], 16;" :: "r"(dst_u32), "l"(src_ptr))
#define CP_COMMIT() asm volatile("cp.async.commit_group;")
#define CP_WAIT1()  asm volatile("cp.async.wait_group 1;")
#define CP_WAIT0()  asm volatile("cp.async.wait_group 0;")

// mma.sync m16n8k16 bf16 -> fp32
static __device__ __forceinline__ void mma16816(float* c, const unsigned* a, const unsigned* b) {
    asm volatile(
        "mma.sync.aligned.m16n8k16.row.col.f32.bf16.bf16.f32 "
        "{%0,%1,%2,%3}, {%4,%5,%6,%7}, {%8,%9}, {%0,%1,%2,%3};"
        : "+f"(c[0]), "+f"(c[1]), "+f"(c[2]), "+f"(c[3])
        : "r"(a[0]), "r"(a[1]), "r"(a[2]), "r"(a[3]), "r"(b[0]), "r"(b[1]));
}

// mma.sync m16n8k16 fp16 -> fp32
static __device__ __forceinline__ void mma16816h(float* c, const unsigned* a, const unsigned* b) {
    asm volatile(
        "mma.sync.aligned.m16n8k16.row.col.f32.f16.f16.f32 "
        "{%0,%1,%2,%3}, {%4,%5,%6,%7}, {%8,%9}, {%0,%1,%2,%3};"
        : "+f"(c[0]), "+f"(c[1]), "+f"(c[2]), "+f"(c[3])
        : "r"(a[0]), "r"(a[1]), "r"(a[2]), "r"(a[3]), "r"(b[0]), "r"(b[1]));
}

static __device__ __forceinline__ void ldsm4(unsigned* r, unsigned addr) {
    asm volatile("ldmatrix.sync.aligned.m8n8.x4.shared.b16 {%0,%1,%2,%3}, [%4];"
                 : "=r"(r[0]), "=r"(r[1]), "=r"(r[2]), "=r"(r[3]) : "r"(addr));
}

static __device__ __forceinline__ void split2(float v, __nv_bfloat16& hi, __nv_bfloat16& lo) {
    hi = __float2bfloat16(v);
    lo = __float2bfloat16(v - __bfloat162float(hi));
}

// ---------------------------------------------------------------------------
// split_x: x fp32 [8192,512] -> g_xh/g_xl bf16. One float4 per thread.
// ---------------------------------------------------------------------------
__global__ __launch_bounds__(256) void split_x_kernel(const float* __restrict__ x)
{
    int i = blockIdx.x * 256 + threadIdx.x;          // float4 index, < 1048576
    float4 v = ((const float4*)x)[i];
    __nv_bfloat16 h[4], l[4];
    split2(v.x, h[0], l[0]); split2(v.y, h[1], l[1]);
    split2(v.z, h[2], l[2]); split2(v.w, h[3], l[3]);
    ((uint2*)g_xh)[i] = *(uint2*)h;
    ((uint2*)g_xl)[i] = *(uint2*)l;
}

// ---------------------------------------------------------------------------
// split_wt: W [512,512] ([k][n]) -> W^T hi/lo [n][k]. 64x64 tiles.
// ---------------------------------------------------------------------------
__global__ __launch_bounds__(256) void split_wt_kernel(
    const float* __restrict__ W0, const float* __restrict__ W1,
    const float* __restrict__ W2)
{
    const float* W = (blockIdx.z == 0) ? W0 : (blockIdx.z == 1) ? W1 : W2;
    __nv_bfloat16* Oh = g_wth + (size_t)blockIdx.z * Dd * Dd;
    __nv_bfloat16* Ol = g_wtl + (size_t)blockIdx.z * Dd * Dd;

    __shared__ __nv_bfloat16 sh[64][68];
    __shared__ __nv_bfloat16 sl[64][68];

    const int k0 = blockIdx.y * 64;
    const int n0 = blockIdx.x * 64;
    const int tid = threadIdx.x;

    int r = tid >> 2;
    int cs = (tid & 3) * 16;
    #pragma unroll
    for (int j = 0; j < 4; j++) {
        float4 v = *(const float4*)(W + (size_t)(k0 + r) * Dd + n0 + cs + j * 4);
        __nv_bfloat16 h, l;
        split2(v.x, h, l); sh[cs + j*4 + 0][r] = h; sl[cs + j*4 + 0][r] = l;
        split2(v.y, h, l); sh[cs + j*4 + 1][r] = h; sl[cs + j*4 + 1][r] = l;
        split2(v.z, h, l); sh[cs + j*4 + 2][r] = h; sl[cs + j*4 + 2][r] = l;
        split2(v.w, h, l); sh[cs + j*4 + 3][r] = h; sl[cs + j*4 + 3][r] = l;
    }
    __syncthreads();

    int n = tid >> 2;
    int ks = (tid & 3) * 16;
    #pragma unroll
    for (int j = 0; j < 8; j++) {
        __nv_bfloat16 p0 = sh[n][ks + j*2], p1 = sh[n][ks + j*2 + 1];
        unsigned uh = (unsigned)__bfloat16_as_ushort(p0) | ((unsigned)__bfloat16_as_ushort(p1) << 16);
        p0 = sl[n][ks + j*2]; p1 = sl[n][ks + j*2 + 1];
        unsigned ul = (unsigned)__bfloat16_as_ushort(p0) | ((unsigned)__bfloat16_as_ushort(p1) << 16);
        *(unsigned*)(Oh + (size_t)(n0 + n) * Dd + k0 + ks + j*2) = uh;
        *(unsigned*)(Ol + (size_t)(n0 + n) * Dd + k0 + ks + j*2) = ul;
    }
}

// ---------------------------------------------------------------------------
// HMMA projection GEMM, fused (gridDim.z picks proj), 2-stage cp.async pipe.
// 64x128 tile, 128 threads (4 warps, each 64x32), KT=64 per stage, 2 CTAs/SM.
// Epilogue: Q scaled by log2e + split; K split; V single fp16 transposed.
// ---------------------------------------------------------------------------
#define GOFF_AH 0
#define GOFF_AL 8192
#define GOFF_BH 16384
#define GOFF_BL 32768
#define GSTAGE  49152
#define SMEM_GEMM (2*GSTAGE)

__global__ __launch_bounds__(128, 2) void gemm_hmma_kernel(
    const float* __restrict__ bq, const float* __restrict__ bk,
    const float* __restrict__ bv)
{
    extern __shared__ char s[];
    const unsigned base_u = smem_u32(s);

    const int which = blockIdx.z;
    const float* bias = (which == 0) ? bq : (which == 1) ? bk : bv;
    __nv_bfloat16* Hi = (which == 0) ? g_qh : g_kh;
    __nv_bfloat16* Lo = (which == 0) ? g_ql : g_kl;
    const char* wh_base = (const char*)(g_wth + (size_t)which * Dd * Dd);
    const char* wl_base = (const char*)(g_wtl + (size_t)which * Dd * Dd);
    const char* xh_base = (const char*)g_xh;
    const char* xl_base = (const char*)g_xl;

    const int tid  = threadIdx.x;
    const int w    = tid >> 5;
    const int lane = tid & 31;
    const int g    = lane >> 2;
    const int mrow = lane & 7;
    const int sel  = lane >> 3;
    const int wn0  = w * 32;
    const int bm   = blockIdx.x * 64;
    const int bn   = blockIdx.y * 128;

    const int a_row_off = ((sel & 1) << 3) + mrow;
    const int a_k_off   = (sel >> 1) << 4;
    const int brow_off  = ((sel >> 1) << 3) + mrow;
    const int bkb       = (sel & 1) << 4;

    float c[4][4][4];
    #pragma unroll
    for (int mi = 0; mi < 4; mi++)
        #pragma unroll
        for (int nj = 0; nj < 4; nj++)
            #pragma unroll
            for (int v = 0; v < 4; v++) c[mi][nj][v] = 0.0f;

    auto issue = [&](int kt) {
        unsigned so = base_u + (kt & 1) * GSTAGE;
        unsigned ko = (unsigned)kt * 128;
        #pragma unroll
        for (int rr = 0; rr < 4; rr++) {
            int idx = tid + rr * 128;
            int row = idx >> 3, c16 = idx & 7;
            unsigned sw = SMEM_SWZ((unsigned)(row * 128 + c16 * 16));
            unsigned gA = (unsigned)(bm + row) * 1024 + c16 * 16 + ko;
            CP_ASYNC16(so + GOFF_AH + sw, xh_base + gA);
            CP_ASYNC16(so + GOFF_AL + sw, xl_base + gA);
        }
        #pragma unroll
        for (int rr = 0; rr < 8; rr++) {
            int idx = tid + rr * 128;
            int row = idx >> 3, c16 = idx & 7;
            unsigned sw = SMEM_SWZ((unsigned)(row * 128 + c16 * 16));
            unsigned gB = (unsigned)(bn + row) * 1024 + c16 * 16 + ko;
            CP_ASYNC16(so + GOFF_BH + sw, wh_base + gB);
            CP_ASYNC16(so + GOFF_BL + sw, wl_base + gB);
        }
        CP_COMMIT();
    };

    issue(0);
    for (int kt = 0; kt < 8; kt++) {
        if (kt < 7) { issue(kt + 1); CP_WAIT1(); } else { CP_WAIT0(); }
        __syncthreads();

        unsigned sb = base_u + (kt & 1) * GSTAGE;
        #pragma unroll
        for (int ks = 0; ks < 4; ks++) {
            unsigned ah[4][4], al[4][4];
            #pragma unroll
            for (int mi = 0; mi < 4; mi++) {
                unsigned sw = SMEM_SWZ((unsigned)((mi * 16 + a_row_off) * 128 + ks * 32 + a_k_off));
                ldsm4(ah[mi], sb + GOFF_AH + sw);
                ldsm4(al[mi], sb + GOFF_AL + sw);
            }
            unsigned bh4[2][4], bl4[2][4];
            #pragma unroll
            for (int np = 0; np < 2; np++) {
                unsigned sw = SMEM_SWZ((unsigned)((wn0 + np * 16 + brow_off) * 128 + ks * 32 + bkb));
                ldsm4(bh4[np], sb + GOFF_BH + sw);
                ldsm4(bl4[np], sb + GOFF_BL + sw);
            }
            #pragma unroll
            for (int mi = 0; mi < 4; mi++)
                #pragma unroll
                for (int nj = 0; nj < 4; nj++) {
                    const unsigned* bp_h = bh4[nj >> 1] + (nj & 1) * 2;
                    const unsigned* bp_l = bl4[nj >> 1] + (nj & 1) * 2;
                    mma16816(c[mi][nj], ah[mi], bp_h);
                    mma16816(c[mi][nj], ah[mi], bp_l);
                    mma16816(c[mi][nj], al[mi], bp_h);
                }
        }
        __syncthreads();
    }

    // Epilogue: bias + per-proj transform + scatter
    #pragma unroll
    for (int nj = 0; nj < 4; nj++) {
        int cb = bn + wn0 + nj * 8 + (lane & 3) * 2;
        float b0 = __ldg(bias + cb), b1 = __ldg(bias + cb + 1);
        int h0 = cb >> 6, d0 = cb & 63;
        int h1 = (cb + 1) >> 6, d1 = (cb + 1) & 63;
        #pragma unroll
        for (int mi = 0; mi < 4; mi++) {
            #pragma unroll
            for (int half = 0; half < 2; half++) {
                int m = bm + mi * 16 + g + half * 8;
                int bb = m >> 10, ns = m & 1023;
                float v0 = c[mi][nj][half * 2 + 0] + b0;
                float v1 = c[mi][nj][half * 2 + 1] + b1;
                if (which == 2) {
                    // V: single fp16, transposed per head
                    size_t dst0 = ((size_t)(bb * Hh + h0) * DHd + d0) * Nn + ns;
                    size_t dst1 = ((size_t)(bb * Hh + h1) * DHd + d1) * Nn + ns;
                    g_vh[dst0] = __float2half(v0);
                    g_vh[dst1] = __float2half(v1);
                } else {
                    if (which == 0) { v0 *= LOG2E; v1 *= LOG2E; }   // exp2-domain softmax
                    size_t dst0 = ((size_t)(bb * Hh + h0) * Nn + ns) * DHd + d0;
                    size_t dst1 = dst0 + (d1 - d0) + (size_t)(h1 - h0) * Nn * DHd;
                    __nv_bfloat16 hi, lo;
                    split2(v0, hi, lo); Hi[dst0] = hi; Lo[dst0] = lo;
                    split2(v1, hi, lo); Hi[dst1] = hi; Lo[dst1] = lo;
                }
            }
        }
    }
}

// ---------------------------------------------------------------------------
// HMMA flash attention, 128 threads (4 warps) over a 64-row q tile,
// 2-stage cp.async K/V pipeline. S: bf16 3-pass; O: fp16 single-pass.
// Row sums via ones-column MMA (accumulator col 0 = running l).
// Q fragments re-loaded from smem each iter (reg relief) -> 3 CTAs/SM.
// grid = (16 q-tiles, 64 bh).
// ---------------------------------------------------------------------------
#define FOFF_Q   0
#define FOFF_QL  8192
#define FSTAGE0  16384
#define FKH 0
#define FKL 8192
#define FV  16384
#define FSTAGE   24576
#define FONES    (FSTAGE0 + 2*FSTAGE)     // 65536, 2KB ones tile
#define SMEM_FA  (FONES + 2048)           // 67584

__global__ __launch_bounds__(128, 3) void fa_kernel(float* __restrict__ y)
{
    extern __shared__ char s[];
    const unsigned base_u = smem_u32(s);

    const int tid  = threadIdx.x;
    const int w    = tid >> 5;
    const int lane = tid & 31;
    const int g    = lane >> 2;
    const int t2   = (lane & 3) * 2;
    const int bh   = blockIdx.y;
    const int b    = bh >> 3, h = bh & 7;
    const int qt   = blockIdx.x;
    const int q0   = qt * 64;
    const int wq0  = w * 16;

    const int mrow = lane & 7;
    const int sel  = lane >> 3;
    const int a_row_off = ((sel & 1) << 3) + mrow;
    const int a_k_off   = (sel >> 1) << 4;
    const int brow_off  = ((sel >> 1) << 3) + mrow;
    const int bkb       = (sel & 1) << 4;

    const char* kh_base = (const char*)(g_kh + (size_t)bh * Nn * DHd);
    const char* kl_base = (const char*)(g_kl + (size_t)bh * Nn * DHd);
    const char* vh_base = (const char*)(g_vh + (size_t)bh * DHd * Nn);

    // per-thread K/V load addressing (4 x 16B chunks per 8KB buffer)
    unsigned f_sw[4]; int f_row[4], f_c16[4];
    #pragma unroll
    for (int rr = 0; rr < 4; rr++) {
        int idx = tid + rr * 128;
        f_row[rr] = idx >> 3; f_c16[rr] = idx & 7;
        f_sw[rr] = SMEM_SWZ((unsigned)(f_row[rr] * 128 + f_c16[rr] * 16));
    }

    auto issue = [&](int t) {
        unsigned so = base_u + FSTAGE0 + (t & 1) * FSTAGE;
        int t0 = t << 6;
        #pragma unroll
        for (int rr = 0; rr < 4; rr++) {
            unsigned kof = (unsigned)(t0 + f_row[rr]) * 128 + f_c16[rr] * 16;
            unsigned vof = (unsigned)f_row[rr] * 2048 + (unsigned)t0 * 2 + f_c16[rr] * 16;
            CP_ASYNC16(so + FKH + f_sw[rr], kh_base + kof);
            CP_ASYNC16(so + FKL + f_sw[rr], kl_base + kof);
            CP_ASYNC16(so + FV  + f_sw[rr], vh_base + vof);
        }
        CP_COMMIT();
    };

    issue(0);   // overlap with Q load below

    // ones tile: 16 rows x 128B; row 0 = fp16 1.0, rows 1..15 = 0.
    // Row content is uniform so the SW128 swizzle (within-row chunk permute)
    // is a no-op for correctness.
    for (int i = tid; i < 512; i += 128) {
        *(unsigned*)(s + FONES + i * 4) = (i < 32) ? 0x3C003C00u : 0u;
    }

    // Q tiles (64 q-rows x 64 d bf16, swizzled 128B rows)
    const char* qh_src = (const char*)(g_qh + ((size_t)bh * Nn + q0) * DHd);
    const char* ql_src = (const char*)(g_ql + ((size_t)bh * Nn + q0) * DHd);
    #pragma unroll
    for (int rr = 0; rr < 4; rr++) {
        int idx = tid + rr * 128;
        int row = idx >> 3, c16 = idx & 7;
        unsigned byte = row * 128 + c16 * 16;
        unsigned sw = SMEM_SWZ(byte);
        *(float4*)(s + FOFF_Q + sw) = *(const float4*)(qh_src + byte);
        *(float4*)(s + FOFF_QL + sw) = *(const float4*)(ql_src + byte);
    }
    __syncthreads();

    // ones B-fragment (constant across iters): rows 0..15 of ones tile
    unsigned onesb[4];
    ldsm4(onesb, base_u + FONES + SMEM_SWZ((unsigned)(brow_off * 128 + bkb)));

    float m0 = -1e30f, m1 = -1e30f;
    float o[8][4];
    float ol[4];                 // ones-column accumulator: col0 = running l
    #pragma unroll
    for (int i = 0; i < 8; i++)
        #pragma unroll
        for (int v = 0; v < 4; v++) o[i][v] = 0.0f;
    #pragma unroll
    for (int v = 0; v < 4; v++) ol[v] = 0.0f;

    for (int t = 0; t < 16; t++) {
        if (t < 15) { issue(t + 1); CP_WAIT1(); } else { CP_WAIT0(); }
        __syncthreads();

        unsigned sb = base_u + FSTAGE0 + (t & 1) * FSTAGE;

        // S = Q K^T (scores in log2 domain via Q prescale)
        float c[8][4];
        #pragma unroll
        for (int j = 0; j < 8; j++)
            #pragma unroll
            for (int v = 0; v < 4; v++) c[j][v] = 0.0f;

        #pragma unroll
        for (int ks = 0; ks < 4; ks++) {
            unsigned qh4[4], ql4[4];
            unsigned qsw = SMEM_SWZ((unsigned)((wq0 + a_row_off) * 128 + ks * 32 + a_k_off));
            ldsm4(qh4, base_u + FOFF_Q + qsw);
            ldsm4(ql4, base_u + FOFF_QL + qsw);
            #pragma unroll
            for (int np = 0; np < 4; np++) {
                unsigned sw = SMEM_SWZ((unsigned)((np * 16 + brow_off) * 128 + ks * 32 + bkb));
                unsigned kh4[4], kl4[4];
                ldsm4(kh4, sb + FKH + sw);
                ldsm4(kl4, sb + FKL + sw);
                mma16816(c[2*np],   qh4, kh4);
                mma16816(c[2*np],   qh4, kl4);
                mma16816(c[2*np],   ql4, kh4);
                mma16816(c[2*np+1], qh4, kh4 + 2);
                mma16816(c[2*np+1], qh4, kl4 + 2);
                mma16816(c[2*np+1], ql4, kh4 + 2);
            }
        }

        // online softmax (exp2 domain); row sums handled by ones-MMA below
        float rm0 = -1e30f, rm1 = -1e30f;
        #pragma unroll
        for (int j = 0; j < 8; j++) {
            rm0 = fmaxf(rm0, fmaxf(c[j][0], c[j][1]));
            rm1 = fmaxf(rm1, fmaxf(c[j][2], c[j][3]));
        }
        rm0 = fmaxf(rm0, __shfl_xor_sync(0xFFFFFFFFu, rm0, 1));
        rm0 = fmaxf(rm0, __shfl_xor_sync(0xFFFFFFFFu, rm0, 2));
        rm1 = fmaxf(rm1, __shfl_xor_sync(0xFFFFFFFFu, rm1, 1));
        rm1 = fmaxf(rm1, __shfl_xor_sync(0xFFFFFFFFu, rm1, 2));

        float mn0 = fmaxf(m0, rm0), mn1 = fmaxf(m1, rm1);
        float cr0 = ex2f(m0 - mn0), cr1 = ex2f(m1 - mn1);
        m0 = mn0; m1 = mn1;

        #pragma unroll
        for (int j = 0; j < 8; j++) {
            c[j][0] = ex2f(c[j][0] - m0);
            c[j][1] = ex2f(c[j][1] - m0);
            c[j][2] = ex2f(c[j][2] - m1);
            c[j][3] = ex2f(c[j][3] - m1);
        }

        // rescale O (and l accumulator) only if any row's max moved
        if (__any_sync(0xFFFFFFFFu, (cr0 != 1.0f) | (cr1 != 1.0f))) {
            #pragma unroll
            for (int jd = 0; jd < 8; jd++) {
                o[jd][0] *= cr0; o[jd][1] *= cr0;
                o[jd][2] *= cr1; o[jd][3] *= cr1;
            }
            ol[0] *= cr0; ol[1] *= cr0;
            ol[2] *= cr1; ol[3] *= cr1;
        }

        // P as single fp16 fragments
        unsigned ph[4][4];
        #pragma unroll
        for (int ks = 0; ks < 4; ks++) {
            #pragma unroll
            for (int u = 0; u < 4; u++) {
                int j = 2 * ks + (u >> 1);
                int v = (u & 1) * 2;
                __half2 hv = __floats2half2_rn(c[j][v], c[j][v + 1]);
                ph[ks][u] = *(unsigned*)&hv;
            }
        }

        // O += P V (fp16), plus ones-column MMA accumulating row sums
        #pragma unroll
        for (int ks = 0; ks < 4; ks++) {
            #pragma unroll
            for (int dp = 0; dp < 4; dp++) {
                unsigned sw = SMEM_SWZ((unsigned)((dp * 16 + brow_off) * 128 + ks * 32 + bkb));
                unsigned vh4[4];
                ldsm4(vh4, sb + FV + sw);
                mma16816h(o[2*dp],   ph[ks], vh4);
                mma16816h(o[2*dp+1], ph[ks], vh4 + 2);
            }
            mma16816h(ol, ph[ks], onesb);
        }
        __syncthreads();   // stage (t&1) reusable at t+2
    }

    // l lives in ones-column col 0 -> lanes with t2==0; broadcast within quad
    float lg0 = __shfl_sync(0xFFFFFFFFu, ol[0], lane & 28);
    float lg1 = __shfl_sync(0xFFFFFFFFu, ol[2], lane & 28);
    float inv0 = 1.0f / lg0, inv1 = 1.0f / lg1;

    int row0 = q0 + wq0 + g;
    int row1 = row0 + 8;
    float* y0 = y + ((size_t)(b * Nn + row0)) * Dd + h * DHd;
    float* y1 = y + ((size_t)(b * Nn + row1)) * Dd + h * DHd;
    #pragma unroll
    for (int jd = 0; jd < 8; jd++) {
        float2 p0 = make_float2(o[jd][0] * inv0, o[jd][1] * inv0);
        float2 p1 = make_float2(o[jd][2] * inv1, o[jd][3] * inv1);
        *(float2*)(y0 + jd * 8 + t2) = p0;
        *(float2*)(y1 + jd * 8 + t2) = p1;
    }
}

// ---------------------------------------------------------------------------
// Inputs (metadata order): x, Wq, bq, Wk, bk, Wv, bv. Output: float32 [B,N,D].
// ---------------------------------------------------------------------------
extern "C" void kernel_launch(void* const* d_in, const int* in_sizes, int n_in,
                              void* d_out, int out_size)
{
    const float* x  = (const float*)d_in[0];
    const float* Wq = (const float*)d_in[1];
    const float* bq = (const float*)d_in[2];
    const float* Wk = (const float*)d_in[3];
    const float* bk = (const float*)d_in[4];
    const float* Wv = (const float*)d_in[5];
    const float* bv = (const float*)d_in[6];
    float* y = (float*)d_out;

    cudaFuncSetAttribute(gemm_hmma_kernel, cudaFuncAttributeMaxDynamicSharedMemorySize, SMEM_GEMM);
    cudaFuncSetAttribute(fa_kernel, cudaFuncAttributeMaxDynamicSharedMemorySize, SMEM_FA);

    split_x_kernel<<<4096, 256>>>(x);
    split_wt_kernel<<<dim3(8, 8, 3), 256>>>(Wq, Wk, Wv);

    dim3 ggrid(MTOT / 64, Dd / 128, 3);    // (128, 4, 3) fused
    gemm_hmma_kernel<<<ggrid, 128, SMEM_GEMM>>>(bq, bk, bv);

    dim3 agrid(Nn / 64, BH);               // (16, 64)
    fa_kernel<<<agrid, 128, SMEM_FA>>>(y);
}

// round 14
// speedup vs baseline: 5.2044x; 1.0271x over previous
#include <cuda_runtime.h>
#include <cuda_bf16.h>
#include <cuda_fp16.h>

// Problem constants
#define Bb   8
#define Nn   1024
#define Dd   512
#define Hh   8
#define DHd  64
#define MTOT (Bb*Nn)   // 8192
#define BH   (Bb*Hh)   // 64
#define LOG2E 1.4426950408889634f

// Split-bf16 operands for the projection GEMMs
__device__ __nv_bfloat16 g_xh[MTOT*Dd];
__device__ __nv_bfloat16 g_xl[MTOT*Dd];
__device__ __nv_bfloat16 g_wth[3*Dd*Dd];   // W^T per proj: [n][k]
__device__ __nv_bfloat16 g_wtl[3*Dd*Dd];

// Q/K split-bf16 head-major [BH, N, 64] (Q pre-scaled by log2e); V^T fp16 [BH, 64, N]
__device__ __nv_bfloat16 g_qh[BH*Nn*DHd];
__device__ __nv_bfloat16 g_ql[BH*Nn*DHd];
__device__ __nv_bfloat16 g_kh[BH*Nn*DHd];
__device__ __nv_bfloat16 g_kl[BH*Nn*DHd];
__device__ __half        g_vh[BH*DHd*Nn];

#define SMEM_SWZ(b) ((b) ^ (((b) >> 3) & 0x70))

static __device__ __forceinline__ unsigned smem_u32(const void* p) {
    unsigned a;
    asm("{ .reg .u64 t; cvta.to.shared.u64 t, %1; cvt.u32.u64 %0, t; }" : "=r"(a) : "l"(p));
    return a;
}

static __device__ __forceinline__ float ex2f(float x) {
    float r;
    asm("ex2.approx.f32 %0, %1;" : "=f"(r) : "f"(x));
    return r;
}

// cp.async helpers (sm_80+)
#define CP_ASYNC16(dst_u32, src_ptr) \
    asm volatile("cp.async.cg.shared.global [%0], [%1], 16;" :: "r"(dst_u32), "l"(src_ptr))
#define CP_COMMIT() asm volatile("cp.async.commit_group;")
#define CP_WAIT1()  asm volatile("cp.async.wait_group 1;")
#define CP_WAIT0()  asm volatile("cp.async.wait_group 0;")

// mma.sync m16n8k16 bf16 -> fp32
static __device__ __forceinline__ void mma16816(float* c, const unsigned* a, const unsigned* b) {
    asm volatile(
        "mma.sync.aligned.m16n8k16.row.col.f32.bf16.bf16.f32 "
        "{%0,%1,%2,%3}, {%4,%5,%6,%7}, {%8,%9}, {%0,%1,%2,%3};"
        : "+f"(c[0]), "+f"(c[1]), "+f"(c[2]), "+f"(c[3])
        : "r"(a[0]), "r"(a[1]), "r"(a[2]), "r"(a[3]), "r"(b[0]), "r"(b[1]));
}

// mma.sync m16n8k16 fp16 -> fp32
static __device__ __forceinline__ void mma16816h(float* c, const unsigned* a, const unsigned* b) {
    asm volatile(
        "mma.sync.aligned.m16n8k16.row.col.f32.f16.f16.f32 "
        "{%0,%1,%2,%3}, {%4,%5,%6,%7}, {%8,%9}, {%0,%1,%2,%3};"
        : "+f"(c[0]), "+f"(c[1]), "+f"(c[2]), "+f"(c[3])
        : "r"(a[0]), "r"(a[1]), "r"(a[2]), "r"(a[3]), "r"(b[0]), "r"(b[1]));
}

static __device__ __forceinline__ void ldsm4(unsigned* r, unsigned addr) {
    asm volatile("ldmatrix.sync.aligned.m8n8.x4.shared.b16 {%0,%1,%2,%3}, [%4];"
                 : "=r"(r[0]), "=r"(r[1]), "=r"(r[2]), "=r"(r[3]) : "r"(addr));
}

static __device__ __forceinline__ void split2(float v, __nv_bfloat16& hi, __nv_bfloat16& lo) {
    hi = __float2bfloat16(v);
    lo = __float2bfloat16(v - __bfloat162float(hi));
}

// ---------------------------------------------------------------------------
// split_x: x fp32 [8192,512] -> g_xh/g_xl bf16. One float4 per thread.
// ---------------------------------------------------------------------------
__global__ __launch_bounds__(256) void split_x_kernel(const float* __restrict__ x)
{
    int i = blockIdx.x * 256 + threadIdx.x;          // float4 index, < 1048576
    float4 v = ((const float4*)x)[i];
    __nv_bfloat16 h[4], l[4];
    split2(v.x, h[0], l[0]); split2(v.y, h[1], l[1]);
    split2(v.z, h[2], l[2]); split2(v.w, h[3], l[3]);
    ((uint2*)g_xh)[i] = *(uint2*)h;
    ((uint2*)g_xl)[i] = *(uint2*)l;
}

// ---------------------------------------------------------------------------
// split_wt: W [512,512] ([k][n]) -> W^T hi/lo [n][k]. 64x64 tiles.
// ---------------------------------------------------------------------------
__global__ __launch_bounds__(256) void split_wt_kernel(
    const float* __restrict__ W0, const float* __restrict__ W1,
    const float* __restrict__ W2)
{
    const float* W = (blockIdx.z == 0) ? W0 : (blockIdx.z == 1) ? W1 : W2;
    __nv_bfloat16* Oh = g_wth + (size_t)blockIdx.z * Dd * Dd;
    __nv_bfloat16* Ol = g_wtl + (size_t)blockIdx.z * Dd * Dd;

    __shared__ __nv_bfloat16 sh[64][68];
    __shared__ __nv_bfloat16 sl[64][68];

    const int k0 = blockIdx.y * 64;
    const int n0 = blockIdx.x * 64;
    const int tid = threadIdx.x;

    int r = tid >> 2;
    int cs = (tid & 3) * 16;
    #pragma unroll
    for (int j = 0; j < 4; j++) {
        float4 v = *(const float4*)(W + (size_t)(k0 + r) * Dd + n0 + cs + j * 4);
        __nv_bfloat16 h, l;
        split2(v.x, h, l); sh[cs + j*4 + 0][r] = h; sl[cs + j*4 + 0][r] = l;
        split2(v.y, h, l); sh[cs + j*4 + 1][r] = h; sl[cs + j*4 + 1][r] = l;
        split2(v.z, h, l); sh[cs + j*4 + 2][r] = h; sl[cs + j*4 + 2][r] = l;
        split2(v.w, h, l); sh[cs + j*4 + 3][r] = h; sl[cs + j*4 + 3][r] = l;
    }
    __syncthreads();

    int n = tid >> 2;
    int ks = (tid & 3) * 16;
    #pragma unroll
    for (int j = 0; j < 8; j++) {
        __nv_bfloat16 p0 = sh[n][ks + j*2], p1 = sh[n][ks + j*2 + 1];
        unsigned uh = (unsigned)__bfloat16_as_ushort(p0) | ((unsigned)__bfloat16_as_ushort(p1) << 16);
        p0 = sl[n][ks + j*2]; p1 = sl[n][ks + j*2 + 1];
        unsigned ul = (unsigned)__bfloat16_as_ushort(p0) | ((unsigned)__bfloat16_as_ushort(p1) << 16);
        *(unsigned*)(Oh + (size_t)(n0 + n) * Dd + k0 + ks + j*2) = uh;
        *(unsigned*)(Ol + (size_t)(n0 + n) * Dd + k0 + ks + j*2) = ul;
    }
}

// ---------------------------------------------------------------------------
// HMMA projection GEMM, fused (gridDim.z picks proj), 2-stage cp.async pipe.
// 64x64 tile, 128 threads (4 warps, each 64m x 16n), KT=64 per stage.
// 32KB/stage x2 = 64KB smem -> 3 CTAs/SM for cross-CTA phase overlap.
// Epilogue: Q scaled by log2e + split; K split; V single fp16 transposed.
// ---------------------------------------------------------------------------
#define GOFF_AH 0
#define GOFF_AL 8192
#define GOFF_BH 16384
#define GOFF_BL 24576
#define GSTAGE  32768
#define SMEM_GEMM (2*GSTAGE)

__global__ __launch_bounds__(128, 3) void gemm_hmma_kernel(
    const float* __restrict__ bq, const float* __restrict__ bk,
    const float* __restrict__ bv)
{
    extern __shared__ char s[];
    const unsigned base_u = smem_u32(s);

    const int which = blockIdx.z;
    const float* bias = (which == 0) ? bq : (which == 1) ? bk : bv;
    __nv_bfloat16* Hi = (which == 0) ? g_qh : g_kh;
    __nv_bfloat16* Lo = (which == 0) ? g_ql : g_kl;
    const char* wh_base = (const char*)(g_wth + (size_t)which * Dd * Dd);
    const char* wl_base = (const char*)(g_wtl + (size_t)which * Dd * Dd);
    const char* xh_base = (const char*)g_xh;
    const char* xl_base = (const char*)g_xl;

    const int tid  = threadIdx.x;
    const int w    = tid >> 5;        // 0..3
    const int lane = tid & 31;
    const int g    = lane >> 2;
    const int mrow = lane & 7;
    const int sel  = lane >> 3;
    const int wn0  = w * 16;          // warp n offset within 64-wide tile
    const int bm   = blockIdx.x * 64;
    const int bn   = blockIdx.y * 64;

    const int a_row_off = ((sel & 1) << 3) + mrow;
    const int a_k_off   = (sel >> 1) << 4;
    const int brow_off  = ((sel >> 1) << 3) + mrow;
    const int bkb       = (sel & 1) << 4;

    float c[4][2][4];
    #pragma unroll
    for (int mi = 0; mi < 4; mi++)
        #pragma unroll
        for (int nj = 0; nj < 2; nj++)
            #pragma unroll
            for (int v = 0; v < 4; v++) c[mi][nj][v] = 0.0f;

    // issue stage for k-tile kt: A 64 rows, B 64 rows (hi+lo each)
    auto issue = [&](int kt) {
        unsigned so = base_u + (kt & 1) * GSTAGE;
        unsigned ko = (unsigned)kt * 128;
        #pragma unroll
        for (int rr = 0; rr < 4; rr++) {
            int idx = tid + rr * 128;            // 0..511
            int row = idx >> 3, c16 = idx & 7;
            unsigned sw = SMEM_SWZ((unsigned)(row * 128 + c16 * 16));
            unsigned gA = (unsigned)(bm + row) * 1024 + c16 * 16 + ko;
            unsigned gB = (unsigned)(bn + row) * 1024 + c16 * 16 + ko;
            CP_ASYNC16(so + GOFF_AH + sw, xh_base + gA);
            CP_ASYNC16(so + GOFF_AL + sw, xl_base + gA);
            CP_ASYNC16(so + GOFF_BH + sw, wh_base + gB);
            CP_ASYNC16(so + GOFF_BL + sw, wl_base + gB);
        }
        CP_COMMIT();
    };

    issue(0);
    for (int kt = 0; kt < 8; kt++) {
        if (kt < 7) { issue(kt + 1); CP_WAIT1(); } else { CP_WAIT0(); }
        __syncthreads();

        unsigned sb = base_u + (kt & 1) * GSTAGE;
        #pragma unroll
        for (int ks = 0; ks < 4; ks++) {
            unsigned ah[4][4], al[4][4];
            #pragma unroll
            for (int mi = 0; mi < 4; mi++) {
                unsigned sw = SMEM_SWZ((unsigned)((mi * 16 + a_row_off) * 128 + ks * 32 + a_k_off));
                ldsm4(ah[mi], sb + GOFF_AH + sw);
                ldsm4(al[mi], sb + GOFF_AL + sw);
            }
            unsigned bh4[4], bl4[4];
            {
                unsigned sw = SMEM_SWZ((unsigned)((wn0 + brow_off) * 128 + ks * 32 + bkb));
                ldsm4(bh4, sb + GOFF_BH + sw);
                ldsm4(bl4, sb + GOFF_BL + sw);
            }
            #pragma unroll
            for (int mi = 0; mi < 4; mi++)
                #pragma unroll
                for (int nj = 0; nj < 2; nj++) {
                    const unsigned* bp_h = bh4 + nj * 2;
                    const unsigned* bp_l = bl4 + nj * 2;
                    mma16816(c[mi][nj], ah[mi], bp_h);
                    mma16816(c[mi][nj], ah[mi], bp_l);
                    mma16816(c[mi][nj], al[mi], bp_h);
                }
        }
        __syncthreads();   // stage (kt&1) free for reuse at kt+2
    }

    // Epilogue: bias + per-proj transform + scatter
    #pragma unroll
    for (int nj = 0; nj < 2; nj++) {
        int cb = bn + wn0 + nj * 8 + (lane & 3) * 2;
        float b0 = __ldg(bias + cb), b1 = __ldg(bias + cb + 1);
        int h0 = cb >> 6, d0 = cb & 63;
        int h1 = (cb + 1) >> 6, d1 = (cb + 1) & 63;
        #pragma unroll
        for (int mi = 0; mi < 4; mi++) {
            #pragma unroll
            for (int half = 0; half < 2; half++) {
                int m = bm + mi * 16 + g + half * 8;
                int bb = m >> 10, ns = m & 1023;
                float v0 = c[mi][nj][half * 2 + 0] + b0;
                float v1 = c[mi][nj][half * 2 + 1] + b1;
                if (which == 2) {
                    // V: single fp16, transposed per head
                    size_t dst0 = ((size_t)(bb * Hh + h0) * DHd + d0) * Nn + ns;
                    size_t dst1 = ((size_t)(bb * Hh + h1) * DHd + d1) * Nn + ns;
                    g_vh[dst0] = __float2half(v0);
                    g_vh[dst1] = __float2half(v1);
                } else {
                    if (which == 0) { v0 *= LOG2E; v1 *= LOG2E; }   // exp2-domain softmax
                    size_t dst0 = ((size_t)(bb * Hh + h0) * Nn + ns) * DHd + d0;
                    size_t dst1 = dst0 + (d1 - d0) + (size_t)(h1 - h0) * Nn * DHd;
                    __nv_bfloat16 hi, lo;
                    split2(v0, hi, lo); Hi[dst0] = hi; Lo[dst0] = lo;
                    split2(v1, hi, lo); Hi[dst1] = hi; Lo[dst1] = lo;
                }
            }
        }
    }
}

// ---------------------------------------------------------------------------
// HMMA flash attention, 128 threads (4 warps) over a 64-row q tile,
// 2-stage cp.async K/V pipeline. S: bf16 3-pass; O: fp16 single-pass.
// Row sums via ones-column MMA (accumulator col 0 = running l).
// Q fragments re-loaded from smem each iter (reg relief) -> 3 CTAs/SM.
// grid = (16 q-tiles, 64 bh).
// ---------------------------------------------------------------------------
#define FOFF_Q   0
#define FOFF_QL  8192
#define FSTAGE0  16384
#define FKH 0
#define FKL 8192
#define FV  16384
#define FSTAGE   24576
#define FONES    (FSTAGE0 + 2*FSTAGE)     // 65536, 2KB ones tile
#define SMEM_FA  (FONES + 2048)           // 67584

__global__ __launch_bounds__(128, 3) void fa_kernel(float* __restrict__ y)
{
    extern __shared__ char s[];
    const unsigned base_u = smem_u32(s);

    const int tid  = threadIdx.x;
    const int w    = tid >> 5;
    const int lane = tid & 31;
    const int g    = lane >> 2;
    const int t2   = (lane & 3) * 2;
    const int bh   = blockIdx.y;
    const int b    = bh >> 3, h = bh & 7;
    const int qt   = blockIdx.x;
    const int q0   = qt * 64;
    const int wq0  = w * 16;

    const int mrow = lane & 7;
    const int sel  = lane >> 3;
    const int a_row_off = ((sel & 1) << 3) + mrow;
    const int a_k_off   = (sel >> 1) << 4;
    const int brow_off  = ((sel >> 1) << 3) + mrow;
    const int bkb       = (sel & 1) << 4;

    const char* kh_base = (const char*)(g_kh + (size_t)bh * Nn * DHd);
    const char* kl_base = (const char*)(g_kl + (size_t)bh * Nn * DHd);
    const char* vh_base = (const char*)(g_vh + (size_t)bh * DHd * Nn);

    // per-thread K/V load addressing (4 x 16B chunks per 8KB buffer)
    unsigned f_sw[4]; int f_row[4], f_c16[4];
    #pragma unroll
    for (int rr = 0; rr < 4; rr++) {
        int idx = tid + rr * 128;
        f_row[rr] = idx >> 3; f_c16[rr] = idx & 7;
        f_sw[rr] = SMEM_SWZ((unsigned)(f_row[rr] * 128 + f_c16[rr] * 16));
    }

    auto issue = [&](int t) {
        unsigned so = base_u + FSTAGE0 + (t & 1) * FSTAGE;
        int t0 = t << 6;
        #pragma unroll
        for (int rr = 0; rr < 4; rr++) {
            unsigned kof = (unsigned)(t0 + f_row[rr]) * 128 + f_c16[rr] * 16;
            unsigned vof = (unsigned)f_row[rr] * 2048 + (unsigned)t0 * 2 + f_c16[rr] * 16;
            CP_ASYNC16(so + FKH + f_sw[rr], kh_base + kof);
            CP_ASYNC16(so + FKL + f_sw[rr], kl_base + kof);
            CP_ASYNC16(so + FV  + f_sw[rr], vh_base + vof);
        }
        CP_COMMIT();
    };

    issue(0);   // overlap with Q load below

    // ones tile: 16 rows x 128B; row 0 = fp16 1.0, rows 1..15 = 0.
    for (int i = tid; i < 512; i += 128) {
        *(unsigned*)(s + FONES + i * 4) = (i < 32) ? 0x3C003C00u : 0u;
    }

    // Q tiles (64 q-rows x 64 d bf16, swizzled 128B rows)
    const char* qh_src = (const char*)(g_qh + ((size_t)bh * Nn + q0) * DHd);
    const char* ql_src = (const char*)(g_ql + ((size_t)bh * Nn + q0) * DHd);
    #pragma unroll
    for (int rr = 0; rr < 4; rr++) {
        int idx = tid + rr * 128;
        int row = idx >> 3, c16 = idx & 7;
        unsigned byte = row * 128 + c16 * 16;
        unsigned sw = SMEM_SWZ(byte);
        *(float4*)(s + FOFF_Q + sw) = *(const float4*)(qh_src + byte);
        *(float4*)(s + FOFF_QL + sw) = *(const float4*)(ql_src + byte);
    }
    __syncthreads();

    // ones B-fragment (constant across iters)
    unsigned onesb[4];
    ldsm4(onesb, base_u + FONES + SMEM_SWZ((unsigned)(brow_off * 128 + bkb)));

    float m0 = -1e30f, m1 = -1e30f;
    float o[8][4];
    float ol[4];                 // ones-column accumulator: col0 = running l
    #pragma unroll
    for (int i = 0; i < 8; i++)
        #pragma unroll
        for (int v = 0; v < 4; v++) o[i][v] = 0.0f;
    #pragma unroll
    for (int v = 0; v < 4; v++) ol[v] = 0.0f;

    for (int t = 0; t < 16; t++) {
        if (t < 15) { issue(t + 1); CP_WAIT1(); } else { CP_WAIT0(); }
        __syncthreads();

        unsigned sb = base_u + FSTAGE0 + (t & 1) * FSTAGE;

        // S = Q K^T (scores in log2 domain via Q prescale)
        float c[8][4];
        #pragma unroll
        for (int j = 0; j < 8; j++)
            #pragma unroll
            for (int v = 0; v < 4; v++) c[j][v] = 0.0f;

        #pragma unroll
        for (int ks = 0; ks < 4; ks++) {
            unsigned qh4[4], ql4[4];
            unsigned qsw = SMEM_SWZ((unsigned)((wq0 + a_row_off) * 128 + ks * 32 + a_k_off));
            ldsm4(qh4, base_u + FOFF_Q + qsw);
            ldsm4(ql4, base_u + FOFF_QL + qsw);
            #pragma unroll
            for (int np = 0; np < 4; np++) {
                unsigned sw = SMEM_SWZ((unsigned)((np * 16 + brow_off) * 128 + ks * 32 + bkb));
                unsigned kh4[4], kl4[4];
                ldsm4(kh4, sb + FKH + sw);
                ldsm4(kl4, sb + FKL + sw);
                mma16816(c[2*np],   qh4, kh4);
                mma16816(c[2*np],   qh4, kl4);
                mma16816(c[2*np],   ql4, kh4);
                mma16816(c[2*np+1], qh4, kh4 + 2);
                mma16816(c[2*np+1], qh4, kl4 + 2);
                mma16816(c[2*np+1], ql4, kh4 + 2);
            }
        }

        // online softmax (exp2 domain); row sums handled by ones-MMA below
        float rm0 = -1e30f, rm1 = -1e30f;
        #pragma unroll
        for (int j = 0; j < 8; j++) {
            rm0 = fmaxf(rm0, fmaxf(c[j][0], c[j][1]));
            rm1 = fmaxf(rm1, fmaxf(c[j][2], c[j][3]));
        }
        rm0 = fmaxf(rm0, __shfl_xor_sync(0xFFFFFFFFu, rm0, 1));
        rm0 = fmaxf(rm0, __shfl_xor_sync(0xFFFFFFFFu, rm0, 2));
        rm1 = fmaxf(rm1, __shfl_xor_sync(0xFFFFFFFFu, rm1, 1));
        rm1 = fmaxf(rm1, __shfl_xor_sync(0xFFFFFFFFu, rm1, 2));

        float mn0 = fmaxf(m0, rm0), mn1 = fmaxf(m1, rm1);
        float cr0 = ex2f(m0 - mn0), cr1 = ex2f(m1 - mn1);
        m0 = mn0; m1 = mn1;

        #pragma unroll
        for (int j = 0; j < 8; j++) {
            c[j][0] = ex2f(c[j][0] - m0);
            c[j][1] = ex2f(c[j][1] - m0);
            c[j][2] = ex2f(c[j][2] - m1);
            c[j][3] = ex2f(c[j][3] - m1);
        }

        // rescale O (and l accumulator) only if any row's max moved
        if (__any_sync(0xFFFFFFFFu, (cr0 != 1.0f) | (cr1 != 1.0f))) {
            #pragma unroll
            for (int jd = 0; jd < 8; jd++) {
                o[jd][0] *= cr0; o[jd][1] *= cr0;
                o[jd][2] *= cr1; o[jd][3] *= cr1;
            }
            ol[0] *= cr0; ol[1] *= cr0;
            ol[2] *= cr1; ol[3] *= cr1;
        }

        // P as single fp16 fragments
        unsigned ph[4][4];
        #pragma unroll
        for (int ks = 0; ks < 4; ks++) {
            #pragma unroll
            for (int u = 0; u < 4; u++) {
                int j = 2 * ks + (u >> 1);
                int v = (u & 1) * 2;
                __half2 hv = __floats2half2_rn(c[j][v], c[j][v + 1]);
                ph[ks][u] = *(unsigned*)&hv;
            }
        }

        // O += P V (fp16), plus ones-column MMA accumulating row sums
        #pragma unroll
        for (int ks = 0; ks < 4; ks++) {
            #pragma unroll
            for (int dp = 0; dp < 4; dp++) {
                unsigned sw = SMEM_SWZ((unsigned)((dp * 16 + brow_off) * 128 + ks * 32 + bkb));
                unsigned vh4[4];
                ldsm4(vh4, sb + FV + sw);
                mma16816h(o[2*dp],   ph[ks], vh4);
                mma16816h(o[2*dp+1], ph[ks], vh4 + 2);
            }
            mma16816h(ol, ph[ks], onesb);
        }
        __syncthreads();   // stage (t&1) reusable at t+2
    }

    // l lives in ones-column col 0 -> lanes with t2==0; broadcast within quad
    float lg0 = __shfl_sync(0xFFFFFFFFu, ol[0], lane & 28);
    float lg1 = __shfl_sync(0xFFFFFFFFu, ol[2], lane & 28);
    float inv0 = 1.0f / lg0, inv1 = 1.0f / lg1;

    int row0 = q0 + wq0 + g;
    int row1 = row0 + 8;
    float* y0 = y + ((size_t)(b * Nn + row0)) * Dd + h * DHd;
    float* y1 = y + ((size_t)(b * Nn + row1)) * Dd + h * DHd;
    #pragma unroll
    for (int jd = 0; jd < 8; jd++) {
        float2 p0 = make_float2(o[jd][0] * inv0, o[jd][1] * inv0);
        float2 p1 = make_float2(o[jd][2] * inv1, o[jd][3] * inv1);
        *(float2*)(y0 + jd * 8 + t2) = p0;
        *(float2*)(y1 + jd * 8 + t2) = p1;
    }
}

// ---------------------------------------------------------------------------
// Inputs (metadata order): x, Wq, bq, Wk, bk, Wv, bv. Output: float32 [B,N,D].
// ---------------------------------------------------------------------------
extern "C" void kernel_launch(void* const* d_in, const int* in_sizes, int n_in,
                              void* d_out, int out_size)
{
    const float* x  = (const float*)d_in[0];
    const float* Wq = (const float*)d_in[1];
    const float* bq = (const float*)d_in[2];
    const float* Wk = (const float*)d_in[3];
    const float* bk = (const float*)d_in[4];
    const float* Wv = (const float*)d_in[5];
    const float* bv = (const float*)d_in[6];
    float* y = (float*)d_out;

    cudaFuncSetAttribute(gemm_hmma_kernel, cudaFuncAttributeMaxDynamicSharedMemorySize, SMEM_GEMM);
    cudaFuncSetAttribute(fa_kernel, cudaFuncAttributeMaxDynamicSharedMemorySize, SMEM_FA);

    split_x_kernel<<<4096, 256>>>(x);
    split_wt_kernel<<<dim3(8, 8, 3), 256>>>(Wq, Wk, Wv);

    dim3 ggrid(MTOT / 64, Dd / 64, 3);     // (128, 8, 3) fused
    gemm_hmma_kernel<<<ggrid, 128, SMEM_GEMM>>>(bq, bk, bv);

    dim3 agrid(Nn / 64, BH);               // (16, 64)
    fa_kernel<<<agrid, 128, SMEM_FA>>>(y);
}

// round 15
// speedup vs baseline: 5.5774x; 1.0717x over previous
#include <cuda_runtime.h>
#include <cuda_bf16.h>
#include <cuda_fp16.h>

// Problem constants
#define Bb   8
#define Nn   1024
#define Dd   512
#define Hh   8
#define DHd  64
#define MTOT (Bb*Nn)   // 8192
#define BH   (Bb*Hh)   // 64
#define LOG2E 1.4426950408889634f

// Split-bf16 operands for the Q/K projection GEMMs
__device__ __nv_bfloat16 g_xh[MTOT*Dd];
__device__ __nv_bfloat16 g_xl[MTOT*Dd];
__device__ __nv_bfloat16 g_wth[2*Dd*Dd];   // W^T per proj (Q,K): [n][k]
__device__ __nv_bfloat16 g_wtl[2*Dd*Dd];
// fp16 operands for the V projection (single-pass)
__device__ __half        g_xf[MTOT*Dd];
__device__ __half        g_wtf[Dd*Dd];     // Wv^T fp16 [n][k]

// Q/K split-bf16 head-major [BH, N, 64] (Q pre-scaled by log2e); V^T fp16 [BH, 64, N]
__device__ __nv_bfloat16 g_qh[BH*Nn*DHd];
__device__ __nv_bfloat16 g_ql[BH*Nn*DHd];
__device__ __nv_bfloat16 g_kh[BH*Nn*DHd];
__device__ __nv_bfloat16 g_kl[BH*Nn*DHd];
__device__ __half        g_vh[BH*DHd*Nn];

#define SMEM_SWZ(b) ((b) ^ (((b) >> 3) & 0x70))

static __device__ __forceinline__ unsigned smem_u32(const void* p) {
    unsigned a;
    asm("{ .reg .u64 t; cvta.to.shared.u64 t, %1; cvt.u32.u64 %0, t; }" : "=r"(a) : "l"(p));
    return a;
}

static __device__ __forceinline__ float ex2f(float x) {
    float r;
    asm("ex2.approx.f32 %0, %1;" : "=f"(r) : "f"(x));
    return r;
}

// cp.async helpers (sm_80+)
#define CP_ASYNC16(dst_u32, src_ptr) \
    asm volatile("cp.async.cg.shared.global [%0], [%1], 16;" :: "r"(dst_u32), "l"(src_ptr))
#define CP_COMMIT() asm volatile("cp.async.commit_group;")
#define CP_WAIT1()  asm volatile("cp.async.wait_group 1;")
#define CP_WAIT0()  asm volatile("cp.async.wait_group 0;")

// mma.sync m16n8k16 bf16 -> fp32
static __device__ __forceinline__ void mma16816(float* c, const unsigned* a, const unsigned* b) {
    asm volatile(
        "mma.sync.aligned.m16n8k16.row.col.f32.bf16.bf16.f32 "
        "{%0,%1,%2,%3}, {%4,%5,%6,%7}, {%8,%9}, {%0,%1,%2,%3};"
        : "+f"(c[0]), "+f"(c[1]), "+f"(c[2]), "+f"(c[3])
        : "r"(a[0]), "r"(a[1]), "r"(a[2]), "r"(a[3]), "r"(b[0]), "r"(b[1]));
}

// mma.sync m16n8k16 fp16 -> fp32
static __device__ __forceinline__ void mma16816h(float* c, const unsigned* a, const unsigned* b) {
    asm volatile(
        "mma.sync.aligned.m16n8k16.row.col.f32.f16.f16.f32 "
        "{%0,%1,%2,%3}, {%4,%5,%6,%7}, {%8,%9}, {%0,%1,%2,%3};"
        : "+f"(c[0]), "+f"(c[1]), "+f"(c[2]), "+f"(c[3])
        : "r"(a[0]), "r"(a[1]), "r"(a[2]), "r"(a[3]), "r"(b[0]), "r"(b[1]));
}

static __device__ __forceinline__ void ldsm4(unsigned* r, unsigned addr) {
    asm volatile("ldmatrix.sync.aligned.m8n8.x4.shared.b16 {%0,%1,%2,%3}, [%4];"
                 : "=r"(r[0]), "=r"(r[1]), "=r"(r[2]), "=r"(r[3]) : "r"(addr));
}

static __device__ __forceinline__ void split2(float v, __nv_bfloat16& hi, __nv_bfloat16& lo) {
    hi = __float2bfloat16(v);
    lo = __float2bfloat16(v - __bfloat162float(hi));
}

// ---------------------------------------------------------------------------
// split_x: x fp32 [8192,512] -> bf16 hi/lo + fp16. One float4 per thread.
// ---------------------------------------------------------------------------
__global__ __launch_bounds__(256) void split_x_kernel(const float* __restrict__ x)
{
    int i = blockIdx.x * 256 + threadIdx.x;          // float4 index, < 1048576
    float4 v = ((const float4*)x)[i];
    __nv_bfloat16 h[4], l[4];
    split2(v.x, h[0], l[0]); split2(v.y, h[1], l[1]);
    split2(v.z, h[2], l[2]); split2(v.w, h[3], l[3]);
    ((uint2*)g_xh)[i] = *(uint2*)h;
    ((uint2*)g_xl)[i] = *(uint2*)l;
    __half f[4];
    f[0] = __float2half(v.x); f[1] = __float2half(v.y);
    f[2] = __float2half(v.z); f[3] = __float2half(v.w);
    ((uint2*)g_xf)[i] = *(uint2*)f;
}

// ---------------------------------------------------------------------------
// split_wt: W [512,512] ([k][n]) -> W^T [n][k]. z=0,1: bf16 hi/lo; z=2: fp16.
// 64x64 tiles, grid (8, 8, 3), 256 threads.
// ---------------------------------------------------------------------------
__global__ __launch_bounds__(256) void split_wt_kernel(
    const float* __restrict__ W0, const float* __restrict__ W1,
    const float* __restrict__ W2)
{
    const int z = blockIdx.z;
    const float* W = (z == 0) ? W0 : (z == 1) ? W1 : W2;

    __shared__ unsigned short sh[64][68];
    __shared__ unsigned short sl[64][68];

    const int k0 = blockIdx.y * 64;
    const int n0 = blockIdx.x * 64;
    const int tid = threadIdx.x;

    int r = tid >> 2;
    int cs = (tid & 3) * 16;
    #pragma unroll
    for (int j = 0; j < 4; j++) {
        float4 v = *(const float4*)(W + (size_t)(k0 + r) * Dd + n0 + cs + j * 4);
        float vv[4] = {v.x, v.y, v.z, v.w};
        #pragma unroll
        for (int e = 0; e < 4; e++) {
            if (z < 2) {
                __nv_bfloat16 h, l;
                split2(vv[e], h, l);
                sh[cs + j*4 + e][r] = __bfloat16_as_ushort(h);
                sl[cs + j*4 + e][r] = __bfloat16_as_ushort(l);
            } else {
                __half f = __float2half(vv[e]);
                sh[cs + j*4 + e][r] = __half_as_ushort(f);
            }
        }
    }
    __syncthreads();

    int n = tid >> 2;
    int ks = (tid & 3) * 16;
    if (z < 2) {
        __nv_bfloat16* Oh = g_wth + (size_t)z * Dd * Dd;
        __nv_bfloat16* Ol = g_wtl + (size_t)z * Dd * Dd;
        #pragma unroll
        for (int j = 0; j < 8; j++) {
            unsigned uh = (unsigned)sh[n][ks + j*2] | ((unsigned)sh[n][ks + j*2 + 1] << 16);
            unsigned ul = (unsigned)sl[n][ks + j*2] | ((unsigned)sl[n][ks + j*2 + 1] << 16);
            *(unsigned*)(Oh + (size_t)(n0 + n) * Dd + k0 + ks + j*2) = uh;
            *(unsigned*)(Ol + (size_t)(n0 + n) * Dd + k0 + ks + j*2) = ul;
        }
    } else {
        #pragma unroll
        for (int j = 0; j < 8; j++) {
            unsigned uf = (unsigned)sh[n][ks + j*2] | ((unsigned)sh[n][ks + j*2 + 1] << 16);
            *(unsigned*)(g_wtf + (size_t)(n0 + n) * Dd + k0 + ks + j*2) = uf;
        }
    }
}

// ---------------------------------------------------------------------------
// HMMA projection GEMM, fused (gridDim.z picks proj), 2-stage cp.async pipe.
// 64x64 tile, 128 threads (4 warps, each 64m x 16n), KT=64 per stage.
// z=0 (Q), z=1 (K): split-bf16 3-pass. z=2 (V): fp16 single-pass.
// 32KB/stage x2 = 64KB smem -> 3 CTAs/SM.
// ---------------------------------------------------------------------------
#define GOFF_AH 0
#define GOFF_AL 8192
#define GOFF_BH 16384
#define GOFF_BL 24576
#define GSTAGE  32768
#define SMEM_GEMM (2*GSTAGE)

__global__ __launch_bounds__(128, 3) void gemm_hmma_kernel(
    const float* __restrict__ bq, const float* __restrict__ bk,
    const float* __restrict__ bv)
{
    extern __shared__ char s[];
    const unsigned base_u = smem_u32(s);

    const int which = blockIdx.z;
    const float* bias = (which == 0) ? bq : (which == 1) ? bk : bv;

    const int tid  = threadIdx.x;
    const int w    = tid >> 5;        // 0..3
    const int lane = tid & 31;
    const int g    = lane >> 2;
    const int mrow = lane & 7;
    const int sel  = lane >> 3;
    const int wn0  = w * 16;          // warp n offset within 64-wide tile
    const int bm   = blockIdx.x * 64;
    const int bn   = blockIdx.y * 64;

    const int a_row_off = ((sel & 1) << 3) + mrow;
    const int a_k_off   = (sel >> 1) << 4;
    const int brow_off  = ((sel >> 1) << 3) + mrow;
    const int bkb       = (sel & 1) << 4;

    float c[4][2][4];
    #pragma unroll
    for (int mi = 0; mi < 4; mi++)
        #pragma unroll
        for (int nj = 0; nj < 2; nj++)
            #pragma unroll
            for (int v = 0; v < 4; v++) c[mi][nj][v] = 0.0f;

    if (which == 2) {
        // ---- V: fp16 single-pass ----
        const char* xf_base = (const char*)g_xf;
        const char* wf_base = (const char*)g_wtf;

        auto issueV = [&](int kt) {
            unsigned so = base_u + (kt & 1) * GSTAGE;
            unsigned ko = (unsigned)kt * 128;
            #pragma unroll
            for (int rr = 0; rr < 4; rr++) {
                int idx = tid + rr * 128;            // 0..511
                int row = idx >> 3, c16 = idx & 7;
                unsigned sw = SMEM_SWZ((unsigned)(row * 128 + c16 * 16));
                unsigned gA = (unsigned)(bm + row) * 1024 + c16 * 16 + ko;
                unsigned gB = (unsigned)(bn + row) * 1024 + c16 * 16 + ko;
                CP_ASYNC16(so + GOFF_AH + sw, xf_base + gA);
                CP_ASYNC16(so + GOFF_BH + sw, wf_base + gB);
            }
            CP_COMMIT();
        };

        issueV(0);
        for (int kt = 0; kt < 8; kt++) {
            if (kt < 7) { issueV(kt + 1); CP_WAIT1(); } else { CP_WAIT0(); }
            __syncthreads();

            unsigned sb = base_u + (kt & 1) * GSTAGE;
            #pragma unroll
            for (int ks = 0; ks < 4; ks++) {
                unsigned ah[4][4];
                #pragma unroll
                for (int mi = 0; mi < 4; mi++) {
                    unsigned sw = SMEM_SWZ((unsigned)((mi * 16 + a_row_off) * 128 + ks * 32 + a_k_off));
                    ldsm4(ah[mi], sb + GOFF_AH + sw);
                }
                unsigned bh4[4];
                {
                    unsigned sw = SMEM_SWZ((unsigned)((wn0 + brow_off) * 128 + ks * 32 + bkb));
                    ldsm4(bh4, sb + GOFF_BH + sw);
                }
                #pragma unroll
                for (int mi = 0; mi < 4; mi++)
                    #pragma unroll
                    for (int nj = 0; nj < 2; nj++)
                        mma16816h(c[mi][nj], ah[mi], bh4 + nj * 2);
            }
            __syncthreads();
        }

        // Epilogue: bias + fp16 store transposed per head
        #pragma unroll
        for (int nj = 0; nj < 2; nj++) {
            int cb = bn + wn0 + nj * 8 + (lane & 3) * 2;
            float b0 = __ldg(bias + cb), b1 = __ldg(bias + cb + 1);
            int h0 = cb >> 6, d0 = cb & 63;
            int h1 = (cb + 1) >> 6, d1 = (cb + 1) & 63;
            #pragma unroll
            for (int mi = 0; mi < 4; mi++) {
                #pragma unroll
                for (int half = 0; half < 2; half++) {
                    int m = bm + mi * 16 + g + half * 8;
                    int bb = m >> 10, ns = m & 1023;
                    float v0 = c[mi][nj][half * 2 + 0] + b0;
                    float v1 = c[mi][nj][half * 2 + 1] + b1;
                    size_t dst0 = ((size_t)(bb * Hh + h0) * DHd + d0) * Nn + ns;
                    size_t dst1 = ((size_t)(bb * Hh + h1) * DHd + d1) * Nn + ns;
                    g_vh[dst0] = __float2half(v0);
                    g_vh[dst1] = __float2half(v1);
                }
            }
        }
        return;
    }

    // ---- Q/K: split-bf16 3-pass ----
    __nv_bfloat16* Hi = (which == 0) ? g_qh : g_kh;
    __nv_bfloat16* Lo = (which == 0) ? g_ql : g_kl;
    const char* wh_base = (const char*)(g_wth + (size_t)which * Dd * Dd);
    const char* wl_base = (const char*)(g_wtl + (size_t)which * Dd * Dd);
    const char* xh_base = (const char*)g_xh;
    const char* xl_base = (const char*)g_xl;

    auto issue = [&](int kt) {
        unsigned so = base_u + (kt & 1) * GSTAGE;
        unsigned ko = (unsigned)kt * 128;
        #pragma unroll
        for (int rr = 0; rr < 4; rr++) {
            int idx = tid + rr * 128;            // 0..511
            int row = idx >> 3, c16 = idx & 7;
            unsigned sw = SMEM_SWZ((unsigned)(row * 128 + c16 * 16));
            unsigned gA = (unsigned)(bm + row) * 1024 + c16 * 16 + ko;
            unsigned gB = (unsigned)(bn + row) * 1024 + c16 * 16 + ko;
            CP_ASYNC16(so + GOFF_AH + sw, xh_base + gA);
            CP_ASYNC16(so + GOFF_AL + sw, xl_base + gA);
            CP_ASYNC16(so + GOFF_BH + sw, wh_base + gB);
            CP_ASYNC16(so + GOFF_BL + sw, wl_base + gB);
        }
        CP_COMMIT();
    };

    issue(0);
    for (int kt = 0; kt < 8; kt++) {
        if (kt < 7) { issue(kt + 1); CP_WAIT1(); } else { CP_WAIT0(); }
        __syncthreads();

        unsigned sb = base_u + (kt & 1) * GSTAGE;
        #pragma unroll
        for (int ks = 0; ks < 4; ks++) {
            unsigned ah[4][4], al[4][4];
            #pragma unroll
            for (int mi = 0; mi < 4; mi++) {
                unsigned sw = SMEM_SWZ((unsigned)((mi * 16 + a_row_off) * 128 + ks * 32 + a_k_off));
                ldsm4(ah[mi], sb + GOFF_AH + sw);
                ldsm4(al[mi], sb + GOFF_AL + sw);
            }
            unsigned bh4[4], bl4[4];
            {
                unsigned sw = SMEM_SWZ((unsigned)((wn0 + brow_off) * 128 + ks * 32 + bkb));
                ldsm4(bh4, sb + GOFF_BH + sw);
                ldsm4(bl4, sb + GOFF_BL + sw);
            }
            #pragma unroll
            for (int mi = 0; mi < 4; mi++)
                #pragma unroll
                for (int nj = 0; nj < 2; nj++) {
                    const unsigned* bp_h = bh4 + nj * 2;
                    const unsigned* bp_l = bl4 + nj * 2;
                    mma16816(c[mi][nj], ah[mi], bp_h);
                    mma16816(c[mi][nj], ah[mi], bp_l);
                    mma16816(c[mi][nj], al[mi], bp_h);
                }
        }
        __syncthreads();   // stage (kt&1) free for reuse at kt+2
    }

    // Epilogue: bias + (Q: log2e scale) + split + scatter head-major
    #pragma unroll
    for (int nj = 0; nj < 2; nj++) {
        int cb = bn + wn0 + nj * 8 + (lane & 3) * 2;
        float b0 = __ldg(bias + cb), b1 = __ldg(bias + cb + 1);
        int h0 = cb >> 6, d0 = cb & 63;
        int h1 = (cb + 1) >> 6, d1 = (cb + 1) & 63;
        #pragma unroll
        for (int mi = 0; mi < 4; mi++) {
            #pragma unroll
            for (int half = 0; half < 2; half++) {
                int m = bm + mi * 16 + g + half * 8;
                int bb = m >> 10, ns = m & 1023;
                float v0 = c[mi][nj][half * 2 + 0] + b0;
                float v1 = c[mi][nj][half * 2 + 1] + b1;
                if (which == 0) { v0 *= LOG2E; v1 *= LOG2E; }   // exp2-domain softmax
                size_t dst0 = ((size_t)(bb * Hh + h0) * Nn + ns) * DHd + d0;
                size_t dst1 = dst0 + (d1 - d0) + (size_t)(h1 - h0) * Nn * DHd;
                __nv_bfloat16 hi, lo;
                split2(v0, hi, lo); Hi[dst0] = hi; Lo[dst0] = lo;
                split2(v1, hi, lo); Hi[dst1] = hi; Lo[dst1] = lo;
            }
        }
    }
}

// ---------------------------------------------------------------------------
// HMMA flash attention, 128 threads (4 warps) over a 64-row q tile,
// 2-stage cp.async K/V pipeline. S: bf16 3-pass; O: fp16 single-pass.
// Row sums via ones-column MMA. 3 CTAs/SM. grid = (16 q-tiles, 64 bh).
// ---------------------------------------------------------------------------
#define FOFF_Q   0
#define FOFF_QL  8192
#define FSTAGE0  16384
#define FKH 0
#define FKL 8192
#define FV  16384
#define FSTAGE   24576
#define FONES    (FSTAGE0 + 2*FSTAGE)     // 65536, 2KB ones tile
#define SMEM_FA  (FONES + 2048)           // 67584

__global__ __launch_bounds__(128, 3) void fa_kernel(float* __restrict__ y)
{
    extern __shared__ char s[];
    const unsigned base_u = smem_u32(s);

    const int tid  = threadIdx.x;
    const int w    = tid >> 5;
    const int lane = tid & 31;
    const int g    = lane >> 2;
    const int t2   = (lane & 3) * 2;
    const int bh   = blockIdx.y;
    const int b    = bh >> 3, h = bh & 7;
    const int qt   = blockIdx.x;
    const int q0   = qt * 64;
    const int wq0  = w * 16;

    const int mrow = lane & 7;
    const int sel  = lane >> 3;
    const int a_row_off = ((sel & 1) << 3) + mrow;
    const int a_k_off   = (sel >> 1) << 4;
    const int brow_off  = ((sel >> 1) << 3) + mrow;
    const int bkb       = (sel & 1) << 4;

    const char* kh_base = (const char*)(g_kh + (size_t)bh * Nn * DHd);
    const char* kl_base = (const char*)(g_kl + (size_t)bh * Nn * DHd);
    const char* vh_base = (const char*)(g_vh + (size_t)bh * DHd * Nn);

    // per-thread K/V load addressing (4 x 16B chunks per 8KB buffer)
    unsigned f_sw[4]; int f_row[4], f_c16[4];
    #pragma unroll
    for (int rr = 0; rr < 4; rr++) {
        int idx = tid + rr * 128;
        f_row[rr] = idx >> 3; f_c16[rr] = idx & 7;
        f_sw[rr] = SMEM_SWZ((unsigned)(f_row[rr] * 128 + f_c16[rr] * 16));
    }

    auto issue = [&](int t) {
        unsigned so = base_u + FSTAGE0 + (t & 1) * FSTAGE;
        int t0 = t << 6;
        #pragma unroll
        for (int rr = 0; rr < 4; rr++) {
            unsigned kof = (unsigned)(t0 + f_row[rr]) * 128 + f_c16[rr] * 16;
            unsigned vof = (unsigned)f_row[rr] * 2048 + (unsigned)t0 * 2 + f_c16[rr] * 16;
            CP_ASYNC16(so + FKH + f_sw[rr], kh_base + kof);
            CP_ASYNC16(so + FKL + f_sw[rr], kl_base + kof);
            CP_ASYNC16(so + FV  + f_sw[rr], vh_base + vof);
        }
        CP_COMMIT();
    };

    issue(0);   // overlap with Q load below

    // ones tile: 16 rows x 128B; row 0 = fp16 1.0, rows 1..15 = 0.
    for (int i = tid; i < 512; i += 128) {
        *(unsigned*)(s + FONES + i * 4) = (i < 32) ? 0x3C003C00u : 0u;
    }

    // Q tiles (64 q-rows x 64 d bf16, swizzled 128B rows)
    const char* qh_src = (const char*)(g_qh + ((size_t)bh * Nn + q0) * DHd);
    const char* ql_src = (const char*)(g_ql + ((size_t)bh * Nn + q0) * DHd);
    #pragma unroll
    for (int rr = 0; rr < 4; rr++) {
        int idx = tid + rr * 128;
        int row = idx >> 3, c16 = idx & 7;
        unsigned byte = row * 128 + c16 * 16;
        unsigned sw = SMEM_SWZ(byte);
        *(float4*)(s + FOFF_Q + sw) = *(const float4*)(qh_src + byte);
        *(float4*)(s + FOFF_QL + sw) = *(const float4*)(ql_src + byte);
    }
    __syncthreads();

    // ones B-fragment (constant across iters)
    unsigned onesb[4];
    ldsm4(onesb, base_u + FONES + SMEM_SWZ((unsigned)(brow_off * 128 + bkb)));

    float m0 = -1e30f, m1 = -1e30f;
    float o[8][4];
    float ol[4];                 // ones-column accumulator: col0 = running l
    #pragma unroll
    for (int i = 0; i < 8; i++)
        #pragma unroll
        for (int v = 0; v < 4; v++) o[i][v] = 0.0f;
    #pragma unroll
    for (int v = 0; v < 4; v++) ol[v] = 0.0f;

    for (int t = 0; t < 16; t++) {
        if (t < 15) { issue(t + 1); CP_WAIT1(); } else { CP_WAIT0(); }
        __syncthreads();

        unsigned sb = base_u + FSTAGE0 + (t & 1) * FSTAGE;

        // S = Q K^T (scores in log2 domain via Q prescale)
        float c[8][4];
        #pragma unroll
        for (int j = 0; j < 8; j++)
            #pragma unroll
            for (int v = 0; v < 4; v++) c[j][v] = 0.0f;

        #pragma unroll
        for (int ks = 0; ks < 4; ks++) {
            unsigned qh4[4], ql4[4];
            unsigned qsw = SMEM_SWZ((unsigned)((wq0 + a_row_off) * 128 + ks * 32 + a_k_off));
            ldsm4(qh4, base_u + FOFF_Q + qsw);
            ldsm4(ql4, base_u + FOFF_QL + qsw);
            #pragma unroll
            for (int np = 0; np < 4; np++) {
                unsigned sw = SMEM_SWZ((unsigned)((np * 16 + brow_off) * 128 + ks * 32 + bkb));
                unsigned kh4[4], kl4[4];
                ldsm4(kh4, sb + FKH + sw);
                ldsm4(kl4, sb + FKL + sw);
                mma16816(c[2*np],   qh4, kh4);
                mma16816(c[2*np],   qh4, kl4);
                mma16816(c[2*np],   ql4, kh4);
                mma16816(c[2*np+1], qh4, kh4 + 2);
                mma16816(c[2*np+1], qh4, kl4 + 2);
                mma16816(c[2*np+1], ql4, kh4 + 2);
            }
        }

        // online softmax (exp2 domain); row sums via ones-MMA below
        float rm0 = -1e30f, rm1 = -1e30f;
        #pragma unroll
        for (int j = 0; j < 8; j++) {
            rm0 = fmaxf(rm0, fmaxf(c[j][0], c[j][1]));
            rm1 = fmaxf(rm1, fmaxf(c[j][2], c[j][3]));
        }
        rm0 = fmaxf(rm0, __shfl_xor_sync(0xFFFFFFFFu, rm0, 1));
        rm0 = fmaxf(rm0, __shfl_xor_sync(0xFFFFFFFFu, rm0, 2));
        rm1 = fmaxf(rm1, __shfl_xor_sync(0xFFFFFFFFu, rm1, 1));
        rm1 = fmaxf(rm1, __shfl_xor_sync(0xFFFFFFFFu, rm1, 2));

        float mn0 = fmaxf(m0, rm0), mn1 = fmaxf(m1, rm1);
        float cr0 = ex2f(m0 - mn0), cr1 = ex2f(m1 - mn1);
        m0 = mn0; m1 = mn1;

        #pragma unroll
        for (int j = 0; j < 8; j++) {
            c[j][0] = ex2f(c[j][0] - m0);
            c[j][1] = ex2f(c[j][1] - m0);
            c[j][2] = ex2f(c[j][2] - m1);
            c[j][3] = ex2f(c[j][3] - m1);
        }

        // rescale O (and l accumulator) only if any row's max moved
        if (__any_sync(0xFFFFFFFFu, (cr0 != 1.0f) | (cr1 != 1.0f))) {
            #pragma unroll
            for (int jd = 0; jd < 8; jd++) {
                o[jd][0] *= cr0; o[jd][1] *= cr0;
                o[jd][2] *= cr1; o[jd][3] *= cr1;
            }
            ol[0] *= cr0; ol[1] *= cr0;
            ol[2] *= cr1; ol[3] *= cr1;
        }

        // P as single fp16 fragments
        unsigned ph[4][4];
        #pragma unroll
        for (int ks = 0; ks < 4; ks++) {
            #pragma unroll
            for (int u = 0; u < 4; u++) {
                int j = 2 * ks + (u >> 1);
                int v = (u & 1) * 2;
                __half2 hv = __floats2half2_rn(c[j][v], c[j][v + 1]);
                ph[ks][u] = *(unsigned*)&hv;
            }
        }

        // O += P V (fp16), plus ones-column MMA accumulating row sums
        #pragma unroll
        for (int ks = 0; ks < 4; ks++) {
            #pragma unroll
            for (int dp = 0; dp < 4; dp++) {
                unsigned sw = SMEM_SWZ((unsigned)((dp * 16 + brow_off) * 128 + ks * 32 + bkb));
                unsigned vh4[4];
                ldsm4(vh4, sb + FV + sw);
                mma16816h(o[2*dp],   ph[ks], vh4);
                mma16816h(o[2*dp+1], ph[ks], vh4 + 2);
            }
            mma16816h(ol, ph[ks], onesb);
        }
        __syncthreads();   // stage (t&1) reusable at t+2
    }

    // l lives in ones-column col 0 -> lanes with t2==0; broadcast within quad
    float lg0 = __shfl_sync(0xFFFFFFFFu, ol[0], lane & 28);
    float lg1 = __shfl_sync(0xFFFFFFFFu, ol[2], lane & 28);
    float inv0 = 1.0f / lg0, inv1 = 1.0f / lg1;

    int row0 = q0 + wq0 + g;
    int row1 = row0 + 8;
    float* y0 = y + ((size_t)(b * Nn + row0)) * Dd + h * DHd;
    float* y1 = y + ((size_t)(b * Nn + row1)) * Dd + h * DHd;
    #pragma unroll
    for (int jd = 0; jd < 8; jd++) {
        float2 p0 = make_float2(o[jd][0] * inv0, o[jd][1] * inv0);
        float2 p1 = make_float2(o[jd][2] * inv1, o[jd][3] * inv1);
        *(float2*)(y0 + jd * 8 + t2) = p0;
        *(float2*)(y1 + jd * 8 + t2) = p1;
    }
}

// ---------------------------------------------------------------------------
// Inputs (metadata order): x, Wq, bq, Wk, bk, Wv, bv. Output: float32 [B,N,D].
// ---------------------------------------------------------------------------
extern "C" void kernel_launch(void* const* d_in, const int* in_sizes, int n_in,
                              void* d_out, int out_size)
{
    const float* x  = (const float*)d_in[0];
    const float* Wq = (const float*)d_in[1];
    const float* bq = (const float*)d_in[2];
    const float* Wk = (const float*)d_in[3];
    const float* bk = (const float*)d_in[4];
    const float* Wv = (const float*)d_in[5];
    const float* bv = (const float*)d_in[6];
    float* y = (float*)d_out;

    cudaFuncSetAttribute(gemm_hmma_kernel, cudaFuncAttributeMaxDynamicSharedMemorySize, SMEM_GEMM);
    cudaFuncSetAttribute(fa_kernel, cudaFuncAttributeMaxDynamicSharedMemorySize, SMEM_FA);

    split_x_kernel<<<4096, 256>>>(x);
    split_wt_kernel<<<dim3(8, 8, 3), 256>>>(Wq, Wk, Wv);

    dim3 ggrid(MTOT / 64, Dd / 64, 3);     // (128, 8, 3) fused; z=2 is cheap V path
    gemm_hmma_kernel<<<ggrid, 128, SMEM_GEMM>>>(bq, bk, bv);

    dim3 agrid(Nn / 64, BH);               // (16, 64)
    fa_kernel<<<agrid, 128, SMEM_FA>>>(y);
}